// round 1
// baseline (speedup 1.0000x reference)
#include <cuda_runtime.h>

// Problem constants
#define B_  2
#define T_  2048
#define D_  2048
#define NH  16
#define HD  128
#define FR  64

// Scratch (device globals: allocation-free, graph-capture safe)
__device__ float g_q[(size_t)B_ * NH * T_ * HD];  // [B,N,T,H]
__device__ float g_k[(size_t)B_ * NH * T_ * HD];  // rope applied
__device__ float g_v[(size_t)B_ * NH * T_ * HD];  // rope applied
__device__ float g_o[(size_t)B_ * T_ * D_];       // attention out, [B,T,D]

// ============================================================================
// Kernel 1: QKV GEMM  qkv = x @ w_attn, fused head-split + RoPE(k,v) epilogue
// M=4096, N=6144, K=2048. BM=BN=128, BK=16, 256 threads, 8x8 per thread.
// Each block's 128 columns cover exactly one (section, head) pair.
// ============================================================================
__global__ __launch_bounds__(256) void qkv_gemm(const float* __restrict__ A,
                                                const float* __restrict__ Bw,
                                                const float* __restrict__ cosT,
                                                const float* __restrict__ sinT)
{
    const int K = 2048, Nn = 6144;
    __shared__ float As[16][128];   // transposed: As[k][m]
    __shared__ float Bs[16][128];   // Bs[k][n]

    int tid = threadIdx.x;
    int tr = tid >> 4, tc = tid & 15;
    int m0 = blockIdx.y << 7, n0 = blockIdx.x << 7;

    float acc[8][8];
#pragma unroll
    for (int i = 0; i < 8; i++)
#pragma unroll
        for (int j = 0; j < 8; j++) acc[i][j] = 0.f;

    int ar = tid >> 1;             // A tile row (0..127)
    int ac = (tid & 1) << 3;       // A tile col base (0 or 8)
    const float* Ap = A + (size_t)(m0 + ar) * K + ac;
    const float* Bp = Bw + (size_t)(tid >> 4) * Nn + (n0 + ((tid & 15) << 3));

    for (int k0 = 0; k0 < K; k0 += 16) {
        float4 a0 = *(const float4*)(Ap + k0);
        float4 a1 = *(const float4*)(Ap + k0 + 4);
        float4 b0 = *(const float4*)(Bp + (size_t)k0 * Nn);
        float4 b1 = *(const float4*)(Bp + (size_t)k0 * Nn + 4);

        As[ac + 0][ar] = a0.x; As[ac + 1][ar] = a0.y;
        As[ac + 2][ar] = a0.z; As[ac + 3][ar] = a0.w;
        As[ac + 4][ar] = a1.x; As[ac + 5][ar] = a1.y;
        As[ac + 6][ar] = a1.z; As[ac + 7][ar] = a1.w;
        *(float4*)&Bs[tid >> 4][(tid & 15) << 3] = b0;
        *(float4*)&Bs[tid >> 4][((tid & 15) << 3) + 4] = b1;
        __syncthreads();

#pragma unroll
        for (int kk = 0; kk < 16; kk++) {
            float ra[8], rb[8];
            *(float4*)&ra[0] = *(float4*)&As[kk][tr << 3];
            *(float4*)&ra[4] = *(float4*)&As[kk][(tr << 3) + 4];
            *(float4*)&rb[0] = *(float4*)&Bs[kk][tc << 3];
            *(float4*)&rb[4] = *(float4*)&Bs[kk][(tc << 3) + 4];
#pragma unroll
            for (int i = 0; i < 8; i++)
#pragma unroll
                for (int j = 0; j < 8; j++)
                    acc[i][j] = fmaf(ra[i], rb[j], acc[i][j]);
        }
        __syncthreads();
    }

    // Epilogue: head split + RoPE on k and v (NOT q)
    int section = n0 >> 11;            // 0=q, 1=k, 2=v
    int head = (n0 & 2047) >> 7;
    int h0 = tc << 3;                  // head-dim offset, even -> pairs local
    float* dst = (section == 0) ? g_q : (section == 1 ? g_k : g_v);

#pragma unroll
    for (int i = 0; i < 8; i++) {
        int m = m0 + (tr << 3) + i;
        int bb = m >> 11, t = m & 2047;
        size_t base = ((size_t)(bb * NH + head) * T_ + t) * HD + h0;
        if (section == 0) {
            *(float4*)&dst[base]     = make_float4(acc[i][0], acc[i][1], acc[i][2], acc[i][3]);
            *(float4*)&dst[base + 4] = make_float4(acc[i][4], acc[i][5], acc[i][6], acc[i][7]);
        } else {
            const float* cr = cosT + t * FR + (h0 >> 1);
            const float* sr = sinT + t * FR + (h0 >> 1);
            float o[8];
#pragma unroll
            for (int p = 0; p < 4; p++) {
                float c = cr[p], s = sr[p];
                float xr = acc[i][2 * p], xi = acc[i][2 * p + 1];
                o[2 * p]     = xr * c - xi * s;
                o[2 * p + 1] = xr * s + xi * c;
            }
            *(float4*)&dst[base]     = make_float4(o[0], o[1], o[2], o[3]);
            *(float4*)&dst[base + 4] = make_float4(o[4], o[5], o[6], o[7]);
        }
    }
}

// ============================================================================
// Kernel 2: causal flash attention, fp32.
// Block = 256 threads (8 warps), Q tile 64 rows, KV tiles of 32.
// Warp w owns rows w*8 + lane/4; lane%4 = cg.
//   S phase:  lane computes 8 scores at cols c*4+cg (interleaved -> no LDS
//             bank conflicts on K rows).
//   O phase:  lane owns 32 output elems at h = hh*4+cg, V kept TRANSPOSED in
//             smem so inner product over j vectorizes as float4.
// Online softmax per row via shfl over the 4-lane row group.
// ============================================================================
#define ATT_SMEM_FLOATS (64 * 132 + 32 * 132 + 128 * 36 + 64 * 36)
#define ATT_SMEM_BYTES  (ATT_SMEM_FLOATS * 4)

__global__ __launch_bounds__(256) void attn_fwd()
{
    extern __shared__ float sm[];
    float* Qs  = sm;                        // [64][132]
    float* Ks  = Qs + 64 * 132;             // [32][132]
    float* VsT = Ks + 32 * 132;             // [128][36]  (transposed V)
    float* Ps  = VsT + 128 * 36;            // [64][36]

    int tid = threadIdx.x;
    int w = tid >> 5, l = tid & 31;
    int r = (w << 3) + (l >> 2);            // q row within tile, 0..63
    int cg = l & 3;

    int qt = (int)gridDim.x - 1 - (int)blockIdx.x;   // heavy blocks first
    int qs = qt << 6;
    size_t hoff = (size_t)(blockIdx.z * NH + blockIdx.y) * ((size_t)T_ * HD);

    // Load Q tile
    for (int i = tid; i < 64 * 32; i += 256) {
        int rr = i >> 5, c4 = (i & 31) << 2;
        *(float4*)&Qs[rr * 132 + c4] =
            *(const float4*)&g_q[hoff + (size_t)(qs + rr) * HD + c4];
    }

    float o[32];
#pragma unroll
    for (int i = 0; i < 32; i++) o[i] = 0.f;
    float m_run = -3.0e38f, l_run = 0.f;
    const float scale = 0.08838834764831845f;   // 1/sqrt(128)

    int ntiles = 2 * qt + 2;
    for (int jt = 0; jt < ntiles; jt++) {
        int j0 = jt << 5;
        __syncthreads();   // prev iter's Vs/Ps reads done; Qs published (iter 0)

        // Load K tile (row-major) and V tile (transposed, conflict-free)
        for (int i = tid; i < 32 * 32; i += 256) {
            int rr = i >> 5, c4 = (i & 31) << 2;
            *(float4*)&Ks[rr * 132 + c4] =
                *(const float4*)&g_k[hoff + (size_t)(j0 + rr) * HD + c4];
        }
        for (int rr = w; rr < 32; rr += 8)
            for (int cc = l; cc < 128; cc += 32)
                VsT[cc * 36 + rr] = g_v[hoff + (size_t)(j0 + rr) * HD + cc];
        __syncthreads();

        // S = Q K^T for this lane's 8 columns (col = c*4+cg)
        float s[8];
#pragma unroll
        for (int c = 0; c < 8; c++) s[c] = 0.f;
        for (int h4 = 0; h4 < HD; h4 += 4) {
            float4 q4 = *(float4*)&Qs[r * 132 + h4];
#pragma unroll
            for (int c = 0; c < 8; c++) {
                float4 k4 = *(float4*)&Ks[(c * 4 + cg) * 132 + h4];
                s[c] = fmaf(q4.x, k4.x, s[c]);
                s[c] = fmaf(q4.y, k4.y, s[c]);
                s[c] = fmaf(q4.z, k4.z, s[c]);
                s[c] = fmaf(q4.w, k4.w, s[c]);
            }
        }

        // scale + causal mask + online softmax (row group = 4 lanes)
        int qi = qs + r;
        float mloc = -3.0e38f;
#pragma unroll
        for (int c = 0; c < 8; c++) {
            int ki = j0 + c * 4 + cg;
            float v = s[c] * scale;
            v = (ki <= qi) ? v : -3.0e38f;
            s[c] = v;
            mloc = fmaxf(mloc, v);
        }
        mloc = fmaxf(mloc, __shfl_xor_sync(0xffffffffu, mloc, 1));
        mloc = fmaxf(mloc, __shfl_xor_sync(0xffffffffu, mloc, 2));
        float m_new = fmaxf(m_run, mloc);
        float alpha = __expf(m_run - m_new);
        float psum = 0.f;
#pragma unroll
        for (int c = 0; c < 8; c++) {
            float p = __expf(s[c] - m_new);
            s[c] = p;
            psum += p;
        }
        psum += __shfl_xor_sync(0xffffffffu, psum, 1);
        psum += __shfl_xor_sync(0xffffffffu, psum, 2);
        l_run = l_run * alpha + psum;
        m_run = m_new;
#pragma unroll
        for (int i = 0; i < 32; i++) o[i] *= alpha;
#pragma unroll
        for (int c = 0; c < 8; c++) Ps[r * 36 + c * 4 + cg] = s[c];
        __syncthreads();

        // O += P V  (lane owns h = hh*4+cg; dot over j via float4 from VsT)
#pragma unroll
        for (int j4 = 0; j4 < 8; j4++) {
            float4 p4 = *(float4*)&Ps[r * 36 + (j4 << 2)];
#pragma unroll
            for (int hh = 0; hh < 32; hh++) {
                int h = (hh << 2) + cg;
                float4 vt = *(float4*)&VsT[h * 36 + (j4 << 2)];
                o[hh] = fmaf(p4.x, vt.x, o[hh]);
                o[hh] = fmaf(p4.y, vt.y, o[hh]);
                o[hh] = fmaf(p4.z, vt.z, o[hh]);
                o[hh] = fmaf(p4.w, vt.w, o[hh]);
            }
        }
    }

    // Epilogue: normalize, write [B,T,D] layout for the output GEMM
    float inv = 1.f / l_run;
    size_t ob = ((size_t)blockIdx.z * T_ + (qs + r)) * D_ + (size_t)blockIdx.y * HD;
#pragma unroll
    for (int hh = 0; hh < 32; hh++)
        g_o[ob + (hh << 2) + cg] = o[hh] * inv;
}

// ============================================================================
// Kernel 3: out = g_o @ w_out  (same tiling as kernel 1, plain store)
// ============================================================================
__global__ __launch_bounds__(256) void out_gemm(const float* __restrict__ Bw,
                                                float* __restrict__ C)
{
    const int K = 2048, Nn = 2048;
    __shared__ float As[16][128];
    __shared__ float Bs[16][128];

    int tid = threadIdx.x;
    int tr = tid >> 4, tc = tid & 15;
    int m0 = blockIdx.y << 7, n0 = blockIdx.x << 7;

    float acc[8][8];
#pragma unroll
    for (int i = 0; i < 8; i++)
#pragma unroll
        for (int j = 0; j < 8; j++) acc[i][j] = 0.f;

    int ar = tid >> 1;
    int ac = (tid & 1) << 3;
    const float* Ap = g_o + (size_t)(m0 + ar) * K + ac;
    const float* Bp = Bw + (size_t)(tid >> 4) * Nn + (n0 + ((tid & 15) << 3));

    for (int k0 = 0; k0 < K; k0 += 16) {
        float4 a0 = *(const float4*)(Ap + k0);
        float4 a1 = *(const float4*)(Ap + k0 + 4);
        float4 b0 = *(const float4*)(Bp + (size_t)k0 * Nn);
        float4 b1 = *(const float4*)(Bp + (size_t)k0 * Nn + 4);

        As[ac + 0][ar] = a0.x; As[ac + 1][ar] = a0.y;
        As[ac + 2][ar] = a0.z; As[ac + 3][ar] = a0.w;
        As[ac + 4][ar] = a1.x; As[ac + 5][ar] = a1.y;
        As[ac + 6][ar] = a1.z; As[ac + 7][ar] = a1.w;
        *(float4*)&Bs[tid >> 4][(tid & 15) << 3] = b0;
        *(float4*)&Bs[tid >> 4][((tid & 15) << 3) + 4] = b1;
        __syncthreads();

#pragma unroll
        for (int kk = 0; kk < 16; kk++) {
            float ra[8], rb[8];
            *(float4*)&ra[0] = *(float4*)&As[kk][tr << 3];
            *(float4*)&ra[4] = *(float4*)&As[kk][(tr << 3) + 4];
            *(float4*)&rb[0] = *(float4*)&Bs[kk][tc << 3];
            *(float4*)&rb[4] = *(float4*)&Bs[kk][(tc << 3) + 4];
#pragma unroll
            for (int i = 0; i < 8; i++)
#pragma unroll
                for (int j = 0; j < 8; j++)
                    acc[i][j] = fmaf(ra[i], rb[j], acc[i][j]);
        }
        __syncthreads();
    }

#pragma unroll
    for (int i = 0; i < 8; i++) {
        size_t row = (size_t)(m0 + (tr << 3) + i) * Nn + n0 + (tc << 3);
        *(float4*)&C[row]     = make_float4(acc[i][0], acc[i][1], acc[i][2], acc[i][3]);
        *(float4*)&C[row + 4] = make_float4(acc[i][4], acc[i][5], acc[i][6], acc[i][7]);
    }
}

// ============================================================================
// Launch. Inputs (metadata order): x, mask, cos, sin, w_attn, w_out.
// mask is always tril -> causal hardcoded.
// ============================================================================
extern "C" void kernel_launch(void* const* d_in, const int* in_sizes, int n_in,
                              void* d_out, int out_size)
{
    const float* x      = (const float*)d_in[0];
    const float* cosT   = (const float*)d_in[2];
    const float* sinT   = (const float*)d_in[3];
    const float* w_attn = (const float*)d_in[4];
    const float* w_out  = (const float*)d_in[5];
    float* out = (float*)d_out;

    qkv_gemm<<<dim3(48, 32), 256>>>(x, w_attn, cosT, sinT);

    cudaFuncSetAttribute(attn_fwd, cudaFuncAttributeMaxDynamicSharedMemorySize,
                         ATT_SMEM_BYTES);
    attn_fwd<<<dim3(32, NH, B_), 256, ATT_SMEM_BYTES>>>();

    out_gemm<<<dim3(16, 32), 256>>>(w_out, out);
}

// round 3
// speedup vs baseline: 1.4763x; 1.4763x over previous
#include <cuda_runtime.h>
#include <cuda_bf16.h>
#include <cstdint>

// Problem constants
#define B_   2
#define T_   2048
#define D_   2048
#define NH   16
#define HD   128
#define FR   64
#define KTOT 2048

// ---------------------------------------------------------------------------
// Device-global scratch (allocation-free, graph-capture safe)
// ---------------------------------------------------------------------------
__device__ float g_q[(size_t)B_ * NH * T_ * HD];
__device__ float g_k[(size_t)B_ * NH * T_ * HD];
__device__ float g_v[(size_t)B_ * NH * T_ * HD];
__device__ float g_o[(size_t)B_ * T_ * D_];
__device__ __nv_bfloat16 g_wa_hi[(size_t)3 * D_ * D_];   // w_attn^T split: [6144][2048]
__device__ __nv_bfloat16 g_wa_lo[(size_t)3 * D_ * D_];
__device__ __nv_bfloat16 g_wo_hi[(size_t)D_ * D_];       // w_out^T split: [2048][2048]
__device__ __nv_bfloat16 g_wo_lo[(size_t)D_ * D_];

__device__ __forceinline__ uint32_t smem_u32(const void* p) {
    uint32_t a;
    asm("{ .reg .u64 t; cvta.to.shared.u64 t, %1; cvt.u32.u64 %0, t; }"
        : "=r"(a) : "l"(p));
    return a;
}

__device__ __forceinline__ void ldsm4(uint32_t& r0, uint32_t& r1, uint32_t& r2,
                                      uint32_t& r3, uint32_t addr) {
    asm volatile("ldmatrix.sync.aligned.m8n8.x4.shared.b16 {%0,%1,%2,%3}, [%4];"
                 : "=r"(r0), "=r"(r1), "=r"(r2), "=r"(r3) : "r"(addr));
}

#define MMA_OP(d, a, b0, b1)                                                   \
    asm volatile("mma.sync.aligned.m16n8k16.row.col.f32.bf16.bf16.f32 "        \
                 "{%0,%1,%2,%3},{%4,%5,%6,%7},{%8,%9},{%0,%1,%2,%3};"          \
                 : "+f"((d)[0]), "+f"((d)[1]), "+f"((d)[2]), "+f"((d)[3])      \
                 : "r"((a)[0]), "r"((a)[1]), "r"((a)[2]), "r"((a)[3]),         \
                   "r"(b0), "r"(b1))

// ---------------------------------------------------------------------------
// Weight transpose + bf16 hi/lo split:  src fp32 [R][C]  ->  dst bf16 [C][R]
// ---------------------------------------------------------------------------
__global__ __launch_bounds__(256) void transpose_split(const float* __restrict__ src,
                                                       int R, int C, int which)
{
    __shared__ float tile[32][33];
    __nv_bfloat16* dhi = which ? g_wo_hi : g_wa_hi;
    __nv_bfloat16* dlo = which ? g_wo_lo : g_wa_lo;

    int x = blockIdx.x * 32 + threadIdx.x;
    int y0 = blockIdx.y * 32;
#pragma unroll
    for (int j = 0; j < 32; j += 8)
        tile[threadIdx.y + j][threadIdx.x] = src[(size_t)(y0 + threadIdx.y + j) * C + x];
    __syncthreads();
    int xo = y0 + threadIdx.x;       // k
    int yo = blockIdx.x * 32;        // n base
#pragma unroll
    for (int j = 0; j < 32; j += 8) {
        float v = tile[threadIdx.x][threadIdx.y + j];
        __nv_bfloat16 h = __float2bfloat16_rn(v);
        __nv_bfloat16 l = __float2bfloat16_rn(v - __bfloat162float(h));
        size_t o = (size_t)(yo + threadIdx.y + j) * R + xo;
        dhi[o] = h;
        dlo[o] = l;
    }
}

// ---------------------------------------------------------------------------
// Split-bf16 mma.sync GEMM.  C[128 x 64] tile = A(fp32) @ B^T(bf16 hi/lo)
// mode 0: A = x,   B = w_attn^T, epilogue = head split + RoPE(k,v)
// mode 1: A = g_o, B = w_out^T,  epilogue = plain store
// Block 256 thr = 8 warps (4m x 2n), warp tile 32x32, BK=32, double buffer.
// SMEM rows padded to 40 bf16 (80B): conflict-free ldmatrix, 16B aligned.
// ---------------------------------------------------------------------------
#define BM 128
#define BN 64
#define BK 32
#define ASTRIDE 40
#define A_TILE_ELE (BM * ASTRIDE)             // 5120 bf16
#define B_TILE_ELE (BN * ASTRIDE)             // 2560 bf16
#define STAGE_ELE  (2 * A_TILE_ELE + 2 * B_TILE_ELE)
#define GEMM_SMEM_BYTES (2 * STAGE_ELE * 2)   // 61440 B

__global__ __launch_bounds__(256, 1) void gemm_mma(
    const float* __restrict__ Ain,
    const float* __restrict__ cosT, const float* __restrict__ sinT,
    float* __restrict__ Cout, int mode)
{
    extern __shared__ __nv_bfloat16 smem_bf[];
    const int tid = threadIdx.x;
    const int wid = tid >> 5, lane = tid & 31;
    const int warp_m = wid & 3, warp_n = wid >> 2;
    const int m0 = blockIdx.y * BM, n0 = blockIdx.x * BN;

    const float* A = (mode == 0) ? Ain : g_o;
    const __nv_bfloat16* Bhi = (mode == 0) ? g_wa_hi : g_wo_hi;
    const __nv_bfloat16* Blo = (mode == 0) ? g_wa_lo : g_wo_lo;

    const uint32_t sbase = smem_u32(smem_bf);

    // gmem load slots
    const int arow = tid >> 3, ac4 = tid & 7;    // A: 4 rows (stride 32), 1 float4 each
    const int brow = tid >> 2, bc8 = tid & 3;    // B: 1 row, 8 bf16 (uint4) each half

    float4 fa[4];
    uint4 fbh, fbl;

    float acc[2][4][4];
#pragma unroll
    for (int i = 0; i < 2; i++)
#pragma unroll
        for (int j = 0; j < 4; j++)
#pragma unroll
            for (int k = 0; k < 4; k++) acc[i][j][k] = 0.f;

    // ldmatrix per-lane base offsets (bytes, within a stage)
    const uint32_t a_lm = ((warp_m * 32 + (lane & 15)) * ASTRIDE + (lane >> 4) * 8) * 2;
    const uint32_t b_lm = (2 * A_TILE_ELE +
                           (warp_n * 32 + (lane & 7) + ((lane >> 4) << 3)) * ASTRIDE +
                           (((lane >> 3) & 1) << 3)) * 2;

    auto LDG = [&](int k0) {
#pragma unroll
        for (int i = 0; i < 4; i++)
            fa[i] = *(const float4*)(A + (size_t)(m0 + arow + i * 32) * KTOT + k0 + ac4 * 4);
        fbh = *(const uint4*)(Bhi + (size_t)(n0 + brow) * KTOT + k0 + bc8 * 8);
        fbl = *(const uint4*)(Blo + (size_t)(n0 + brow) * KTOT + k0 + bc8 * 8);
    };

    auto STS = [&](int st) {
        __nv_bfloat16* Ah_s = smem_bf + st * STAGE_ELE;
        __nv_bfloat16* Al_s = Ah_s + A_TILE_ELE;
        __nv_bfloat16* Bh_s = Ah_s + 2 * A_TILE_ELE;
        __nv_bfloat16* Bl_s = Bh_s + B_TILE_ELE;
#pragma unroll
        for (int i = 0; i < 4; i++) {
            float4 f = fa[i];
            __nv_bfloat162 h01 = __floats2bfloat162_rn(f.x, f.y);
            __nv_bfloat162 h23 = __floats2bfloat162_rn(f.z, f.w);
            __nv_bfloat162 l01 = __floats2bfloat162_rn(f.x - __low2float(h01),
                                                       f.y - __high2float(h01));
            __nv_bfloat162 l23 = __floats2bfloat162_rn(f.z - __low2float(h23),
                                                       f.w - __high2float(h23));
            uint32_t e = (arow + i * 32) * ASTRIDE + ac4 * 4;
            *(uint2*)(Ah_s + e) = make_uint2(*(uint32_t*)&h01, *(uint32_t*)&h23);
            *(uint2*)(Al_s + e) = make_uint2(*(uint32_t*)&l01, *(uint32_t*)&l23);
        }
        uint32_t eb = brow * ASTRIDE + bc8 * 8;
        *(uint4*)(Bh_s + eb) = fbh;
        *(uint4*)(Bl_s + eb) = fbl;
    };

    auto COMPUTE = [&](int st) {
        uint32_t stb = sbase + (uint32_t)st * STAGE_ELE * 2;
#pragma unroll
        for (int ks = 0; ks < 2; ks++) {
            uint32_t ah[2][4], al[2][4], bh[2][4], bl[2][4];
#pragma unroll
            for (int mt = 0; mt < 2; mt++) {
                uint32_t ad = stb + a_lm + (mt * 16 * ASTRIDE + ks * 16) * 2;
                ldsm4(ah[mt][0], ah[mt][1], ah[mt][2], ah[mt][3], ad);
                ldsm4(al[mt][0], al[mt][1], al[mt][2], al[mt][3], ad + A_TILE_ELE * 2);
            }
#pragma unroll
            for (int ng = 0; ng < 2; ng++) {
                uint32_t bd = stb + b_lm + (ng * 16 * ASTRIDE + ks * 16) * 2;
                ldsm4(bh[ng][0], bh[ng][1], bh[ng][2], bh[ng][3], bd);
                ldsm4(bl[ng][0], bl[ng][1], bl[ng][2], bl[ng][3], bd + B_TILE_ELE * 2);
            }
#pragma unroll
            for (int mt = 0; mt < 2; mt++)
#pragma unroll
                for (int ng = 0; ng < 2; ng++)
#pragma unroll
                    for (int s = 0; s < 2; s++) {
                        float* d = acc[mt][ng * 2 + s];
                        MMA_OP(d, ah[mt], bh[ng][2 * s], bh[ng][2 * s + 1]);
                        MMA_OP(d, ah[mt], bl[ng][2 * s], bl[ng][2 * s + 1]);
                        MMA_OP(d, al[mt], bh[ng][2 * s], bh[ng][2 * s + 1]);
                    }
        }
    };

    const int NI = KTOT / BK;      // 64
    LDG(0);
    STS(0);
    __syncthreads();
#pragma unroll 1
    for (int it = 0; it < NI; it++) {
        if (it + 1 < NI) LDG((it + 1) * BK);
        COMPUTE(it & 1);
        __syncthreads();
        if (it + 1 < NI) {
            STS((it + 1) & 1);
            __syncthreads();
        }
    }

    // ---------------- epilogue ----------------
    const int rb = lane >> 2;
    const int cb = (lane & 3) * 2;
    if (mode == 0) {
        int sec = n0 >> 11;
        int head = (n0 >> 7) & 15;
        float* dst = (sec == 0) ? g_q : (sec == 1 ? g_k : g_v);
#pragma unroll
        for (int mt = 0; mt < 2; mt++)
#pragma unroll
            for (int hf = 0; hf < 2; hf++) {
                int m = m0 + warp_m * 32 + mt * 16 + hf * 8 + rb;
                int b = m >> 11, t = m & 2047;
                size_t rowbase = ((size_t)(b * NH + head) * T_ + t) * HD;
#pragma unroll
                for (int nt = 0; nt < 4; nt++) {
                    int n = n0 + warp_n * 32 + nt * 8 + cb;
                    int hh = n & 127;
                    float v0 = acc[mt][nt][hf * 2];
                    float v1 = acc[mt][nt][hf * 2 + 1];
                    if (sec) {
                        float cz = cosT[t * FR + (hh >> 1)];
                        float sz = sinT[t * FR + (hh >> 1)];
                        float r0 = v0 * cz - v1 * sz;
                        float r1 = v0 * sz + v1 * cz;
                        v0 = r0; v1 = r1;
                    }
                    *(float2*)&dst[rowbase + hh] = make_float2(v0, v1);
                }
            }
    } else {
#pragma unroll
        for (int mt = 0; mt < 2; mt++)
#pragma unroll
            for (int hf = 0; hf < 2; hf++) {
                int m = m0 + warp_m * 32 + mt * 16 + hf * 8 + rb;
#pragma unroll
                for (int nt = 0; nt < 4; nt++) {
                    int n = n0 + warp_n * 32 + nt * 8 + cb;
                    *(float2*)&Cout[(size_t)m * D_ + n] =
                        make_float2(acc[mt][nt][hf * 2], acc[mt][nt][hf * 2 + 1]);
                }
            }
    }
}

// ---------------------------------------------------------------------------
// Causal flash attention, fp32 (unchanged from passing R1 kernel)
// ---------------------------------------------------------------------------
#define ATT_SMEM_FLOATS (64 * 132 + 32 * 132 + 128 * 36 + 64 * 36)
#define ATT_SMEM_BYTES  (ATT_SMEM_FLOATS * 4)

__global__ __launch_bounds__(256) void attn_fwd()
{
    extern __shared__ float sm[];
    float* Qs  = sm;
    float* Ks  = Qs + 64 * 132;
    float* VsT = Ks + 32 * 132;
    float* Ps  = VsT + 128 * 36;

    int tid = threadIdx.x;
    int w = tid >> 5, l = tid & 31;
    int r = (w << 3) + (l >> 2);
    int cg = l & 3;

    int qt = (int)gridDim.x - 1 - (int)blockIdx.x;
    int qs = qt << 6;
    size_t hoff = (size_t)(blockIdx.z * NH + blockIdx.y) * ((size_t)T_ * HD);

    for (int i = tid; i < 64 * 32; i += 256) {
        int rr = i >> 5, c4 = (i & 31) << 2;
        *(float4*)&Qs[rr * 132 + c4] =
            *(const float4*)&g_q[hoff + (size_t)(qs + rr) * HD + c4];
    }

    float o[32];
#pragma unroll
    for (int i = 0; i < 32; i++) o[i] = 0.f;
    float m_run = -3.0e38f, l_run = 0.f;
    const float scale = 0.08838834764831845f;

    int ntiles = 2 * qt + 2;
    for (int jt = 0; jt < ntiles; jt++) {
        int j0 = jt << 5;
        __syncthreads();

        for (int i = tid; i < 32 * 32; i += 256) {
            int rr = i >> 5, c4 = (i & 31) << 2;
            *(float4*)&Ks[rr * 132 + c4] =
                *(const float4*)&g_k[hoff + (size_t)(j0 + rr) * HD + c4];
        }
        for (int rr = w; rr < 32; rr += 8)
            for (int cc = l; cc < 128; cc += 32)
                VsT[cc * 36 + rr] = g_v[hoff + (size_t)(j0 + rr) * HD + cc];
        __syncthreads();

        float s[8];
#pragma unroll
        for (int c = 0; c < 8; c++) s[c] = 0.f;
        for (int h4 = 0; h4 < HD; h4 += 4) {
            float4 q4 = *(float4*)&Qs[r * 132 + h4];
#pragma unroll
            for (int c = 0; c < 8; c++) {
                float4 k4 = *(float4*)&Ks[(c * 4 + cg) * 132 + h4];
                s[c] = fmaf(q4.x, k4.x, s[c]);
                s[c] = fmaf(q4.y, k4.y, s[c]);
                s[c] = fmaf(q4.z, k4.z, s[c]);
                s[c] = fmaf(q4.w, k4.w, s[c]);
            }
        }

        int qi = qs + r;
        float mloc = -3.0e38f;
#pragma unroll
        for (int c = 0; c < 8; c++) {
            int ki = j0 + c * 4 + cg;
            float v = s[c] * scale;
            v = (ki <= qi) ? v : -3.0e38f;
            s[c] = v;
            mloc = fmaxf(mloc, v);
        }
        mloc = fmaxf(mloc, __shfl_xor_sync(0xffffffffu, mloc, 1));
        mloc = fmaxf(mloc, __shfl_xor_sync(0xffffffffu, mloc, 2));
        float m_new = fmaxf(m_run, mloc);
        float alpha = __expf(m_run - m_new);
        float psum = 0.f;
#pragma unroll
        for (int c = 0; c < 8; c++) {
            float p = __expf(s[c] - m_new);
            s[c] = p;
            psum += p;
        }
        psum += __shfl_xor_sync(0xffffffffu, psum, 1);
        psum += __shfl_xor_sync(0xffffffffu, psum, 2);
        l_run = l_run * alpha + psum;
        m_run = m_new;
#pragma unroll
        for (int i = 0; i < 32; i++) o[i] *= alpha;
#pragma unroll
        for (int c = 0; c < 8; c++) Ps[r * 36 + c * 4 + cg] = s[c];
        __syncthreads();

#pragma unroll
        for (int j4 = 0; j4 < 8; j4++) {
            float4 p4 = *(float4*)&Ps[r * 36 + (j4 << 2)];
#pragma unroll
            for (int hh = 0; hh < 32; hh++) {
                int h = (hh << 2) + cg;
                float4 vt = *(float4*)&VsT[h * 36 + (j4 << 2)];
                o[hh] = fmaf(p4.x, vt.x, o[hh]);
                o[hh] = fmaf(p4.y, vt.y, o[hh]);
                o[hh] = fmaf(p4.z, vt.z, o[hh]);
                o[hh] = fmaf(p4.w, vt.w, o[hh]);
            }
        }
    }

    float inv = 1.f / l_run;
    size_t ob = ((size_t)blockIdx.z * T_ + (qs + r)) * D_ + (size_t)blockIdx.y * HD;
#pragma unroll
    for (int hh = 0; hh < 32; hh++)
        g_o[ob + (hh << 2) + cg] = o[hh] * inv;
}

// ---------------------------------------------------------------------------
// Launch. Inputs: x, mask, cos, sin, w_attn, w_out. mask is tril -> causal.
// ---------------------------------------------------------------------------
extern "C" void kernel_launch(void* const* d_in, const int* in_sizes, int n_in,
                              void* d_out, int out_size)
{
    const float* x      = (const float*)d_in[0];
    const float* cosT   = (const float*)d_in[2];
    const float* sinT   = (const float*)d_in[3];
    const float* w_attn = (const float*)d_in[4];
    const float* w_out  = (const float*)d_in[5];
    float* out = (float*)d_out;

    cudaFuncSetAttribute(gemm_mma, cudaFuncAttributeMaxDynamicSharedMemorySize,
                         GEMM_SMEM_BYTES);
    cudaFuncSetAttribute(attn_fwd, cudaFuncAttributeMaxDynamicSharedMemorySize,
                         ATT_SMEM_BYTES);

    // Weight transpose + hi/lo split (bandwidth-bound, ~100us)
    transpose_split<<<dim3(192, 64), dim3(32, 8)>>>(w_attn, D_, 3 * D_, 0);
    transpose_split<<<dim3(64, 64), dim3(32, 8)>>>(w_out, D_, D_, 1);

    // QKV projection (tensor-core split-bf16) + head split + RoPE
    gemm_mma<<<dim3(96, 32), 256, GEMM_SMEM_BYTES>>>(x, cosT, sinT, nullptr, 0);

    // Flash attention (fp32 SIMT)
    attn_fwd<<<dim3(32, NH, B_), 256, ATT_SMEM_BYTES>>>();

    // Output projection (tensor-core split-bf16)
    gemm_mma<<<dim3(32, 32), 256, GEMM_SMEM_BYTES>>>(nullptr, cosT, sinT, out, 1);
}

// round 5
// speedup vs baseline: 3.2262x; 2.1854x over previous
#include <cuda_runtime.h>
#include <cuda_bf16.h>
#include <cstdint>

// Problem constants
#define B_   2
#define T_   2048
#define D_   2048
#define NH   16
#define HD   128
#define FR   64
#define KTOT 2048
#define QK_SCALE 0.08838834764831845f   // 1/sqrt(128)

// ---------------------------------------------------------------------------
// Device-global scratch (allocation-free, graph-capture safe)
// Q/K/V stored pre-split bf16 hi/lo, [B,N,T,H]; Q pre-scaled by 1/sqrt(H).
// ---------------------------------------------------------------------------
__device__ __nv_bfloat16 g_q_hi[(size_t)B_ * NH * T_ * HD];
__device__ __nv_bfloat16 g_q_lo[(size_t)B_ * NH * T_ * HD];
__device__ __nv_bfloat16 g_k_hi[(size_t)B_ * NH * T_ * HD];
__device__ __nv_bfloat16 g_k_lo[(size_t)B_ * NH * T_ * HD];
__device__ __nv_bfloat16 g_v_hi[(size_t)B_ * NH * T_ * HD];
__device__ __nv_bfloat16 g_v_lo[(size_t)B_ * NH * T_ * HD];
__device__ float g_o[(size_t)B_ * T_ * D_];
__device__ __nv_bfloat16 g_wa_hi[(size_t)3 * D_ * D_];   // w_attn^T split: [6144][2048]
__device__ __nv_bfloat16 g_wa_lo[(size_t)3 * D_ * D_];
__device__ __nv_bfloat16 g_wo_hi[(size_t)D_ * D_];       // w_out^T split: [2048][2048]
__device__ __nv_bfloat16 g_wo_lo[(size_t)D_ * D_];

__device__ __forceinline__ uint32_t smem_u32(const void* p) {
    uint32_t a;
    asm("{ .reg .u64 t; cvta.to.shared.u64 t, %1; cvt.u32.u64 %0, t; }"
        : "=r"(a) : "l"(p));
    return a;
}

__device__ __forceinline__ void ldsm4(uint32_t& r0, uint32_t& r1, uint32_t& r2,
                                      uint32_t& r3, uint32_t addr) {
    asm volatile("ldmatrix.sync.aligned.m8n8.x4.shared.b16 {%0,%1,%2,%3}, [%4];"
                 : "=r"(r0), "=r"(r1), "=r"(r2), "=r"(r3) : "r"(addr));
}
__device__ __forceinline__ void ldsm4t(uint32_t& r0, uint32_t& r1, uint32_t& r2,
                                       uint32_t& r3, uint32_t addr) {
    asm volatile("ldmatrix.sync.aligned.m8n8.x4.trans.shared.b16 {%0,%1,%2,%3}, [%4];"
                 : "=r"(r0), "=r"(r1), "=r"(r2), "=r"(r3) : "r"(addr));
}

#define MMA_OP(d, a, b0, b1)                                                   \
    asm volatile("mma.sync.aligned.m16n8k16.row.col.f32.bf16.bf16.f32 "        \
                 "{%0,%1,%2,%3},{%4,%5,%6,%7},{%8,%9},{%0,%1,%2,%3};"          \
                 : "+f"((d)[0]), "+f"((d)[1]), "+f"((d)[2]), "+f"((d)[3])      \
                 : "r"((a)[0]), "r"((a)[1]), "r"((a)[2]), "r"((a)[3]),         \
                   "r"(b0), "r"(b1))

__device__ __forceinline__ void cpa16(uint32_t dst, const void* src) {
    asm volatile("cp.async.cg.shared.global [%0], [%1], 16;"
                 :: "r"(dst), "l"(src));
}
#define CP_COMMIT() asm volatile("cp.async.commit_group;" ::: "memory")
#define CP_WAIT0()  asm volatile("cp.async.wait_group 0;" ::: "memory")

// ---------------------------------------------------------------------------
// Weight transpose + bf16 hi/lo split:  src fp32 [R][C]  ->  dst bf16 [C][R]
// ---------------------------------------------------------------------------
__global__ __launch_bounds__(256) void transpose_split(const float* __restrict__ src,
                                                       int R, int C, int which)
{
    __shared__ float tile[32][33];
    __nv_bfloat16* dhi = which ? g_wo_hi : g_wa_hi;
    __nv_bfloat16* dlo = which ? g_wo_lo : g_wa_lo;

    int x = blockIdx.x * 32 + threadIdx.x;
    int y0 = blockIdx.y * 32;
#pragma unroll
    for (int j = 0; j < 32; j += 8)
        tile[threadIdx.y + j][threadIdx.x] = src[(size_t)(y0 + threadIdx.y + j) * C + x];
    __syncthreads();
    int xo = y0 + threadIdx.x;
    int yo = blockIdx.x * 32;
#pragma unroll
    for (int j = 0; j < 32; j += 8) {
        float v = tile[threadIdx.x][threadIdx.y + j];
        __nv_bfloat16 h = __float2bfloat16_rn(v);
        __nv_bfloat16 l = __float2bfloat16_rn(v - __bfloat162float(h));
        size_t o = (size_t)(yo + threadIdx.y + j) * R + xo;
        dhi[o] = h;
        dlo[o] = l;
    }
}

// ---------------------------------------------------------------------------
// Split-bf16 mma.sync GEMM.  C[128 x 64] tile = A(fp32) @ B^T(bf16 hi/lo)
// mode 0: A = x,   B = w_attn^T, epilogue = head split + scale(q)/RoPE(k,v),
//         output = bf16 hi/lo pairs into g_{q,k,v}_{hi,lo}
// mode 1: A = g_o, B = w_out^T,  epilogue = plain fp32 store
// ---------------------------------------------------------------------------
#define BM 128
#define BN 64
#define BK 32
#define ASTRIDE 40
#define A_TILE_ELE (BM * ASTRIDE)
#define B_TILE_ELE (BN * ASTRIDE)
#define STAGE_ELE  (2 * A_TILE_ELE + 2 * B_TILE_ELE)
#define GEMM_SMEM_BYTES (2 * STAGE_ELE * 2)

__global__ __launch_bounds__(256, 1) void gemm_mma(
    const float* __restrict__ Ain,
    const float* __restrict__ cosT, const float* __restrict__ sinT,
    float* __restrict__ Cout, int mode)
{
    extern __shared__ __nv_bfloat16 smem_bf[];
    const int tid = threadIdx.x;
    const int wid = tid >> 5, lane = tid & 31;
    const int warp_m = wid & 3, warp_n = wid >> 2;
    const int m0 = blockIdx.y * BM, n0 = blockIdx.x * BN;

    const float* A = (mode == 0) ? Ain : g_o;
    const __nv_bfloat16* Bhi = (mode == 0) ? g_wa_hi : g_wo_hi;
    const __nv_bfloat16* Blo = (mode == 0) ? g_wa_lo : g_wo_lo;

    const uint32_t sbase = smem_u32(smem_bf);

    const int arow = tid >> 3, ac4 = tid & 7;
    const int brow = tid >> 2, bc8 = tid & 3;

    float4 fa[4];
    uint4 fbh, fbl;

    float acc[2][4][4];
#pragma unroll
    for (int i = 0; i < 2; i++)
#pragma unroll
        for (int j = 0; j < 4; j++)
#pragma unroll
            for (int k = 0; k < 4; k++) acc[i][j][k] = 0.f;

    const uint32_t a_lm = ((warp_m * 32 + (lane & 15)) * ASTRIDE + (lane >> 4) * 8) * 2;
    const uint32_t b_lm = (2 * A_TILE_ELE +
                           (warp_n * 32 + (lane & 7) + ((lane >> 4) << 3)) * ASTRIDE +
                           (((lane >> 3) & 1) << 3)) * 2;

    auto LDG = [&](int k0) {
#pragma unroll
        for (int i = 0; i < 4; i++)
            fa[i] = *(const float4*)(A + (size_t)(m0 + arow + i * 32) * KTOT + k0 + ac4 * 4);
        fbh = *(const uint4*)(Bhi + (size_t)(n0 + brow) * KTOT + k0 + bc8 * 8);
        fbl = *(const uint4*)(Blo + (size_t)(n0 + brow) * KTOT + k0 + bc8 * 8);
    };

    auto STS = [&](int st) {
        __nv_bfloat16* Ah_s = smem_bf + st * STAGE_ELE;
        __nv_bfloat16* Al_s = Ah_s + A_TILE_ELE;
        __nv_bfloat16* Bh_s = Ah_s + 2 * A_TILE_ELE;
        __nv_bfloat16* Bl_s = Bh_s + B_TILE_ELE;
#pragma unroll
        for (int i = 0; i < 4; i++) {
            float4 f = fa[i];
            __nv_bfloat162 h01 = __floats2bfloat162_rn(f.x, f.y);
            __nv_bfloat162 h23 = __floats2bfloat162_rn(f.z, f.w);
            __nv_bfloat162 l01 = __floats2bfloat162_rn(f.x - __low2float(h01),
                                                       f.y - __high2float(h01));
            __nv_bfloat162 l23 = __floats2bfloat162_rn(f.z - __low2float(h23),
                                                       f.w - __high2float(h23));
            uint32_t e = (arow + i * 32) * ASTRIDE + ac4 * 4;
            *(uint2*)(Ah_s + e) = make_uint2(*(uint32_t*)&h01, *(uint32_t*)&h23);
            *(uint2*)(Al_s + e) = make_uint2(*(uint32_t*)&l01, *(uint32_t*)&l23);
        }
        uint32_t eb = brow * ASTRIDE + bc8 * 8;
        *(uint4*)(Bh_s + eb) = fbh;
        *(uint4*)(Bl_s + eb) = fbl;
    };

    auto COMPUTE = [&](int st) {
        uint32_t stb = sbase + (uint32_t)st * STAGE_ELE * 2;
#pragma unroll
        for (int ks = 0; ks < 2; ks++) {
            uint32_t ah[2][4], al[2][4], bh[2][4], bl[2][4];
#pragma unroll
            for (int mt = 0; mt < 2; mt++) {
                uint32_t ad = stb + a_lm + (mt * 16 * ASTRIDE + ks * 16) * 2;
                ldsm4(ah[mt][0], ah[mt][1], ah[mt][2], ah[mt][3], ad);
                ldsm4(al[mt][0], al[mt][1], al[mt][2], al[mt][3], ad + A_TILE_ELE * 2);
            }
#pragma unroll
            for (int ng = 0; ng < 2; ng++) {
                uint32_t bd = stb + b_lm + (ng * 16 * ASTRIDE + ks * 16) * 2;
                ldsm4(bh[ng][0], bh[ng][1], bh[ng][2], bh[ng][3], bd);
                ldsm4(bl[ng][0], bl[ng][1], bl[ng][2], bl[ng][3], bd + B_TILE_ELE * 2);
            }
#pragma unroll
            for (int mt = 0; mt < 2; mt++)
#pragma unroll
                for (int ng = 0; ng < 2; ng++)
#pragma unroll
                    for (int s = 0; s < 2; s++) {
                        float* d = acc[mt][ng * 2 + s];
                        MMA_OP(d, ah[mt], bh[ng][2 * s], bh[ng][2 * s + 1]);
                        MMA_OP(d, ah[mt], bl[ng][2 * s], bl[ng][2 * s + 1]);
                        MMA_OP(d, al[mt], bh[ng][2 * s], bh[ng][2 * s + 1]);
                    }
        }
    };

    const int NI = KTOT / BK;
    LDG(0);
    STS(0);
    __syncthreads();
#pragma unroll 1
    for (int it = 0; it < NI; it++) {
        if (it + 1 < NI) LDG((it + 1) * BK);
        COMPUTE(it & 1);
        __syncthreads();
        if (it + 1 < NI) {
            STS((it + 1) & 1);
            __syncthreads();
        }
    }

    // ---------------- epilogue ----------------
    const int rb = lane >> 2;
    const int cb = (lane & 3) * 2;
    if (mode == 0) {
        int sec = n0 >> 11;
        int head = (n0 >> 7) & 15;
        __nv_bfloat16* dh = (sec == 0) ? g_q_hi : (sec == 1 ? g_k_hi : g_v_hi);
        __nv_bfloat16* dl = (sec == 0) ? g_q_lo : (sec == 1 ? g_k_lo : g_v_lo);
#pragma unroll
        for (int mt = 0; mt < 2; mt++)
#pragma unroll
            for (int hf = 0; hf < 2; hf++) {
                int m = m0 + warp_m * 32 + mt * 16 + hf * 8 + rb;
                int b = m >> 11, t = m & 2047;
                size_t rowbase = ((size_t)(b * NH + head) * T_ + t) * HD;
#pragma unroll
                for (int nt = 0; nt < 4; nt++) {
                    int n = n0 + warp_n * 32 + nt * 8 + cb;
                    int hh = n & 127;
                    float v0 = acc[mt][nt][hf * 2];
                    float v1 = acc[mt][nt][hf * 2 + 1];
                    if (sec) {
                        float cz = cosT[t * FR + (hh >> 1)];
                        float sz = sinT[t * FR + (hh >> 1)];
                        float r0 = v0 * cz - v1 * sz;
                        float r1 = v0 * sz + v1 * cz;
                        v0 = r0; v1 = r1;
                    } else {
                        v0 *= QK_SCALE; v1 *= QK_SCALE;
                    }
                    __nv_bfloat162 h2 = __floats2bfloat162_rn(v0, v1);
                    __nv_bfloat162 l2 = __floats2bfloat162_rn(v0 - __low2float(h2),
                                                              v1 - __high2float(h2));
                    *(__nv_bfloat162*)(dh + rowbase + hh) = h2;
                    *(__nv_bfloat162*)(dl + rowbase + hh) = l2;
                }
            }
    } else {
#pragma unroll
        for (int mt = 0; mt < 2; mt++)
#pragma unroll
            for (int hf = 0; hf < 2; hf++) {
                int m = m0 + warp_m * 32 + mt * 16 + hf * 8 + rb;
#pragma unroll
                for (int nt = 0; nt < 4; nt++) {
                    int n = n0 + warp_n * 32 + nt * 8 + cb;
                    *(float2*)&Cout[(size_t)m * D_ + n] =
                        make_float2(acc[mt][nt][hf * 2], acc[mt][nt][hf * 2 + 1]);
                }
            }
    }
}

// ---------------------------------------------------------------------------
// Tensor-core causal flash attention (split-bf16, 3-MMA scheme both GEMMs).
// 4 warps, Q tile 64 (16 rows/warp), KV tile 64. cp.async loads.
// SMEM: Qh Ql Kh Kl Vh Vl, each [64][136] bf16.
// ---------------------------------------------------------------------------
#define AT_STRIDE 136
#define AT_TILE   (64 * AT_STRIDE)                 // 8704 elements
#define AT_SMEM_BYTES (6 * AT_TILE * 2)            // 104448 B

__global__ __launch_bounds__(128) void attn_mma()
{
    extern __shared__ __nv_bfloat16 sm_at[];
    const int tid = threadIdx.x, wid = tid >> 5, lane = tid & 31;
    const int qt = 31 - (int)blockIdx.x;           // heavy tiles first
    const int qs = qt << 6;
    const int head = blockIdx.y, b = blockIdx.z;
    const size_t hbase = (size_t)(b * NH + head) * T_ * HD;
    const uint32_t sb = smem_u32(sm_at);

    const uint32_t QH = 0, QL = AT_TILE, KH = 2 * AT_TILE, KL = 3 * AT_TILE,
                   VH = 4 * AT_TILE, VL = 5 * AT_TILE;

    // preload Q hi/lo: 64 rows x 128 cols = 1024 16B-chunks per matrix
#pragma unroll
    for (int i = 0; i < 8; i++) {
        int c = tid + i * 128;                     // 0..1023
        int r = c >> 4, col = (c & 15) << 3;
        size_t g = hbase + (size_t)(qs + r) * HD + col;
        uint32_t so = (uint32_t)(r * AT_STRIDE + col) * 2;
        cpa16(sb + QH * 2 + so, g_q_hi + g);
        cpa16(sb + QL * 2 + so, g_q_lo + g);
    }

    float oacc[16][4];
#pragma unroll
    for (int i = 0; i < 16; i++)
#pragma unroll
        for (int j = 0; j < 4; j++) oacc[i][j] = 0.f;
    float mA = -1e30f, mB = -1e30f, lA = 0.f, lB = 0.f;

    // ldmatrix per-lane bases (byte offsets from sb)
    const uint32_t qbase = sb + QH * 2 +
        ((wid * 16 + (lane & 15)) * AT_STRIDE + ((lane >> 4) << 3)) * 2;
    const uint32_t kbase = sb + KH * 2 +
        (((lane & 7) + ((lane >> 4) << 3)) * AT_STRIDE + (((lane >> 3) & 1) << 3)) * 2;
    const uint32_t vbase = sb + VH * 2 +
        ((lane & 15) * AT_STRIDE + ((lane >> 4) << 3)) * 2;

#pragma unroll 1
    for (int jt = 0; jt <= qt; jt++) {
        const int j0 = jt << 6;
        if (jt) __syncthreads();           // everyone done reading prev K/V
#pragma unroll
        for (int i = 0; i < 8; i++) {
            int c = tid + i * 128;                 // 0..1023
            int r = c >> 4, col = (c & 15) << 3;
            size_t g = hbase + (size_t)(j0 + r) * HD + col;
            uint32_t so = (uint32_t)(r * AT_STRIDE + col) * 2;
            cpa16(sb + KH * 2 + so, g_k_hi + g);
            cpa16(sb + KL * 2 + so, g_k_lo + g);
            cpa16(sb + VH * 2 + so, g_v_hi + g);
            cpa16(sb + VL * 2 + so, g_v_lo + g);
        }
        CP_COMMIT();
        CP_WAIT0();
        __syncthreads();

        // ---- S = Q K^T (split 3-MMA), Q pre-scaled ----
        float sacc[8][4];
#pragma unroll
        for (int i = 0; i < 8; i++)
#pragma unroll
            for (int j = 0; j < 4; j++) sacc[i][j] = 0.f;

#pragma unroll
        for (int ks = 0; ks < 8; ks++) {
            uint32_t qh[4], ql[4];
            uint32_t qa = qbase + ks * 32;
            ldsm4(qh[0], qh[1], qh[2], qh[3], qa);
            ldsm4(ql[0], ql[1], ql[2], ql[3], qa + (QL - QH) * 2);
#pragma unroll
            for (int np = 0; np < 4; np++) {
                uint32_t kh[4], kl[4];
                uint32_t ka = kbase + (np * 16 * AT_STRIDE) * 2 + ks * 32;
                ldsm4(kh[0], kh[1], kh[2], kh[3], ka);
                ldsm4(kl[0], kl[1], kl[2], kl[3], ka + (KL - KH) * 2);
                float* d0 = sacc[2 * np];
                float* d1 = sacc[2 * np + 1];
                MMA_OP(d0, qh, kh[0], kh[1]);
                MMA_OP(d0, qh, kl[0], kl[1]);
                MMA_OP(d0, ql, kh[0], kh[1]);
                MMA_OP(d1, qh, kh[2], kh[3]);
                MMA_OP(d1, qh, kl[2], kl[3]);
                MMA_OP(d1, ql, kh[2], kh[3]);
            }
        }

        // ---- causal mask (diagonal tile only) ----
        if (jt == qt) {
            int rA = wid * 16 + (lane >> 2);
            int c0 = 2 * (lane & 3);
#pragma unroll
            for (int nt = 0; nt < 8; nt++) {
                int cc = nt * 8 + c0;
                if (cc > rA)         sacc[nt][0] = -1e30f;
                if (cc + 1 > rA)     sacc[nt][1] = -1e30f;
                if (cc > rA + 8)     sacc[nt][2] = -1e30f;
                if (cc + 1 > rA + 8) sacc[nt][3] = -1e30f;
            }
        }

        // ---- online softmax ----
        float tmA = -1e30f, tmB = -1e30f;
#pragma unroll
        for (int nt = 0; nt < 8; nt++) {
            tmA = fmaxf(tmA, fmaxf(sacc[nt][0], sacc[nt][1]));
            tmB = fmaxf(tmB, fmaxf(sacc[nt][2], sacc[nt][3]));
        }
        tmA = fmaxf(tmA, __shfl_xor_sync(0xffffffffu, tmA, 1));
        tmA = fmaxf(tmA, __shfl_xor_sync(0xffffffffu, tmA, 2));
        tmB = fmaxf(tmB, __shfl_xor_sync(0xffffffffu, tmB, 1));
        tmB = fmaxf(tmB, __shfl_xor_sync(0xffffffffu, tmB, 2));
        float mnA = fmaxf(mA, tmA), mnB = fmaxf(mB, tmB);
        float aAl = __expf(mA - mnA), aBl = __expf(mB - mnB);
        mA = mnA; mB = mnB;

        float psA = 0.f, psB = 0.f;
        uint32_t ph[8][2], pl[8][2];
#pragma unroll
        for (int nt = 0; nt < 8; nt++) {
            float p0 = __expf(sacc[nt][0] - mA);
            float p1 = __expf(sacc[nt][1] - mA);
            float p2 = __expf(sacc[nt][2] - mB);
            float p3 = __expf(sacc[nt][3] - mB);
            psA += p0 + p1;
            psB += p2 + p3;
            __nv_bfloat162 hA2 = __floats2bfloat162_rn(p0, p1);
            __nv_bfloat162 hB2 = __floats2bfloat162_rn(p2, p3);
            __nv_bfloat162 lA2 = __floats2bfloat162_rn(p0 - __low2float(hA2),
                                                       p1 - __high2float(hA2));
            __nv_bfloat162 lB2 = __floats2bfloat162_rn(p2 - __low2float(hB2),
                                                       p3 - __high2float(hB2));
            ph[nt][0] = *(uint32_t*)&hA2;
            ph[nt][1] = *(uint32_t*)&hB2;
            pl[nt][0] = *(uint32_t*)&lA2;
            pl[nt][1] = *(uint32_t*)&lB2;
        }
        lA = lA * aAl + psA;
        lB = lB * aBl + psB;
#pragma unroll
        for (int nt = 0; nt < 16; nt++) {
            oacc[nt][0] *= aAl;
            oacc[nt][1] *= aAl;
            oacc[nt][2] *= aBl;
            oacc[nt][3] *= aBl;
        }

        // ---- O += P V (split 3-MMA), V b-frags via ldmatrix.trans ----
#pragma unroll
        for (int ks = 0; ks < 4; ks++) {
            uint32_t aph[4] = {ph[2 * ks][0], ph[2 * ks][1],
                               ph[2 * ks + 1][0], ph[2 * ks + 1][1]};
            uint32_t apl[4] = {pl[2 * ks][0], pl[2 * ks][1],
                               pl[2 * ks + 1][0], pl[2 * ks + 1][1]};
#pragma unroll
            for (int np = 0; np < 8; np++) {
                uint32_t vh[4], vl[4];
                uint32_t va = vbase + (ks * 16 * AT_STRIDE) * 2 + np * 32;
                ldsm4t(vh[0], vh[1], vh[2], vh[3], va);
                ldsm4t(vl[0], vl[1], vl[2], vl[3], va + (VL - VH) * 2);
                float* d0 = oacc[2 * np];
                float* d1 = oacc[2 * np + 1];
                MMA_OP(d0, aph, vh[0], vh[1]);
                MMA_OP(d0, aph, vl[0], vl[1]);
                MMA_OP(d0, apl, vh[0], vh[1]);
                MMA_OP(d1, aph, vh[2], vh[3]);
                MMA_OP(d1, aph, vl[2], vl[3]);
                MMA_OP(d1, apl, vh[2], vh[3]);
            }
        }
    }

    // ---- finalize: normalize, store fp32 to g_o [B,T,D] ----
    lA += __shfl_xor_sync(0xffffffffu, lA, 1);
    lA += __shfl_xor_sync(0xffffffffu, lA, 2);
    lB += __shfl_xor_sync(0xffffffffu, lB, 1);
    lB += __shfl_xor_sync(0xffffffffu, lB, 2);
    float invA = 1.f / lA, invB = 1.f / lB;

    int rA = qs + wid * 16 + (lane >> 2);
    int c0 = 2 * (lane & 3);
    size_t baseA = ((size_t)(b * T_ + rA)) * D_ + head * HD;
    size_t baseB = baseA + (size_t)8 * D_;
#pragma unroll
    for (int nt = 0; nt < 16; nt++) {
        int cc = nt * 8 + c0;
        *(float2*)&g_o[baseA + cc] = make_float2(oacc[nt][0] * invA, oacc[nt][1] * invA);
        *(float2*)&g_o[baseB + cc] = make_float2(oacc[nt][2] * invB, oacc[nt][3] * invB);
    }
}

// ---------------------------------------------------------------------------
// Launch. Inputs: x, mask, cos, sin, w_attn, w_out. mask is tril -> causal.
// ---------------------------------------------------------------------------
extern "C" void kernel_launch(void* const* d_in, const int* in_sizes, int n_in,
                              void* d_out, int out_size)
{
    const float* x      = (const float*)d_in[0];
    const float* cosT   = (const float*)d_in[2];
    const float* sinT   = (const float*)d_in[3];
    const float* w_attn = (const float*)d_in[4];
    const float* w_out  = (const float*)d_in[5];
    float* out = (float*)d_out;

    cudaFuncSetAttribute(gemm_mma, cudaFuncAttributeMaxDynamicSharedMemorySize,
                         GEMM_SMEM_BYTES);
    cudaFuncSetAttribute(attn_mma, cudaFuncAttributeMaxDynamicSharedMemorySize,
                         AT_SMEM_BYTES);

    // Weight transpose + hi/lo split
    transpose_split<<<dim3(192, 64), dim3(32, 8)>>>(w_attn, D_, 3 * D_, 0);
    transpose_split<<<dim3(64, 64), dim3(32, 8)>>>(w_out, D_, D_, 1);

    // QKV projection + head split + scale/RoPE + bf16 hi/lo store
    gemm_mma<<<dim3(96, 32), 256, GEMM_SMEM_BYTES>>>(x, cosT, sinT, nullptr, 0);

    // Tensor-core flash attention
    attn_mma<<<dim3(32, NH, B_), 128, AT_SMEM_BYTES>>>();

    // Output projection
    gemm_mma<<<dim3(32, 32), 256, GEMM_SMEM_BYTES>>>(nullptr, cosT, sinT, out, 1);
}

// round 7
// speedup vs baseline: 4.5205x; 1.4012x over previous
#include <cuda_runtime.h>
#include <cuda_bf16.h>
#include <cuda_fp16.h>
#include <cstdint>

// Problem constants
#define B_   2
#define T_   2048
#define D_   2048
#define NH   16
#define HD   128
#define FR   64
#define KTOT 2048
#define QK_SCALE 0.08838834764831845f   // 1/sqrt(128)

// ---------------------------------------------------------------------------
// Device-global scratch (allocation-free, graph-capture safe)
// ---------------------------------------------------------------------------
__device__ __half g_x_hi[(size_t)B_ * T_ * D_];          // x split, fp16 hi/lo
__device__ __half g_x_lo[(size_t)B_ * T_ * D_];
__device__ __half g_oh[(size_t)B_ * T_ * D_];            // attn out split
__device__ __half g_ol[(size_t)B_ * T_ * D_];
__device__ __half g_wa_h[(size_t)3 * D_ * D_];           // w_attn^T fp16 hi: [6144][2048]
__device__ __half g_wo_h[(size_t)D_ * D_];               // w_out^T fp16 hi: [2048][2048]
// Q/K/V pre-split bf16 hi/lo, [B,N,T,H]; Q pre-scaled by 1/sqrt(H)
__device__ __nv_bfloat16 g_q_hi[(size_t)B_ * NH * T_ * HD];
__device__ __nv_bfloat16 g_q_lo[(size_t)B_ * NH * T_ * HD];
__device__ __nv_bfloat16 g_k_hi[(size_t)B_ * NH * T_ * HD];
__device__ __nv_bfloat16 g_k_lo[(size_t)B_ * NH * T_ * HD];
__device__ __nv_bfloat16 g_v_hi[(size_t)B_ * NH * T_ * HD];
__device__ __nv_bfloat16 g_v_lo[(size_t)B_ * NH * T_ * HD];

__device__ __forceinline__ uint32_t smem_u32(const void* p) {
    uint32_t a;
    asm("{ .reg .u64 t; cvta.to.shared.u64 t, %1; cvt.u32.u64 %0, t; }"
        : "=r"(a) : "l"(p));
    return a;
}
__device__ __forceinline__ void ldsm4(uint32_t& r0, uint32_t& r1, uint32_t& r2,
                                      uint32_t& r3, uint32_t addr) {
    asm volatile("ldmatrix.sync.aligned.m8n8.x4.shared.b16 {%0,%1,%2,%3}, [%4];"
                 : "=r"(r0), "=r"(r1), "=r"(r2), "=r"(r3) : "r"(addr));
}
__device__ __forceinline__ void ldsm4t(uint32_t& r0, uint32_t& r1, uint32_t& r2,
                                       uint32_t& r3, uint32_t addr) {
    asm volatile("ldmatrix.sync.aligned.m8n8.x4.trans.shared.b16 {%0,%1,%2,%3}, [%4];"
                 : "=r"(r0), "=r"(r1), "=r"(r2), "=r"(r3) : "r"(addr));
}
// bf16 mma (attention)
#define MMA_OP(d, a, b0, b1)                                                   \
    asm volatile("mma.sync.aligned.m16n8k16.row.col.f32.bf16.bf16.f32 "        \
                 "{%0,%1,%2,%3},{%4,%5,%6,%7},{%8,%9},{%0,%1,%2,%3};"          \
                 : "+f"((d)[0]), "+f"((d)[1]), "+f"((d)[2]), "+f"((d)[3])      \
                 : "r"((a)[0]), "r"((a)[1]), "r"((a)[2]), "r"((a)[3]),         \
                   "r"(b0), "r"(b1))
// fp16 mma (projections)
#define MMA_H(d, a, b0, b1)                                                    \
    asm volatile("mma.sync.aligned.m16n8k16.row.col.f32.f16.f16.f32 "          \
                 "{%0,%1,%2,%3},{%4,%5,%6,%7},{%8,%9},{%0,%1,%2,%3};"          \
                 : "+f"((d)[0]), "+f"((d)[1]), "+f"((d)[2]), "+f"((d)[3])      \
                 : "r"((a)[0]), "r"((a)[1]), "r"((a)[2]), "r"((a)[3]),         \
                   "r"(b0), "r"(b1))

__device__ __forceinline__ void cpa16(uint32_t dst, const void* src) {
    asm volatile("cp.async.cg.shared.global [%0], [%1], 16;"
                 :: "r"(dst), "l"(src));
}
#define CP_COMMIT() asm volatile("cp.async.commit_group;" ::: "memory")
#define CP_WAIT0()  asm volatile("cp.async.wait_group 0;" ::: "memory")
#define CP_WAIT2()  asm volatile("cp.async.wait_group 2;" ::: "memory")

// ---------------------------------------------------------------------------
// x -> fp16 hi/lo split (elementwise)
// ---------------------------------------------------------------------------
__global__ __launch_bounds__(256) void split_act(const float* __restrict__ src)
{
    int i = blockIdx.x * 256 + threadIdx.x;          // float4 index
    float4 f = ((const float4*)src)[i];
    __half2 h0 = __floats2half2_rn(f.x, f.y);
    __half2 h1 = __floats2half2_rn(f.z, f.w);
    __half2 l0 = __floats2half2_rn(f.x - __low2float(h0), f.y - __high2float(h0));
    __half2 l1 = __floats2half2_rn(f.z - __low2float(h1), f.w - __high2float(h1));
    ((__half2*)g_x_hi)[2 * i]     = h0;
    ((__half2*)g_x_hi)[2 * i + 1] = h1;
    ((__half2*)g_x_lo)[2 * i]     = l0;
    ((__half2*)g_x_lo)[2 * i + 1] = l1;
}

// ---------------------------------------------------------------------------
// Weight transpose to fp16 (hi only): src fp32 [R][C] -> dst fp16 [C][R]
// ---------------------------------------------------------------------------
__global__ __launch_bounds__(256) void transpose_h(const float* __restrict__ src,
                                                   int R, int C, int which)
{
    __shared__ float tile[32][33];
    __half* dh = which ? g_wo_h : g_wa_h;
    int x = blockIdx.x * 32 + threadIdx.x;
    int y0 = blockIdx.y * 32;
#pragma unroll
    for (int j = 0; j < 32; j += 8)
        tile[threadIdx.y + j][threadIdx.x] = src[(size_t)(y0 + threadIdx.y + j) * C + x];
    __syncthreads();
    int xo = y0 + threadIdx.x;
    int yo = blockIdx.x * 32;
#pragma unroll
    for (int j = 0; j < 32; j += 8)
        dh[(size_t)(yo + threadIdx.y + j) * R + xo] =
            __float2half_rn(tile[threadIdx.x][threadIdx.y + j]);
}

// ---------------------------------------------------------------------------
// 2-MMA fp16 projection GEMM.  C[128x128] = (Ahi+Alo) @ Whi^T
// mode 0: A = x split, W = w_attn^T; epilogue head split + scale(q)/RoPE(k,v),
//         writes Q/K/V as bf16 hi/lo.
// mode 1: A = attn-out split, W = w_out^T; plain fp32 store.
// 256 thr = 8 warps (4m x 2n), warp tile 32x64, BK=32, 4-buffer cp.async.
// ---------------------------------------------------------------------------
#define GSTRIDE 40
#define G_A (128 * GSTRIDE)              // halves per matrix per stage
#define G_STAGE (3 * G_A)                // Ah, Al, Wh
#define G_SMEM (4 * G_STAGE * 2)         // 122880 bytes

__global__ __launch_bounds__(256, 1) void gemm2(
    const float* __restrict__ cosT, const float* __restrict__ sinT,
    float* __restrict__ Cout, int mode)
{
    extern __shared__ __half smem_h[];
    const int tid = threadIdx.x;
    const int wid = tid >> 5, lane = tid & 31;
    const int warp_m = wid & 3, warp_n = wid >> 2;
    const int m0 = (int)blockIdx.y << 7, n0 = (int)blockIdx.x << 7;
    const uint32_t sb = smem_u32(smem_h);

    const __half* Ah_g = mode ? g_oh : g_x_hi;
    const __half* Al_g = mode ? g_ol : g_x_lo;
    const __half* Wh_g = mode ? g_wo_h : g_wa_h;

    float acc[2][8][4];
#pragma unroll
    for (int i = 0; i < 2; i++)
#pragma unroll
        for (int j = 0; j < 8; j++)
#pragma unroll
            for (int k = 0; k < 4; k++) acc[i][j][k] = 0.f;

    // ldmatrix per-lane bases (byte offsets within a stage)
    const uint32_t a_lm = ((warp_m * 32 + (lane & 15)) * GSTRIDE + (lane >> 4) * 8) * 2;
    const uint32_t b_lm = (uint32_t)(2 * G_A +
        (warp_n * 64 + (lane & 7) + ((lane >> 4) << 3)) * GSTRIDE +
        (((lane >> 3) & 1) << 3)) * 2;

    auto LOAD = [&](int stage, int kc) {
        int k0 = kc << 5;
        uint32_t sbs = sb + (uint32_t)stage * G_STAGE * 2;
#pragma unroll
        for (int i = 0; i < 2; i++) {
            int c = tid + (i << 8);              // 0..511
            int r = c >> 2, col = (c & 3) << 3;
            size_t ga = (size_t)(m0 + r) * KTOT + k0 + col;
            size_t gb = (size_t)(n0 + r) * KTOT + k0 + col;
            uint32_t so = (uint32_t)(r * GSTRIDE + col) * 2;
            cpa16(sbs + so, Ah_g + ga);
            cpa16(sbs + (uint32_t)G_A * 2 + so, Al_g + ga);
            cpa16(sbs + (uint32_t)2 * G_A * 2 + so, Wh_g + gb);
        }
        CP_COMMIT();
    };

    auto COMPUTE = [&](int st) {
        uint32_t stb = sb + (uint32_t)st * G_STAGE * 2;
#pragma unroll
        for (int ks = 0; ks < 2; ks++) {
            uint32_t ah[2][4], al[2][4];
#pragma unroll
            for (int mt = 0; mt < 2; mt++) {
                uint32_t ad = stb + a_lm + (mt * 16 * GSTRIDE + ks * 16) * 2;
                ldsm4(ah[mt][0], ah[mt][1], ah[mt][2], ah[mt][3], ad);
                ldsm4(al[mt][0], al[mt][1], al[mt][2], al[mt][3],
                      ad + (uint32_t)G_A * 2);
            }
#pragma unroll
            for (int np = 0; np < 4; np++) {
                uint32_t bh[4];
                ldsm4(bh[0], bh[1], bh[2], bh[3],
                      stb + b_lm + (np * 16 * GSTRIDE + ks * 16) * 2);
#pragma unroll
                for (int mt = 0; mt < 2; mt++) {
                    float* d0 = acc[mt][np * 2];
                    float* d1 = acc[mt][np * 2 + 1];
                    MMA_H(d0, ah[mt], bh[0], bh[1]);
                    MMA_H(d0, al[mt], bh[0], bh[1]);
                    MMA_H(d1, ah[mt], bh[2], bh[3]);
                    MMA_H(d1, al[mt], bh[2], bh[3]);
                }
            }
        }
    };

    const int NI = KTOT / 32;            // 64
    LOAD(0, 0);
    LOAD(1, 1);
    LOAD(2, 2);
#pragma unroll 1
    for (int it = 0; it < NI; it++) {
        CP_WAIT2();
        __syncthreads();
        if (it + 3 < NI) LOAD((it + 3) & 3, it + 3);
        else CP_COMMIT();                // keep group count uniform
        COMPUTE(it & 3);
    }

    // ---------------- epilogue ----------------
    const int rb = lane >> 2;
    const int cb = (lane & 3) * 2;
    if (mode == 0) {
        int sec = n0 >> 11;              // 0=q 1=k 2=v
        int head = (n0 >> 7) & 15;
        __nv_bfloat16* dh = (sec == 0) ? g_q_hi : (sec == 1 ? g_k_hi : g_v_hi);
        __nv_bfloat16* dl = (sec == 0) ? g_q_lo : (sec == 1 ? g_k_lo : g_v_lo);
#pragma unroll
        for (int mt = 0; mt < 2; mt++)
#pragma unroll
            for (int hf = 0; hf < 2; hf++) {
                int m = m0 + warp_m * 32 + mt * 16 + hf * 8 + rb;
                int b = m >> 11, t = m & 2047;
                size_t rowbase = ((size_t)(b * NH + head) * T_ + t) * HD;
#pragma unroll
                for (int j = 0; j < 8; j++) {
                    int hh = warp_n * 64 + j * 8 + cb;
                    float v0 = acc[mt][j][hf * 2];
                    float v1 = acc[mt][j][hf * 2 + 1];
                    if (sec) {
                        float cz = cosT[t * FR + (hh >> 1)];
                        float sz = sinT[t * FR + (hh >> 1)];
                        float r0 = v0 * cz - v1 * sz;
                        float r1 = v0 * sz + v1 * cz;
                        v0 = r0; v1 = r1;
                    } else {
                        v0 *= QK_SCALE; v1 *= QK_SCALE;
                    }
                    __nv_bfloat162 h2 = __floats2bfloat162_rn(v0, v1);
                    __nv_bfloat162 l2 = __floats2bfloat162_rn(v0 - __low2float(h2),
                                                              v1 - __high2float(h2));
                    *(__nv_bfloat162*)(dh + rowbase + hh) = h2;
                    *(__nv_bfloat162*)(dl + rowbase + hh) = l2;
                }
            }
    } else {
#pragma unroll
        for (int mt = 0; mt < 2; mt++)
#pragma unroll
            for (int hf = 0; hf < 2; hf++) {
                int m = m0 + warp_m * 32 + mt * 16 + hf * 8 + rb;
#pragma unroll
                for (int j = 0; j < 8; j++) {
                    int n = n0 + warp_n * 64 + j * 8 + cb;
                    *(float2*)&Cout[(size_t)m * D_ + n] =
                        make_float2(acc[mt][j][hf * 2], acc[mt][j][hf * 2 + 1]);
                }
            }
    }
}

// ---------------------------------------------------------------------------
// Tensor-core causal flash attention (split-bf16, 3-MMA; unchanged math).
// Epilogue writes fp16 hi/lo for the out-projection.
// ---------------------------------------------------------------------------
#define AT_STRIDE 136
#define AT_TILE   (64 * AT_STRIDE)
#define AT_SMEM_BYTES (6 * AT_TILE * 2)

__global__ __launch_bounds__(128) void attn_mma()
{
    extern __shared__ __nv_bfloat16 sm_at[];
    const int tid = threadIdx.x, wid = tid >> 5, lane = tid & 31;
    const int qt = 31 - (int)blockIdx.x;
    const int qs = qt << 6;
    const int head = blockIdx.y, b = blockIdx.z;
    const size_t hbase = (size_t)(b * NH + head) * T_ * HD;
    const uint32_t sb = smem_u32(sm_at);

    const uint32_t QH = 0, QL = AT_TILE, KH = 2 * AT_TILE, KL = 3 * AT_TILE,
                   VH = 4 * AT_TILE, VL = 5 * AT_TILE;

#pragma unroll
    for (int i = 0; i < 8; i++) {
        int c = tid + i * 128;
        int r = c >> 4, col = (c & 15) << 3;
        size_t g = hbase + (size_t)(qs + r) * HD + col;
        uint32_t so = (uint32_t)(r * AT_STRIDE + col) * 2;
        cpa16(sb + QH * 2 + so, g_q_hi + g);
        cpa16(sb + QL * 2 + so, g_q_lo + g);
    }

    float oacc[16][4];
#pragma unroll
    for (int i = 0; i < 16; i++)
#pragma unroll
        for (int j = 0; j < 4; j++) oacc[i][j] = 0.f;
    float mA = -1e30f, mB = -1e30f, lA = 0.f, lB = 0.f;

    const uint32_t qbase = sb + QH * 2 +
        ((wid * 16 + (lane & 15)) * AT_STRIDE + ((lane >> 4) << 3)) * 2;
    const uint32_t kbase = sb + KH * 2 +
        (((lane & 7) + ((lane >> 4) << 3)) * AT_STRIDE + (((lane >> 3) & 1) << 3)) * 2;
    const uint32_t vbase = sb + VH * 2 +
        ((lane & 15) * AT_STRIDE + ((lane >> 4) << 3)) * 2;

#pragma unroll 1
    for (int jt = 0; jt <= qt; jt++) {
        const int j0 = jt << 6;
        if (jt) __syncthreads();
#pragma unroll
        for (int i = 0; i < 8; i++) {
            int c = tid + i * 128;
            int r = c >> 4, col = (c & 15) << 3;
            size_t g = hbase + (size_t)(j0 + r) * HD + col;
            uint32_t so = (uint32_t)(r * AT_STRIDE + col) * 2;
            cpa16(sb + KH * 2 + so, g_k_hi + g);
            cpa16(sb + KL * 2 + so, g_k_lo + g);
            cpa16(sb + VH * 2 + so, g_v_hi + g);
            cpa16(sb + VL * 2 + so, g_v_lo + g);
        }
        CP_COMMIT();
        CP_WAIT0();
        __syncthreads();

        float sacc[8][4];
#pragma unroll
        for (int i = 0; i < 8; i++)
#pragma unroll
            for (int j = 0; j < 4; j++) sacc[i][j] = 0.f;

#pragma unroll
        for (int ks = 0; ks < 8; ks++) {
            uint32_t qh[4], ql[4];
            uint32_t qa = qbase + ks * 32;
            ldsm4(qh[0], qh[1], qh[2], qh[3], qa);
            ldsm4(ql[0], ql[1], ql[2], ql[3], qa + (QL - QH) * 2);
#pragma unroll
            for (int np = 0; np < 4; np++) {
                uint32_t kh[4], kl[4];
                uint32_t ka = kbase + (np * 16 * AT_STRIDE) * 2 + ks * 32;
                ldsm4(kh[0], kh[1], kh[2], kh[3], ka);
                ldsm4(kl[0], kl[1], kl[2], kl[3], ka + (KL - KH) * 2);
                float* d0 = sacc[2 * np];
                float* d1 = sacc[2 * np + 1];
                MMA_OP(d0, qh, kh[0], kh[1]);
                MMA_OP(d0, qh, kl[0], kl[1]);
                MMA_OP(d0, ql, kh[0], kh[1]);
                MMA_OP(d1, qh, kh[2], kh[3]);
                MMA_OP(d1, qh, kl[2], kl[3]);
                MMA_OP(d1, ql, kh[2], kh[3]);
            }
        }

        if (jt == qt) {
            int rA = wid * 16 + (lane >> 2);
            int c0 = 2 * (lane & 3);
#pragma unroll
            for (int nt = 0; nt < 8; nt++) {
                int cc = nt * 8 + c0;
                if (cc > rA)         sacc[nt][0] = -1e30f;
                if (cc + 1 > rA)     sacc[nt][1] = -1e30f;
                if (cc > rA + 8)     sacc[nt][2] = -1e30f;
                if (cc + 1 > rA + 8) sacc[nt][3] = -1e30f;
            }
        }

        float tmA = -1e30f, tmB = -1e30f;
#pragma unroll
        for (int nt = 0; nt < 8; nt++) {
            tmA = fmaxf(tmA, fmaxf(sacc[nt][0], sacc[nt][1]));
            tmB = fmaxf(tmB, fmaxf(sacc[nt][2], sacc[nt][3]));
        }
        tmA = fmaxf(tmA, __shfl_xor_sync(0xffffffffu, tmA, 1));
        tmA = fmaxf(tmA, __shfl_xor_sync(0xffffffffu, tmA, 2));
        tmB = fmaxf(tmB, __shfl_xor_sync(0xffffffffu, tmB, 1));
        tmB = fmaxf(tmB, __shfl_xor_sync(0xffffffffu, tmB, 2));
        float mnA = fmaxf(mA, tmA), mnB = fmaxf(mB, tmB);
        float aAl = __expf(mA - mnA), aBl = __expf(mB - mnB);
        mA = mnA; mB = mnB;

        float psA = 0.f, psB = 0.f;
        uint32_t ph[8][2], pl[8][2];
#pragma unroll
        for (int nt = 0; nt < 8; nt++) {
            float p0 = __expf(sacc[nt][0] - mA);
            float p1 = __expf(sacc[nt][1] - mA);
            float p2 = __expf(sacc[nt][2] - mB);
            float p3 = __expf(sacc[nt][3] - mB);
            psA += p0 + p1;
            psB += p2 + p3;
            __nv_bfloat162 hA2 = __floats2bfloat162_rn(p0, p1);
            __nv_bfloat162 hB2 = __floats2bfloat162_rn(p2, p3);
            __nv_bfloat162 lA2 = __floats2bfloat162_rn(p0 - __low2float(hA2),
                                                       p1 - __high2float(hA2));
            __nv_bfloat162 lB2 = __floats2bfloat162_rn(p2 - __low2float(hB2),
                                                       p3 - __high2float(hB2));
            ph[nt][0] = *(uint32_t*)&hA2;
            ph[nt][1] = *(uint32_t*)&hB2;
            pl[nt][0] = *(uint32_t*)&lA2;
            pl[nt][1] = *(uint32_t*)&lB2;
        }
        lA = lA * aAl + psA;
        lB = lB * aBl + psB;
#pragma unroll
        for (int nt = 0; nt < 16; nt++) {
            oacc[nt][0] *= aAl;
            oacc[nt][1] *= aAl;
            oacc[nt][2] *= aBl;
            oacc[nt][3] *= aBl;
        }

#pragma unroll
        for (int ks = 0; ks < 4; ks++) {
            uint32_t aph[4] = {ph[2 * ks][0], ph[2 * ks][1],
                               ph[2 * ks + 1][0], ph[2 * ks + 1][1]};
            uint32_t apl[4] = {pl[2 * ks][0], pl[2 * ks][1],
                               pl[2 * ks + 1][0], pl[2 * ks + 1][1]};
#pragma unroll
            for (int np = 0; np < 8; np++) {
                uint32_t vh[4], vl[4];
                uint32_t va = vbase + (ks * 16 * AT_STRIDE) * 2 + np * 32;
                ldsm4t(vh[0], vh[1], vh[2], vh[3], va);
                ldsm4t(vl[0], vl[1], vl[2], vl[3], va + (VL - VH) * 2);
                float* d0 = oacc[2 * np];
                float* d1 = oacc[2 * np + 1];
                MMA_OP(d0, aph, vh[0], vh[1]);
                MMA_OP(d0, aph, vl[0], vl[1]);
                MMA_OP(d0, apl, vh[0], vh[1]);
                MMA_OP(d1, aph, vh[2], vh[3]);
                MMA_OP(d1, aph, vl[2], vl[3]);
                MMA_OP(d1, apl, vh[2], vh[3]);
            }
        }
    }

    // ---- finalize: normalize, write fp16 hi/lo to g_oh/g_ol [B,T,D] ----
    lA += __shfl_xor_sync(0xffffffffu, lA, 1);
    lA += __shfl_xor_sync(0xffffffffu, lA, 2);
    lB += __shfl_xor_sync(0xffffffffu, lB, 1);
    lB += __shfl_xor_sync(0xffffffffu, lB, 2);
    float invA = 1.f / lA, invB = 1.f / lB;

    int rA = qs + wid * 16 + (lane >> 2);
    int c0 = 2 * (lane & 3);
    size_t baseA = ((size_t)(b * T_ + rA)) * D_ + head * HD;
    size_t baseB = baseA + (size_t)8 * D_;
#pragma unroll
    for (int nt = 0; nt < 16; nt++) {
        int cc = nt * 8 + c0;
        float a0 = oacc[nt][0] * invA, a1 = oacc[nt][1] * invA;
        float b0 = oacc[nt][2] * invB, b1 = oacc[nt][3] * invB;
        __half2 hA = __floats2half2_rn(a0, a1);
        __half2 lA2 = __floats2half2_rn(a0 - __low2float(hA), a1 - __high2float(hA));
        __half2 hB = __floats2half2_rn(b0, b1);
        __half2 lB2 = __floats2half2_rn(b0 - __low2float(hB), b1 - __high2float(hB));
        *(__half2*)(g_oh + baseA + cc) = hA;
        *(__half2*)(g_ol + baseA + cc) = lA2;
        *(__half2*)(g_oh + baseB + cc) = hB;
        *(__half2*)(g_ol + baseB + cc) = lB2;
    }
}

// ---------------------------------------------------------------------------
// Launch. Inputs: x, mask, cos, sin, w_attn, w_out. mask is tril -> causal.
// ---------------------------------------------------------------------------
extern "C" void kernel_launch(void* const* d_in, const int* in_sizes, int n_in,
                              void* d_out, int out_size)
{
    const float* x      = (const float*)d_in[0];
    const float* cosT   = (const float*)d_in[2];
    const float* sinT   = (const float*)d_in[3];
    const float* w_attn = (const float*)d_in[4];
    const float* w_out  = (const float*)d_in[5];
    float* out = (float*)d_out;

    cudaFuncSetAttribute(gemm2, cudaFuncAttributeMaxDynamicSharedMemorySize, G_SMEM);
    cudaFuncSetAttribute(attn_mma, cudaFuncAttributeMaxDynamicSharedMemorySize,
                         AT_SMEM_BYTES);

    // Preprocessing: x split + weight transposes (fp16 hi)
    split_act<<<(B_ * T_ * D_ / 4) / 256, 256>>>(x);
    transpose_h<<<dim3(192, 64), dim3(32, 8)>>>(w_attn, D_, 3 * D_, 0);
    transpose_h<<<dim3(64, 64), dim3(32, 8)>>>(w_out, D_, D_, 1);

    // QKV projection (2-MMA fp16) + head split + scale/RoPE -> bf16 hi/lo
    gemm2<<<dim3(48, 32), 256, G_SMEM>>>(cosT, sinT, nullptr, 0);

    // Tensor-core flash attention (3-MMA bf16) -> fp16 hi/lo
    attn_mma<<<dim3(32, NH, B_), 128, AT_SMEM_BYTES>>>();

    // Output projection (2-MMA fp16)
    gemm2<<<dim3(16, 32), 256, G_SMEM>>>(cosT, sinT, out, 1);
}

// round 8
// speedup vs baseline: 4.6002x; 1.0176x over previous
#include <cuda_runtime.h>
#include <cuda_bf16.h>
#include <cuda_fp16.h>
#include <cstdint>

// Problem constants
#define B_   2
#define T_   2048
#define D_   2048
#define NH   16
#define HD   128
#define FR   64
#define KTOT 2048
#define QK_SCALE 0.08838834764831845f   // 1/sqrt(128)

// ---------------------------------------------------------------------------
// Device-global scratch (allocation-free, graph-capture safe)
// ---------------------------------------------------------------------------
__device__ __half g_x_hi[(size_t)B_ * T_ * D_];          // x split, fp16 hi/lo
__device__ __half g_x_lo[(size_t)B_ * T_ * D_];
__device__ __half g_oh[(size_t)B_ * T_ * D_];            // attn out split
__device__ __half g_ol[(size_t)B_ * T_ * D_];
__device__ __half g_wa_h[(size_t)3 * D_ * D_];           // w_attn^T fp16 hi: [6144][2048]
__device__ __half g_wo_h[(size_t)D_ * D_];               // w_out^T fp16 hi: [2048][2048]
// Q/K/V pre-split bf16 hi/lo, [B,N,T,H]; Q pre-scaled by 1/sqrt(H)
__device__ __nv_bfloat16 g_q_hi[(size_t)B_ * NH * T_ * HD];
__device__ __nv_bfloat16 g_q_lo[(size_t)B_ * NH * T_ * HD];
__device__ __nv_bfloat16 g_k_hi[(size_t)B_ * NH * T_ * HD];
__device__ __nv_bfloat16 g_k_lo[(size_t)B_ * NH * T_ * HD];
__device__ __nv_bfloat16 g_v_hi[(size_t)B_ * NH * T_ * HD];
__device__ __nv_bfloat16 g_v_lo[(size_t)B_ * NH * T_ * HD];

__device__ __forceinline__ uint32_t smem_u32(const void* p) {
    uint32_t a;
    asm("{ .reg .u64 t; cvta.to.shared.u64 t, %1; cvt.u32.u64 %0, t; }"
        : "=r"(a) : "l"(p));
    return a;
}
__device__ __forceinline__ void ldsm4(uint32_t& r0, uint32_t& r1, uint32_t& r2,
                                      uint32_t& r3, uint32_t addr) {
    asm volatile("ldmatrix.sync.aligned.m8n8.x4.shared.b16 {%0,%1,%2,%3}, [%4];"
                 : "=r"(r0), "=r"(r1), "=r"(r2), "=r"(r3) : "r"(addr));
}
__device__ __forceinline__ void ldsm4t(uint32_t& r0, uint32_t& r1, uint32_t& r2,
                                       uint32_t& r3, uint32_t addr) {
    asm volatile("ldmatrix.sync.aligned.m8n8.x4.trans.shared.b16 {%0,%1,%2,%3}, [%4];"
                 : "=r"(r0), "=r"(r1), "=r"(r2), "=r"(r3) : "r"(addr));
}
// bf16 mma (attention)
#define MMA_OP(d, a, b0, b1)                                                   \
    asm volatile("mma.sync.aligned.m16n8k16.row.col.f32.bf16.bf16.f32 "        \
                 "{%0,%1,%2,%3},{%4,%5,%6,%7},{%8,%9},{%0,%1,%2,%3};"          \
                 : "+f"((d)[0]), "+f"((d)[1]), "+f"((d)[2]), "+f"((d)[3])      \
                 : "r"((a)[0]), "r"((a)[1]), "r"((a)[2]), "r"((a)[3]),         \
                   "r"(b0), "r"(b1))
// fp16 mma (projections)
#define MMA_H(d, a, b0, b1)                                                    \
    asm volatile("mma.sync.aligned.m16n8k16.row.col.f32.f16.f16.f32 "          \
                 "{%0,%1,%2,%3},{%4,%5,%6,%7},{%8,%9},{%0,%1,%2,%3};"          \
                 : "+f"((d)[0]), "+f"((d)[1]), "+f"((d)[2]), "+f"((d)[3])      \
                 : "r"((a)[0]), "r"((a)[1]), "r"((a)[2]), "r"((a)[3]),         \
                   "r"(b0), "r"(b1))

__device__ __forceinline__ void cpa16(uint32_t dst, const void* src) {
    asm volatile("cp.async.cg.shared.global [%0], [%1], 16;"
                 :: "r"(dst), "l"(src));
}
#define CP_COMMIT() asm volatile("cp.async.commit_group;" ::: "memory")
#define CP_WAIT0()  asm volatile("cp.async.wait_group 0;" ::: "memory")
#define CP_WAIT2()  asm volatile("cp.async.wait_group 2;" ::: "memory")

// ---------------------------------------------------------------------------
// x -> fp16 hi/lo split (elementwise)
// ---------------------------------------------------------------------------
__global__ __launch_bounds__(256) void split_act(const float* __restrict__ src)
{
    int i = blockIdx.x * 256 + threadIdx.x;          // float4 index
    float4 f = ((const float4*)src)[i];
    __half2 h0 = __floats2half2_rn(f.x, f.y);
    __half2 h1 = __floats2half2_rn(f.z, f.w);
    __half2 l0 = __floats2half2_rn(f.x - __low2float(h0), f.y - __high2float(h0));
    __half2 l1 = __floats2half2_rn(f.z - __low2float(h1), f.w - __high2float(h1));
    ((__half2*)g_x_hi)[2 * i]     = h0;
    ((__half2*)g_x_hi)[2 * i + 1] = h1;
    ((__half2*)g_x_lo)[2 * i]     = l0;
    ((__half2*)g_x_lo)[2 * i + 1] = l1;
}

// ---------------------------------------------------------------------------
// Weight transpose to fp16 (hi only): src fp32 [R][C] -> dst fp16 [C][R]
// ---------------------------------------------------------------------------
__global__ __launch_bounds__(256) void transpose_h(const float* __restrict__ src,
                                                   int R, int C, int which)
{
    __shared__ float tile[32][33];
    __half* dh = which ? g_wo_h : g_wa_h;
    int x = blockIdx.x * 32 + threadIdx.x;
    int y0 = blockIdx.y * 32;
#pragma unroll
    for (int j = 0; j < 32; j += 8)
        tile[threadIdx.y + j][threadIdx.x] = src[(size_t)(y0 + threadIdx.y + j) * C + x];
    __syncthreads();
    int xo = y0 + threadIdx.x;
    int yo = blockIdx.x * 32;
#pragma unroll
    for (int j = 0; j < 32; j += 8)
        dh[(size_t)(yo + threadIdx.y + j) * R + xo] =
            __float2half_rn(tile[threadIdx.x][threadIdx.y + j]);
}

// ---------------------------------------------------------------------------
// 2-MMA fp16 projection GEMM.  C[128 x 64] = (Ahi+Alo) @ Whi^T
// 256 thr = 8 warps (4m x 2n), warp tile 32x32, BK=32, 4-stage cp.async,
// 100 KB smem -> 2 CTAs/SM so barriers/latency of one CTA hide under the
// other CTA's MMAs.
// mode 0: epilogue head split + scale(q)/RoPE(k,v) -> bf16 hi/lo Q/K/V.
// mode 1: plain fp32 store.
// ---------------------------------------------------------------------------
#define GSTRIDE 40
#define GA_ELE (128 * GSTRIDE)           // 5120 halves per A matrix per stage
#define GW_ELE (64 * GSTRIDE)            // 2560 halves for W per stage
#define G_STAGE_ELE (2 * GA_ELE + GW_ELE)   // 12800 halves
#define G_SMEM (4 * G_STAGE_ELE * 2)        // 102400 bytes

__global__ __launch_bounds__(256, 2) void gemm2(
    const float* __restrict__ cosT, const float* __restrict__ sinT,
    float* __restrict__ Cout, int mode)
{
    extern __shared__ __half smem_h[];
    const int tid = threadIdx.x;
    const int wid = tid >> 5, lane = tid & 31;
    const int warp_m = wid & 3, warp_n = wid >> 2;
    const int m0 = (int)blockIdx.y << 7, n0 = (int)blockIdx.x << 6;
    const uint32_t sb = smem_u32(smem_h);

    const __half* Ah_g = mode ? g_oh : g_x_hi;
    const __half* Al_g = mode ? g_ol : g_x_lo;
    const __half* Wh_g = mode ? g_wo_h : g_wa_h;

    float acc[2][4][4];
#pragma unroll
    for (int i = 0; i < 2; i++)
#pragma unroll
        for (int j = 0; j < 4; j++)
#pragma unroll
            for (int k = 0; k < 4; k++) acc[i][j][k] = 0.f;

    // ldmatrix per-lane bases (byte offsets within a stage)
    const uint32_t a_lm = ((warp_m * 32 + (lane & 15)) * GSTRIDE + (lane >> 4) * 8) * 2;
    const uint32_t b_lm = (uint32_t)(2 * GA_ELE +
        (warp_n * 32 + (lane & 7) + ((lane >> 4) << 3)) * GSTRIDE +
        (((lane >> 3) & 1) << 3)) * 2;

    auto LOAD = [&](int stage, int kc) {
        int k0 = kc << 5;
        uint32_t sbs = sb + (uint32_t)stage * G_STAGE_ELE * 2;
        // A hi/lo: 512 chunks each (2 per thread)
#pragma unroll
        for (int i = 0; i < 2; i++) {
            int c = tid + (i << 8);
            int r = c >> 2, col = (c & 3) << 3;
            size_t ga = (size_t)(m0 + r) * KTOT + k0 + col;
            uint32_t so = (uint32_t)(r * GSTRIDE + col) * 2;
            cpa16(sbs + so, Ah_g + ga);
            cpa16(sbs + (uint32_t)GA_ELE * 2 + so, Al_g + ga);
        }
        // W: 256 chunks (1 per thread)
        {
            int r = tid >> 2, col = (tid & 3) << 3;
            size_t gb = (size_t)(n0 + r) * KTOT + k0 + col;
            uint32_t so = (uint32_t)(r * GSTRIDE + col) * 2;
            cpa16(sbs + (uint32_t)2 * GA_ELE * 2 + so, Wh_g + gb);
        }
        CP_COMMIT();
    };

    auto COMPUTE = [&](int st) {
        uint32_t stb = sb + (uint32_t)st * G_STAGE_ELE * 2;
#pragma unroll
        for (int ks = 0; ks < 2; ks++) {
            uint32_t ah[2][4], al[2][4], bh[2][4];
#pragma unroll
            for (int mt = 0; mt < 2; mt++) {
                uint32_t ad = stb + a_lm + (mt * 16 * GSTRIDE + ks * 16) * 2;
                ldsm4(ah[mt][0], ah[mt][1], ah[mt][2], ah[mt][3], ad);
                ldsm4(al[mt][0], al[mt][1], al[mt][2], al[mt][3],
                      ad + (uint32_t)GA_ELE * 2);
            }
#pragma unroll
            for (int np = 0; np < 2; np++)
                ldsm4(bh[np][0], bh[np][1], bh[np][2], bh[np][3],
                      stb + b_lm + (np * 16 * GSTRIDE + ks * 16) * 2);
#pragma unroll
            for (int mt = 0; mt < 2; mt++)
#pragma unroll
                for (int np = 0; np < 2; np++) {
                    float* d0 = acc[mt][np * 2];
                    float* d1 = acc[mt][np * 2 + 1];
                    MMA_H(d0, ah[mt], bh[np][0], bh[np][1]);
                    MMA_H(d0, al[mt], bh[np][0], bh[np][1]);
                    MMA_H(d1, ah[mt], bh[np][2], bh[np][3]);
                    MMA_H(d1, al[mt], bh[np][2], bh[np][3]);
                }
        }
    };

    const int NI = KTOT / 32;            // 64
    LOAD(0, 0);
    LOAD(1, 1);
    LOAD(2, 2);
#pragma unroll 1
    for (int it = 0; it < NI; it++) {
        CP_WAIT2();
        __syncthreads();
        if (it + 3 < NI) LOAD((it + 3) & 3, it + 3);
        else CP_COMMIT();                // keep group count uniform
        COMPUTE(it & 3);
    }

    // ---------------- epilogue ----------------
    const int rb = lane >> 2;
    const int cb = (lane & 3) * 2;
    if (mode == 0) {
        int sec = n0 >> 11;              // 0=q 1=k 2=v
        int head = (n0 >> 7) & 15;
        __nv_bfloat16* dh = (sec == 0) ? g_q_hi : (sec == 1 ? g_k_hi : g_v_hi);
        __nv_bfloat16* dl = (sec == 0) ? g_q_lo : (sec == 1 ? g_k_lo : g_v_lo);
#pragma unroll
        for (int mt = 0; mt < 2; mt++)
#pragma unroll
            for (int hf = 0; hf < 2; hf++) {
                int m = m0 + warp_m * 32 + mt * 16 + hf * 8 + rb;
                int b = m >> 11, t = m & 2047;
                size_t rowbase = ((size_t)(b * NH + head) * T_ + t) * HD;
#pragma unroll
                for (int j = 0; j < 4; j++) {
                    int n = n0 + warp_n * 32 + j * 8 + cb;
                    int hh = n & 127;
                    float v0 = acc[mt][j][hf * 2];
                    float v1 = acc[mt][j][hf * 2 + 1];
                    if (sec) {
                        float cz = cosT[t * FR + (hh >> 1)];
                        float sz = sinT[t * FR + (hh >> 1)];
                        float r0 = v0 * cz - v1 * sz;
                        float r1 = v0 * sz + v1 * cz;
                        v0 = r0; v1 = r1;
                    } else {
                        v0 *= QK_SCALE; v1 *= QK_SCALE;
                    }
                    __nv_bfloat162 h2 = __floats2bfloat162_rn(v0, v1);
                    __nv_bfloat162 l2 = __floats2bfloat162_rn(v0 - __low2float(h2),
                                                              v1 - __high2float(h2));
                    *(__nv_bfloat162*)(dh + rowbase + hh) = h2;
                    *(__nv_bfloat162*)(dl + rowbase + hh) = l2;
                }
            }
    } else {
#pragma unroll
        for (int mt = 0; mt < 2; mt++)
#pragma unroll
            for (int hf = 0; hf < 2; hf++) {
                int m = m0 + warp_m * 32 + mt * 16 + hf * 8 + rb;
#pragma unroll
                for (int j = 0; j < 4; j++) {
                    int n = n0 + warp_n * 32 + j * 8 + cb;
                    *(float2*)&Cout[(size_t)m * D_ + n] =
                        make_float2(acc[mt][j][hf * 2], acc[mt][j][hf * 2 + 1]);
                }
            }
    }
}

// ---------------------------------------------------------------------------
// Tensor-core causal flash attention (split-bf16, 3-MMA; unchanged).
// Epilogue writes fp16 hi/lo for the out-projection.
// ---------------------------------------------------------------------------
#define AT_STRIDE 136
#define AT_TILE   (64 * AT_STRIDE)
#define AT_SMEM_BYTES (6 * AT_TILE * 2)

__global__ __launch_bounds__(128) void attn_mma()
{
    extern __shared__ __nv_bfloat16 sm_at[];
    const int tid = threadIdx.x, wid = tid >> 5, lane = tid & 31;
    const int qt = 31 - (int)blockIdx.x;
    const int qs = qt << 6;
    const int head = blockIdx.y, b = blockIdx.z;
    const size_t hbase = (size_t)(b * NH + head) * T_ * HD;
    const uint32_t sb = smem_u32(sm_at);

    const uint32_t QH = 0, QL = AT_TILE, KH = 2 * AT_TILE, KL = 3 * AT_TILE,
                   VH = 4 * AT_TILE, VL = 5 * AT_TILE;

#pragma unroll
    for (int i = 0; i < 8; i++) {
        int c = tid + i * 128;
        int r = c >> 4, col = (c & 15) << 3;
        size_t g = hbase + (size_t)(qs + r) * HD + col;
        uint32_t so = (uint32_t)(r * AT_STRIDE + col) * 2;
        cpa16(sb + QH * 2 + so, g_q_hi + g);
        cpa16(sb + QL * 2 + so, g_q_lo + g);
    }

    float oacc[16][4];
#pragma unroll
    for (int i = 0; i < 16; i++)
#pragma unroll
        for (int j = 0; j < 4; j++) oacc[i][j] = 0.f;
    float mA = -1e30f, mB = -1e30f, lA = 0.f, lB = 0.f;

    const uint32_t qbase = sb + QH * 2 +
        ((wid * 16 + (lane & 15)) * AT_STRIDE + ((lane >> 4) << 3)) * 2;
    const uint32_t kbase = sb + KH * 2 +
        (((lane & 7) + ((lane >> 4) << 3)) * AT_STRIDE + (((lane >> 3) & 1) << 3)) * 2;
    const uint32_t vbase = sb + VH * 2 +
        ((lane & 15) * AT_STRIDE + ((lane >> 4) << 3)) * 2;

#pragma unroll 1
    for (int jt = 0; jt <= qt; jt++) {
        const int j0 = jt << 6;
        if (jt) __syncthreads();
#pragma unroll
        for (int i = 0; i < 8; i++) {
            int c = tid + i * 128;
            int r = c >> 4, col = (c & 15) << 3;
            size_t g = hbase + (size_t)(j0 + r) * HD + col;
            uint32_t so = (uint32_t)(r * AT_STRIDE + col) * 2;
            cpa16(sb + KH * 2 + so, g_k_hi + g);
            cpa16(sb + KL * 2 + so, g_k_lo + g);
            cpa16(sb + VH * 2 + so, g_v_hi + g);
            cpa16(sb + VL * 2 + so, g_v_lo + g);
        }
        CP_COMMIT();
        CP_WAIT0();
        __syncthreads();

        float sacc[8][4];
#pragma unroll
        for (int i = 0; i < 8; i++)
#pragma unroll
            for (int j = 0; j < 4; j++) sacc[i][j] = 0.f;

#pragma unroll
        for (int ks = 0; ks < 8; ks++) {
            uint32_t qh[4], ql[4];
            uint32_t qa = qbase + ks * 32;
            ldsm4(qh[0], qh[1], qh[2], qh[3], qa);
            ldsm4(ql[0], ql[1], ql[2], ql[3], qa + (QL - QH) * 2);
#pragma unroll
            for (int np = 0; np < 4; np++) {
                uint32_t kh[4], kl[4];
                uint32_t ka = kbase + (np * 16 * AT_STRIDE) * 2 + ks * 32;
                ldsm4(kh[0], kh[1], kh[2], kh[3], ka);
                ldsm4(kl[0], kl[1], kl[2], kl[3], ka + (KL - KH) * 2);
                float* d0 = sacc[2 * np];
                float* d1 = sacc[2 * np + 1];
                MMA_OP(d0, qh, kh[0], kh[1]);
                MMA_OP(d0, qh, kl[0], kl[1]);
                MMA_OP(d0, ql, kh[0], kh[1]);
                MMA_OP(d1, qh, kh[2], kh[3]);
                MMA_OP(d1, qh, kl[2], kl[3]);
                MMA_OP(d1, ql, kh[2], kh[3]);
            }
        }

        if (jt == qt) {
            int rA = wid * 16 + (lane >> 2);
            int c0 = 2 * (lane & 3);
#pragma unroll
            for (int nt = 0; nt < 8; nt++) {
                int cc = nt * 8 + c0;
                if (cc > rA)         sacc[nt][0] = -1e30f;
                if (cc + 1 > rA)     sacc[nt][1] = -1e30f;
                if (cc > rA + 8)     sacc[nt][2] = -1e30f;
                if (cc + 1 > rA + 8) sacc[nt][3] = -1e30f;
            }
        }

        float tmA = -1e30f, tmB = -1e30f;
#pragma unroll
        for (int nt = 0; nt < 8; nt++) {
            tmA = fmaxf(tmA, fmaxf(sacc[nt][0], sacc[nt][1]));
            tmB = fmaxf(tmB, fmaxf(sacc[nt][2], sacc[nt][3]));
        }
        tmA = fmaxf(tmA, __shfl_xor_sync(0xffffffffu, tmA, 1));
        tmA = fmaxf(tmA, __shfl_xor_sync(0xffffffffu, tmA, 2));
        tmB = fmaxf(tmB, __shfl_xor_sync(0xffffffffu, tmB, 1));
        tmB = fmaxf(tmB, __shfl_xor_sync(0xffffffffu, tmB, 2));
        float mnA = fmaxf(mA, tmA), mnB = fmaxf(mB, tmB);
        float aAl = __expf(mA - mnA), aBl = __expf(mB - mnB);
        mA = mnA; mB = mnB;

        float psA = 0.f, psB = 0.f;
        uint32_t ph[8][2], pl[8][2];
#pragma unroll
        for (int nt = 0; nt < 8; nt++) {
            float p0 = __expf(sacc[nt][0] - mA);
            float p1 = __expf(sacc[nt][1] - mA);
            float p2 = __expf(sacc[nt][2] - mB);
            float p3 = __expf(sacc[nt][3] - mB);
            psA += p0 + p1;
            psB += p2 + p3;
            __nv_bfloat162 hA2 = __floats2bfloat162_rn(p0, p1);
            __nv_bfloat162 hB2 = __floats2bfloat162_rn(p2, p3);
            __nv_bfloat162 lA2 = __floats2bfloat162_rn(p0 - __low2float(hA2),
                                                       p1 - __high2float(hA2));
            __nv_bfloat162 lB2 = __floats2bfloat162_rn(p2 - __low2float(hB2),
                                                       p3 - __high2float(hB2));
            ph[nt][0] = *(uint32_t*)&hA2;
            ph[nt][1] = *(uint32_t*)&hB2;
            pl[nt][0] = *(uint32_t*)&lA2;
            pl[nt][1] = *(uint32_t*)&lB2;
        }
        lA = lA * aAl + psA;
        lB = lB * aBl + psB;
#pragma unroll
        for (int nt = 0; nt < 16; nt++) {
            oacc[nt][0] *= aAl;
            oacc[nt][1] *= aAl;
            oacc[nt][2] *= aBl;
            oacc[nt][3] *= aBl;
        }

#pragma unroll
        for (int ks = 0; ks < 4; ks++) {
            uint32_t aph[4] = {ph[2 * ks][0], ph[2 * ks][1],
                               ph[2 * ks + 1][0], ph[2 * ks + 1][1]};
            uint32_t apl[4] = {pl[2 * ks][0], pl[2 * ks][1],
                               pl[2 * ks + 1][0], pl[2 * ks + 1][1]};
#pragma unroll
            for (int np = 0; np < 8; np++) {
                uint32_t vh[4], vl[4];
                uint32_t va = vbase + (ks * 16 * AT_STRIDE) * 2 + np * 32;
                ldsm4t(vh[0], vh[1], vh[2], vh[3], va);
                ldsm4t(vl[0], vl[1], vl[2], vl[3], va + (VL - VH) * 2);
                float* d0 = oacc[2 * np];
                float* d1 = oacc[2 * np + 1];
                MMA_OP(d0, aph, vh[0], vh[1]);
                MMA_OP(d0, aph, vl[0], vl[1]);
                MMA_OP(d0, apl, vh[0], vh[1]);
                MMA_OP(d1, aph, vh[2], vh[3]);
                MMA_OP(d1, aph, vl[2], vl[3]);
                MMA_OP(d1, apl, vh[2], vh[3]);
            }
        }
    }

    // ---- finalize: normalize, write fp16 hi/lo to g_oh/g_ol [B,T,D] ----
    lA += __shfl_xor_sync(0xffffffffu, lA, 1);
    lA += __shfl_xor_sync(0xffffffffu, lA, 2);
    lB += __shfl_xor_sync(0xffffffffu, lB, 1);
    lB += __shfl_xor_sync(0xffffffffu, lB, 2);
    float invA = 1.f / lA, invB = 1.f / lB;

    int rA = qs + wid * 16 + (lane >> 2);
    int c0 = 2 * (lane & 3);
    size_t baseA = ((size_t)(b * T_ + rA)) * D_ + head * HD;
    size_t baseB = baseA + (size_t)8 * D_;
#pragma unroll
    for (int nt = 0; nt < 16; nt++) {
        int cc = nt * 8 + c0;
        float a0 = oacc[nt][0] * invA, a1 = oacc[nt][1] * invA;
        float b0 = oacc[nt][2] * invB, b1 = oacc[nt][3] * invB;
        __half2 hA = __floats2half2_rn(a0, a1);
        __half2 lA2 = __floats2half2_rn(a0 - __low2float(hA), a1 - __high2float(hA));
        __half2 hB = __floats2half2_rn(b0, b1);
        __half2 lB2 = __floats2half2_rn(b0 - __low2float(hB), b1 - __high2float(hB));
        *(__half2*)(g_oh + baseA + cc) = hA;
        *(__half2*)(g_ol + baseA + cc) = lA2;
        *(__half2*)(g_oh + baseB + cc) = hB;
        *(__half2*)(g_ol + baseB + cc) = lB2;
    }
}

// ---------------------------------------------------------------------------
// Launch. Inputs: x, mask, cos, sin, w_attn, w_out. mask is tril -> causal.
// ---------------------------------------------------------------------------
extern "C" void kernel_launch(void* const* d_in, const int* in_sizes, int n_in,
                              void* d_out, int out_size)
{
    const float* x      = (const float*)d_in[0];
    const float* cosT   = (const float*)d_in[2];
    const float* sinT   = (const float*)d_in[3];
    const float* w_attn = (const float*)d_in[4];
    const float* w_out  = (const float*)d_in[5];
    float* out = (float*)d_out;

    cudaFuncSetAttribute(gemm2, cudaFuncAttributeMaxDynamicSharedMemorySize, G_SMEM);
    cudaFuncSetAttribute(attn_mma, cudaFuncAttributeMaxDynamicSharedMemorySize,
                         AT_SMEM_BYTES);

    // Preprocessing: x split + weight transposes (fp16 hi)
    split_act<<<(B_ * T_ * D_ / 4) / 256, 256>>>(x);
    transpose_h<<<dim3(192, 64), dim3(32, 8)>>>(w_attn, D_, 3 * D_, 0);
    transpose_h<<<dim3(64, 64), dim3(32, 8)>>>(w_out, D_, D_, 1);

    // QKV projection (2-MMA fp16) + head split + scale/RoPE -> bf16 hi/lo
    gemm2<<<dim3(96, 32), 256, G_SMEM>>>(cosT, sinT, nullptr, 0);

    // Tensor-core flash attention (3-MMA bf16) -> fp16 hi/lo
    attn_mma<<<dim3(32, NH, B_), 128, AT_SMEM_BYTES>>>();

    // Output projection (2-MMA fp16)
    gemm2<<<dim3(32, 32), 256, G_SMEM>>>(cosT, sinT, out, 1);
}

// round 9
// speedup vs baseline: 5.8483x; 1.2713x over previous
#include <cuda_runtime.h>
#include <cuda_bf16.h>
#include <cuda_fp16.h>
#include <cstdint>

// Problem constants
#define B_   2
#define T_   2048
#define D_   2048
#define NH   16
#define HD   128
#define FR   64
#define KTOT 2048
#define QK_SCALE 0.08838834764831845f   // 1/sqrt(128)

// ---------------------------------------------------------------------------
// Device-global scratch (allocation-free, graph-capture safe)
// ---------------------------------------------------------------------------
__device__ __half g_x_hi[(size_t)B_ * T_ * D_];          // x as fp16 (hi only)
__device__ __half g_oh[(size_t)B_ * T_ * D_];            // attn out split hi/lo
__device__ __half g_ol[(size_t)B_ * T_ * D_];
__device__ __half g_wa_h[(size_t)3 * D_ * D_];           // w_attn^T fp16: [6144][2048]
__device__ __half g_wo_h[(size_t)D_ * D_];               // w_out^T fp16: [2048][2048]
// Q/K/V pre-split bf16 hi/lo, [B,N,T,H]; Q pre-scaled by 1/sqrt(H)
__device__ __nv_bfloat16 g_q_hi[(size_t)B_ * NH * T_ * HD];
__device__ __nv_bfloat16 g_q_lo[(size_t)B_ * NH * T_ * HD];
__device__ __nv_bfloat16 g_k_hi[(size_t)B_ * NH * T_ * HD];
__device__ __nv_bfloat16 g_k_lo[(size_t)B_ * NH * T_ * HD];
__device__ __nv_bfloat16 g_v_hi[(size_t)B_ * NH * T_ * HD];
__device__ __nv_bfloat16 g_v_lo[(size_t)B_ * NH * T_ * HD];

__device__ __forceinline__ uint32_t smem_u32(const void* p) {
    uint32_t a;
    asm("{ .reg .u64 t; cvta.to.shared.u64 t, %1; cvt.u32.u64 %0, t; }"
        : "=r"(a) : "l"(p));
    return a;
}
__device__ __forceinline__ void ldsm4(uint32_t& r0, uint32_t& r1, uint32_t& r2,
                                      uint32_t& r3, uint32_t addr) {
    asm volatile("ldmatrix.sync.aligned.m8n8.x4.shared.b16 {%0,%1,%2,%3}, [%4];"
                 : "=r"(r0), "=r"(r1), "=r"(r2), "=r"(r3) : "r"(addr));
}
__device__ __forceinline__ void ldsm4t(uint32_t& r0, uint32_t& r1, uint32_t& r2,
                                       uint32_t& r3, uint32_t addr) {
    asm volatile("ldmatrix.sync.aligned.m8n8.x4.trans.shared.b16 {%0,%1,%2,%3}, [%4];"
                 : "=r"(r0), "=r"(r1), "=r"(r2), "=r"(r3) : "r"(addr));
}
// bf16 mma (attention)
#define MMA_OP(d, a, b0, b1)                                                   \
    asm volatile("mma.sync.aligned.m16n8k16.row.col.f32.bf16.bf16.f32 "        \
                 "{%0,%1,%2,%3},{%4,%5,%6,%7},{%8,%9},{%0,%1,%2,%3};"          \
                 : "+f"((d)[0]), "+f"((d)[1]), "+f"((d)[2]), "+f"((d)[3])      \
                 : "r"((a)[0]), "r"((a)[1]), "r"((a)[2]), "r"((a)[3]),         \
                   "r"(b0), "r"(b1))
// fp16 mma (projections)
#define MMA_H(d, a, b0, b1)                                                    \
    asm volatile("mma.sync.aligned.m16n8k16.row.col.f32.f16.f16.f32 "          \
                 "{%0,%1,%2,%3},{%4,%5,%6,%7},{%8,%9},{%0,%1,%2,%3};"          \
                 : "+f"((d)[0]), "+f"((d)[1]), "+f"((d)[2]), "+f"((d)[3])      \
                 : "r"((a)[0]), "r"((a)[1]), "r"((a)[2]), "r"((a)[3]),         \
                   "r"(b0), "r"(b1))

__device__ __forceinline__ void cpa16(uint32_t dst, const void* src) {
    asm volatile("cp.async.cg.shared.global [%0], [%1], 16;"
                 :: "r"(dst), "l"(src));
}
#define CP_COMMIT() asm volatile("cp.async.commit_group;" ::: "memory")
#define CP_WAIT0()  asm volatile("cp.async.wait_group 0;" ::: "memory")
#define CP_WAIT2()  asm volatile("cp.async.wait_group 2;" ::: "memory")

// ---------------------------------------------------------------------------
// x -> fp16 (hi only; QKV uses 1-term MMA)
// ---------------------------------------------------------------------------
__global__ __launch_bounds__(256) void split_act(const float* __restrict__ src)
{
    int i = blockIdx.x * 256 + threadIdx.x;          // float4 index
    float4 f = ((const float4*)src)[i];
    __half2 h0 = __floats2half2_rn(f.x, f.y);
    __half2 h1 = __floats2half2_rn(f.z, f.w);
    ((__half2*)g_x_hi)[2 * i]     = h0;
    ((__half2*)g_x_hi)[2 * i + 1] = h1;
}

// ---------------------------------------------------------------------------
// Weight transpose to fp16 (hi only): src fp32 [R][C] -> dst fp16 [C][R]
// ---------------------------------------------------------------------------
__global__ __launch_bounds__(256) void transpose_h(const float* __restrict__ src,
                                                   int R, int C, int which)
{
    __shared__ float tile[32][33];
    __half* dh = which ? g_wo_h : g_wa_h;
    int x = blockIdx.x * 32 + threadIdx.x;
    int y0 = blockIdx.y * 32;
#pragma unroll
    for (int j = 0; j < 32; j += 8)
        tile[threadIdx.y + j][threadIdx.x] = src[(size_t)(y0 + threadIdx.y + j) * C + x];
    __syncthreads();
    int xo = y0 + threadIdx.x;
    int yo = blockIdx.x * 32;
#pragma unroll
    for (int j = 0; j < 32; j += 8)
        dh[(size_t)(yo + threadIdx.y + j) * R + xo] =
            __float2half_rn(tile[threadIdx.x][threadIdx.y + j]);
}

// ---------------------------------------------------------------------------
// fp16 projection GEMM, templated on term count.
// MODE 0 (QKV): C = xhi @ Whi^T              (1 MMA/tile)
//   epilogue: head split + scale(q)/RoPE(k,v) -> bf16 hi/lo Q/K/V.
// MODE 1 (out): C = (oh+ol) @ Whi^T          (2 MMA/tile)
//   epilogue: plain fp32 store.
// CTA tile 128x64, 8 warps (4m x 2n), warp tile 32x32, BK=32, 4-stage cp.async.
// ---------------------------------------------------------------------------
#define GSTRIDE 40
#define GA_ELE (128 * GSTRIDE)              // 5120 halves per A matrix per stage
#define GW_ELE (64 * GSTRIDE)               // 2560 halves for W per stage
#define G_STAGE_ELE (2 * GA_ELE + GW_ELE)   // 12800 halves (Ah, Al, Wh)
#define G_SMEM (4 * G_STAGE_ELE * 2)        // 102400 bytes

template <int MODE>
__global__ __launch_bounds__(256, 2) void gemm2(
    const float* __restrict__ cosT, const float* __restrict__ sinT,
    float* __restrict__ Cout)
{
    extern __shared__ __half smem_h[];
    const int tid = threadIdx.x;
    const int wid = tid >> 5, lane = tid & 31;
    const int warp_m = wid & 3, warp_n = wid >> 2;
    const int m0 = (int)blockIdx.y << 7, n0 = (int)blockIdx.x << 6;
    const uint32_t sb = smem_u32(smem_h);

    const __half* Ah_g = MODE ? g_oh : g_x_hi;
    const __half* Al_g = MODE ? g_ol : g_x_hi;    // unused in MODE 0
    const __half* Wh_g = MODE ? g_wo_h : g_wa_h;

    float acc[2][4][4];
#pragma unroll
    for (int i = 0; i < 2; i++)
#pragma unroll
        for (int j = 0; j < 4; j++)
#pragma unroll
            for (int k = 0; k < 4; k++) acc[i][j][k] = 0.f;

    const uint32_t a_lm = ((warp_m * 32 + (lane & 15)) * GSTRIDE + (lane >> 4) * 8) * 2;
    const uint32_t b_lm = (uint32_t)(2 * GA_ELE +
        (warp_n * 32 + (lane & 7) + ((lane >> 4) << 3)) * GSTRIDE +
        (((lane >> 3) & 1) << 3)) * 2;

    auto LOAD = [&](int stage, int kc) {
        int k0 = kc << 5;
        uint32_t sbs = sb + (uint32_t)stage * G_STAGE_ELE * 2;
#pragma unroll
        for (int i = 0; i < 2; i++) {
            int c = tid + (i << 8);
            int r = c >> 2, col = (c & 3) << 3;
            size_t ga = (size_t)(m0 + r) * KTOT + k0 + col;
            uint32_t so = (uint32_t)(r * GSTRIDE + col) * 2;
            cpa16(sbs + so, Ah_g + ga);
            if (MODE) cpa16(sbs + (uint32_t)GA_ELE * 2 + so, Al_g + ga);
        }
        {
            int r = tid >> 2, col = (tid & 3) << 3;
            size_t gb = (size_t)(n0 + r) * KTOT + k0 + col;
            uint32_t so = (uint32_t)(r * GSTRIDE + col) * 2;
            cpa16(sbs + (uint32_t)2 * GA_ELE * 2 + so, Wh_g + gb);
        }
        CP_COMMIT();
    };

    auto COMPUTE = [&](int st) {
        uint32_t stb = sb + (uint32_t)st * G_STAGE_ELE * 2;
#pragma unroll
        for (int ks = 0; ks < 2; ks++) {
            uint32_t ah[2][4], al[2][4], bh[2][4];
#pragma unroll
            for (int mt = 0; mt < 2; mt++) {
                uint32_t ad = stb + a_lm + (mt * 16 * GSTRIDE + ks * 16) * 2;
                ldsm4(ah[mt][0], ah[mt][1], ah[mt][2], ah[mt][3], ad);
                if (MODE)
                    ldsm4(al[mt][0], al[mt][1], al[mt][2], al[mt][3],
                          ad + (uint32_t)GA_ELE * 2);
            }
#pragma unroll
            for (int np = 0; np < 2; np++)
                ldsm4(bh[np][0], bh[np][1], bh[np][2], bh[np][3],
                      stb + b_lm + (np * 16 * GSTRIDE + ks * 16) * 2);
#pragma unroll
            for (int mt = 0; mt < 2; mt++)
#pragma unroll
                for (int np = 0; np < 2; np++) {
                    float* d0 = acc[mt][np * 2];
                    float* d1 = acc[mt][np * 2 + 1];
                    MMA_H(d0, ah[mt], bh[np][0], bh[np][1]);
                    MMA_H(d1, ah[mt], bh[np][2], bh[np][3]);
                    if (MODE) {
                        MMA_H(d0, al[mt], bh[np][0], bh[np][1]);
                        MMA_H(d1, al[mt], bh[np][2], bh[np][3]);
                    }
                }
        }
    };

    const int NI = KTOT / 32;            // 64
    LOAD(0, 0);
    LOAD(1, 1);
    LOAD(2, 2);
#pragma unroll 1
    for (int it = 0; it < NI; it++) {
        CP_WAIT2();
        __syncthreads();
        if (it + 3 < NI) LOAD((it + 3) & 3, it + 3);
        else CP_COMMIT();                // keep group count uniform
        COMPUTE(it & 3);
    }

    // ---------------- epilogue ----------------
    const int rb = lane >> 2;
    const int cb = (lane & 3) * 2;
    if (MODE == 0) {
        int sec = n0 >> 11;              // 0=q 1=k 2=v
        int head = (n0 >> 7) & 15;
        __nv_bfloat16* dh = (sec == 0) ? g_q_hi : (sec == 1 ? g_k_hi : g_v_hi);
        __nv_bfloat16* dl = (sec == 0) ? g_q_lo : (sec == 1 ? g_k_lo : g_v_lo);
#pragma unroll
        for (int mt = 0; mt < 2; mt++)
#pragma unroll
            for (int hf = 0; hf < 2; hf++) {
                int m = m0 + warp_m * 32 + mt * 16 + hf * 8 + rb;
                int b = m >> 11, t = m & 2047;
                size_t rowbase = ((size_t)(b * NH + head) * T_ + t) * HD;
#pragma unroll
                for (int j = 0; j < 4; j++) {
                    int n = n0 + warp_n * 32 + j * 8 + cb;
                    int hh = n & 127;
                    float v0 = acc[mt][j][hf * 2];
                    float v1 = acc[mt][j][hf * 2 + 1];
                    if (sec) {
                        float cz = cosT[t * FR + (hh >> 1)];
                        float sz = sinT[t * FR + (hh >> 1)];
                        float r0 = v0 * cz - v1 * sz;
                        float r1 = v0 * sz + v1 * cz;
                        v0 = r0; v1 = r1;
                    } else {
                        v0 *= QK_SCALE; v1 *= QK_SCALE;
                    }
                    __nv_bfloat162 h2 = __floats2bfloat162_rn(v0, v1);
                    __nv_bfloat162 l2 = __floats2bfloat162_rn(v0 - __low2float(h2),
                                                              v1 - __high2float(h2));
                    *(__nv_bfloat162*)(dh + rowbase + hh) = h2;
                    *(__nv_bfloat162*)(dl + rowbase + hh) = l2;
                }
            }
    } else {
#pragma unroll
        for (int mt = 0; mt < 2; mt++)
#pragma unroll
            for (int hf = 0; hf < 2; hf++) {
                int m = m0 + warp_m * 32 + mt * 16 + hf * 8 + rb;
#pragma unroll
                for (int j = 0; j < 4; j++) {
                    int n = n0 + warp_n * 32 + j * 8 + cb;
                    *(float2*)&Cout[(size_t)m * D_ + n] =
                        make_float2(acc[mt][j][hf * 2], acc[mt][j][hf * 2 + 1]);
                }
            }
    }
}

// ---------------------------------------------------------------------------
// Tensor-core causal flash attention (split-bf16, 3-MMA; unchanged).
// Epilogue writes fp16 hi/lo for the out-projection.
// ---------------------------------------------------------------------------
#define AT_STRIDE 136
#define AT_TILE   (64 * AT_STRIDE)
#define AT_SMEM_BYTES (6 * AT_TILE * 2)

__global__ __launch_bounds__(128) void attn_mma()
{
    extern __shared__ __nv_bfloat16 sm_at[];
    const int tid = threadIdx.x, wid = tid >> 5, lane = tid & 31;
    const int qt = 31 - (int)blockIdx.x;
    const int qs = qt << 6;
    const int head = blockIdx.y, b = blockIdx.z;
    const size_t hbase = (size_t)(b * NH + head) * T_ * HD;
    const uint32_t sb = smem_u32(sm_at);

    const uint32_t QH = 0, QL = AT_TILE, KH = 2 * AT_TILE, KL = 3 * AT_TILE,
                   VH = 4 * AT_TILE, VL = 5 * AT_TILE;

#pragma unroll
    for (int i = 0; i < 8; i++) {
        int c = tid + i * 128;
        int r = c >> 4, col = (c & 15) << 3;
        size_t g = hbase + (size_t)(qs + r) * HD + col;
        uint32_t so = (uint32_t)(r * AT_STRIDE + col) * 2;
        cpa16(sb + QH * 2 + so, g_q_hi + g);
        cpa16(sb + QL * 2 + so, g_q_lo + g);
    }

    float oacc[16][4];
#pragma unroll
    for (int i = 0; i < 16; i++)
#pragma unroll
        for (int j = 0; j < 4; j++) oacc[i][j] = 0.f;
    float mA = -1e30f, mB = -1e30f, lA = 0.f, lB = 0.f;

    const uint32_t qbase = sb + QH * 2 +
        ((wid * 16 + (lane & 15)) * AT_STRIDE + ((lane >> 4) << 3)) * 2;
    const uint32_t kbase = sb + KH * 2 +
        (((lane & 7) + ((lane >> 4) << 3)) * AT_STRIDE + (((lane >> 3) & 1) << 3)) * 2;
    const uint32_t vbase = sb + VH * 2 +
        ((lane & 15) * AT_STRIDE + ((lane >> 4) << 3)) * 2;

#pragma unroll 1
    for (int jt = 0; jt <= qt; jt++) {
        const int j0 = jt << 6;
        if (jt) __syncthreads();
#pragma unroll
        for (int i = 0; i < 8; i++) {
            int c = tid + i * 128;
            int r = c >> 4, col = (c & 15) << 3;
            size_t g = hbase + (size_t)(j0 + r) * HD + col;
            uint32_t so = (uint32_t)(r * AT_STRIDE + col) * 2;
            cpa16(sb + KH * 2 + so, g_k_hi + g);
            cpa16(sb + KL * 2 + so, g_k_lo + g);
            cpa16(sb + VH * 2 + so, g_v_hi + g);
            cpa16(sb + VL * 2 + so, g_v_lo + g);
        }
        CP_COMMIT();
        CP_WAIT0();
        __syncthreads();

        float sacc[8][4];
#pragma unroll
        for (int i = 0; i < 8; i++)
#pragma unroll
            for (int j = 0; j < 4; j++) sacc[i][j] = 0.f;

#pragma unroll
        for (int ks = 0; ks < 8; ks++) {
            uint32_t qh[4], ql[4];
            uint32_t qa = qbase + ks * 32;
            ldsm4(qh[0], qh[1], qh[2], qh[3], qa);
            ldsm4(ql[0], ql[1], ql[2], ql[3], qa + (QL - QH) * 2);
#pragma unroll
            for (int np = 0; np < 4; np++) {
                uint32_t kh[4], kl[4];
                uint32_t ka = kbase + (np * 16 * AT_STRIDE) * 2 + ks * 32;
                ldsm4(kh[0], kh[1], kh[2], kh[3], ka);
                ldsm4(kl[0], kl[1], kl[2], kl[3], ka + (KL - KH) * 2);
                float* d0 = sacc[2 * np];
                float* d1 = sacc[2 * np + 1];
                MMA_OP(d0, qh, kh[0], kh[1]);
                MMA_OP(d0, qh, kl[0], kl[1]);
                MMA_OP(d0, ql, kh[0], kh[1]);
                MMA_OP(d1, qh, kh[2], kh[3]);
                MMA_OP(d1, qh, kl[2], kl[3]);
                MMA_OP(d1, ql, kh[2], kh[3]);
            }
        }

        if (jt == qt) {
            int rA = wid * 16 + (lane >> 2);
            int c0 = 2 * (lane & 3);
#pragma unroll
            for (int nt = 0; nt < 8; nt++) {
                int cc = nt * 8 + c0;
                if (cc > rA)         sacc[nt][0] = -1e30f;
                if (cc + 1 > rA)     sacc[nt][1] = -1e30f;
                if (cc > rA + 8)     sacc[nt][2] = -1e30f;
                if (cc + 1 > rA + 8) sacc[nt][3] = -1e30f;
            }
        }

        float tmA = -1e30f, tmB = -1e30f;
#pragma unroll
        for (int nt = 0; nt < 8; nt++) {
            tmA = fmaxf(tmA, fmaxf(sacc[nt][0], sacc[nt][1]));
            tmB = fmaxf(tmB, fmaxf(sacc[nt][2], sacc[nt][3]));
        }
        tmA = fmaxf(tmA, __shfl_xor_sync(0xffffffffu, tmA, 1));
        tmA = fmaxf(tmA, __shfl_xor_sync(0xffffffffu, tmA, 2));
        tmB = fmaxf(tmB, __shfl_xor_sync(0xffffffffu, tmB, 1));
        tmB = fmaxf(tmB, __shfl_xor_sync(0xffffffffu, tmB, 2));
        float mnA = fmaxf(mA, tmA), mnB = fmaxf(mB, tmB);
        float aAl = __expf(mA - mnA), aBl = __expf(mB - mnB);
        mA = mnA; mB = mnB;

        float psA = 0.f, psB = 0.f;
        uint32_t ph[8][2], pl[8][2];
#pragma unroll
        for (int nt = 0; nt < 8; nt++) {
            float p0 = __expf(sacc[nt][0] - mA);
            float p1 = __expf(sacc[nt][1] - mA);
            float p2 = __expf(sacc[nt][2] - mB);
            float p3 = __expf(sacc[nt][3] - mB);
            psA += p0 + p1;
            psB += p2 + p3;
            __nv_bfloat162 hA2 = __floats2bfloat162_rn(p0, p1);
            __nv_bfloat162 hB2 = __floats2bfloat162_rn(p2, p3);
            __nv_bfloat162 lA2 = __floats2bfloat162_rn(p0 - __low2float(hA2),
                                                       p1 - __high2float(hA2));
            __nv_bfloat162 lB2 = __floats2bfloat162_rn(p2 - __low2float(hB2),
                                                       p3 - __high2float(hB2));
            ph[nt][0] = *(uint32_t*)&hA2;
            ph[nt][1] = *(uint32_t*)&hB2;
            pl[nt][0] = *(uint32_t*)&lA2;
            pl[nt][1] = *(uint32_t*)&lB2;
        }
        lA = lA * aAl + psA;
        lB = lB * aBl + psB;
#pragma unroll
        for (int nt = 0; nt < 16; nt++) {
            oacc[nt][0] *= aAl;
            oacc[nt][1] *= aAl;
            oacc[nt][2] *= aBl;
            oacc[nt][3] *= aBl;
        }

#pragma unroll
        for (int ks = 0; ks < 4; ks++) {
            uint32_t aph[4] = {ph[2 * ks][0], ph[2 * ks][1],
                               ph[2 * ks + 1][0], ph[2 * ks + 1][1]};
            uint32_t apl[4] = {pl[2 * ks][0], pl[2 * ks][1],
                               pl[2 * ks + 1][0], pl[2 * ks + 1][1]};
#pragma unroll
            for (int np = 0; np < 8; np++) {
                uint32_t vh[4], vl[4];
                uint32_t va = vbase + (ks * 16 * AT_STRIDE) * 2 + np * 32;
                ldsm4t(vh[0], vh[1], vh[2], vh[3], va);
                ldsm4t(vl[0], vl[1], vl[2], vl[3], va + (VL - VH) * 2);
                float* d0 = oacc[2 * np];
                float* d1 = oacc[2 * np + 1];
                MMA_OP(d0, aph, vh[0], vh[1]);
                MMA_OP(d0, aph, vl[0], vl[1]);
                MMA_OP(d0, apl, vh[0], vh[1]);
                MMA_OP(d1, aph, vh[2], vh[3]);
                MMA_OP(d1, aph, vl[2], vl[3]);
                MMA_OP(d1, apl, vh[2], vh[3]);
            }
        }
    }

    // ---- finalize: normalize, write fp16 hi/lo to g_oh/g_ol [B,T,D] ----
    lA += __shfl_xor_sync(0xffffffffu, lA, 1);
    lA += __shfl_xor_sync(0xffffffffu, lA, 2);
    lB += __shfl_xor_sync(0xffffffffu, lB, 1);
    lB += __shfl_xor_sync(0xffffffffu, lB, 2);
    float invA = 1.f / lA, invB = 1.f / lB;

    int rA = qs + wid * 16 + (lane >> 2);
    int c0 = 2 * (lane & 3);
    size_t baseA = ((size_t)(b * T_ + rA)) * D_ + head * HD;
    size_t baseB = baseA + (size_t)8 * D_;
#pragma unroll
    for (int nt = 0; nt < 16; nt++) {
        int cc = nt * 8 + c0;
        float a0 = oacc[nt][0] * invA, a1 = oacc[nt][1] * invA;
        float b0 = oacc[nt][2] * invB, b1 = oacc[nt][3] * invB;
        __half2 hA = __floats2half2_rn(a0, a1);
        __half2 lA2 = __floats2half2_rn(a0 - __low2float(hA), a1 - __high2float(hA));
        __half2 hB = __floats2half2_rn(b0, b1);
        __half2 lB2 = __floats2half2_rn(b0 - __low2float(hB), b1 - __high2float(hB));
        *(__half2*)(g_oh + baseA + cc) = hA;
        *(__half2*)(g_ol + baseA + cc) = lA2;
        *(__half2*)(g_oh + baseB + cc) = hB;
        *(__half2*)(g_ol + baseB + cc) = lB2;
    }
}

// ---------------------------------------------------------------------------
// Launch. Inputs: x, mask, cos, sin, w_attn, w_out. mask is tril -> causal.
// ---------------------------------------------------------------------------
extern "C" void kernel_launch(void* const* d_in, const int* in_sizes, int n_in,
                              void* d_out, int out_size)
{
    const float* x      = (const float*)d_in[0];
    const float* cosT   = (const float*)d_in[2];
    const float* sinT   = (const float*)d_in[3];
    const float* w_attn = (const float*)d_in[4];
    const float* w_out  = (const float*)d_in[5];
    float* out = (float*)d_out;

    cudaFuncSetAttribute(gemm2<0>, cudaFuncAttributeMaxDynamicSharedMemorySize, G_SMEM);
    cudaFuncSetAttribute(gemm2<1>, cudaFuncAttributeMaxDynamicSharedMemorySize, G_SMEM);
    cudaFuncSetAttribute(attn_mma, cudaFuncAttributeMaxDynamicSharedMemorySize,
                         AT_SMEM_BYTES);

    // Preprocessing: x -> fp16 + weight transposes (fp16 hi)
    split_act<<<(B_ * T_ * D_ / 4) / 256, 256>>>(x);
    transpose_h<<<dim3(192, 64), dim3(32, 8)>>>(w_attn, D_, 3 * D_, 0);
    transpose_h<<<dim3(64, 64), dim3(32, 8)>>>(w_out, D_, D_, 1);

    // QKV projection (1-MMA fp16) + head split + scale/RoPE -> bf16 hi/lo
    gemm2<0><<<dim3(96, 32), 256, G_SMEM>>>(cosT, sinT, nullptr);

    // Tensor-core flash attention (3-MMA bf16) -> fp16 hi/lo
    attn_mma<<<dim3(32, NH, B_), 128, AT_SMEM_BYTES>>>();

    // Output projection (2-MMA fp16)
    gemm2<1><<<dim3(32, 32), 256, G_SMEM>>>(cosT, sinT, out);
}

// round 10
// speedup vs baseline: 6.6153x; 1.1312x over previous
#include <cuda_runtime.h>
#include <cuda_bf16.h>
#include <cuda_fp16.h>
#include <cstdint>

// Problem constants
#define B_   2
#define T_   2048
#define D_   2048
#define NH   16
#define HD   128
#define FR   64
#define KTOT 2048
#define QK_SCALE 0.08838834764831845f   // 1/sqrt(128)

// ---------------------------------------------------------------------------
// Device-global scratch (allocation-free, graph-capture safe)
// ---------------------------------------------------------------------------
__device__ __half g_x_hi[(size_t)B_ * T_ * D_];          // x as fp16
__device__ __half g_oh[(size_t)B_ * T_ * D_];            // attn out split hi/lo
__device__ __half g_ol[(size_t)B_ * T_ * D_];
__device__ __half g_wa_h[(size_t)3 * D_ * D_];           // w_attn^T fp16: [6144][2048]
__device__ __half g_wo_h[(size_t)D_ * D_];               // w_out^T fp16: [2048][2048]
// Q split fp16 hi/lo (unscaled), K/V single fp16 (RoPE applied), [B,N,T,H]
__device__ __half g_qh[(size_t)B_ * NH * T_ * HD];
__device__ __half g_ql[(size_t)B_ * NH * T_ * HD];
__device__ __half g_kh[(size_t)B_ * NH * T_ * HD];
__device__ __half g_vh[(size_t)B_ * NH * T_ * HD];

__device__ __forceinline__ uint32_t smem_u32(const void* p) {
    uint32_t a;
    asm("{ .reg .u64 t; cvta.to.shared.u64 t, %1; cvt.u32.u64 %0, t; }"
        : "=r"(a) : "l"(p));
    return a;
}
__device__ __forceinline__ void ldsm4(uint32_t& r0, uint32_t& r1, uint32_t& r2,
                                      uint32_t& r3, uint32_t addr) {
    asm volatile("ldmatrix.sync.aligned.m8n8.x4.shared.b16 {%0,%1,%2,%3}, [%4];"
                 : "=r"(r0), "=r"(r1), "=r"(r2), "=r"(r3) : "r"(addr));
}
__device__ __forceinline__ void ldsm4t(uint32_t& r0, uint32_t& r1, uint32_t& r2,
                                       uint32_t& r3, uint32_t addr) {
    asm volatile("ldmatrix.sync.aligned.m8n8.x4.trans.shared.b16 {%0,%1,%2,%3}, [%4];"
                 : "=r"(r0), "=r"(r1), "=r"(r2), "=r"(r3) : "r"(addr));
}
// fp16 mma
#define MMA_H(d, a, b0, b1)                                                    \
    asm volatile("mma.sync.aligned.m16n8k16.row.col.f32.f16.f16.f32 "          \
                 "{%0,%1,%2,%3},{%4,%5,%6,%7},{%8,%9},{%0,%1,%2,%3};"          \
                 : "+f"((d)[0]), "+f"((d)[1]), "+f"((d)[2]), "+f"((d)[3])      \
                 : "r"((a)[0]), "r"((a)[1]), "r"((a)[2]), "r"((a)[3]),         \
                   "r"(b0), "r"(b1))

__device__ __forceinline__ void cpa16(uint32_t dst, const void* src) {
    asm volatile("cp.async.cg.shared.global [%0], [%1], 16;"
                 :: "r"(dst), "l"(src));
}
#define CP_COMMIT() asm volatile("cp.async.commit_group;" ::: "memory")
#define CP_WAIT0()  asm volatile("cp.async.wait_group 0;" ::: "memory")
#define CP_WAIT2()  asm volatile("cp.async.wait_group 2;" ::: "memory")

// ---------------------------------------------------------------------------
// x -> fp16
// ---------------------------------------------------------------------------
__global__ __launch_bounds__(256) void split_act(const float* __restrict__ src)
{
    int i = blockIdx.x * 256 + threadIdx.x;          // float4 index
    float4 f = ((const float4*)src)[i];
    ((__half2*)g_x_hi)[2 * i]     = __floats2half2_rn(f.x, f.y);
    ((__half2*)g_x_hi)[2 * i + 1] = __floats2half2_rn(f.z, f.w);
}

// ---------------------------------------------------------------------------
// Weight transpose to fp16: src fp32 [R][C] -> dst fp16 [C][R]
// ---------------------------------------------------------------------------
__global__ __launch_bounds__(256) void transpose_h(const float* __restrict__ src,
                                                   int R, int C, int which)
{
    __shared__ float tile[32][33];
    __half* dh = which ? g_wo_h : g_wa_h;
    int x = blockIdx.x * 32 + threadIdx.x;
    int y0 = blockIdx.y * 32;
#pragma unroll
    for (int j = 0; j < 32; j += 8)
        tile[threadIdx.y + j][threadIdx.x] = src[(size_t)(y0 + threadIdx.y + j) * C + x];
    __syncthreads();
    int xo = y0 + threadIdx.x;
    int yo = blockIdx.x * 32;
#pragma unroll
    for (int j = 0; j < 32; j += 8)
        dh[(size_t)(yo + threadIdx.y + j) * R + xo] =
            __float2half_rn(tile[threadIdx.x][threadIdx.y + j]);
}

// ---------------------------------------------------------------------------
// QKV projection: C[128x64] = xhi @ Whi^T   (1 MMA term, BK=64)
// 8 warps (4m x 2n), warp tile 32x32, 4-stage cp.async, 108KB smem -> 2 CTA/SM.
// Epilogue: head split; q -> fp16 hi/lo (UNscaled); k,v -> RoPE, single fp16.
// ---------------------------------------------------------------------------
#define QSTRIDE 72
#define QA_ELE (128 * QSTRIDE)              // 9216 halves
#define QW_ELE (64 * QSTRIDE)               // 4608 halves
#define Q_STAGE_ELE (QA_ELE + QW_ELE)       // 13824 halves
#define Q_SMEM (4 * Q_STAGE_ELE * 2)        // 110592 bytes

__global__ __launch_bounds__(256, 2) void gemm_qkv(
    const float* __restrict__ cosT, const float* __restrict__ sinT)
{
    extern __shared__ __half smem_h[];
    const int tid = threadIdx.x;
    const int wid = tid >> 5, lane = tid & 31;
    const int warp_m = wid & 3, warp_n = wid >> 2;
    const int m0 = (int)blockIdx.y << 7, n0 = (int)blockIdx.x << 6;
    const uint32_t sb = smem_u32(smem_h);

    float acc[2][4][4];
#pragma unroll
    for (int i = 0; i < 2; i++)
#pragma unroll
        for (int j = 0; j < 4; j++)
#pragma unroll
            for (int k = 0; k < 4; k++) acc[i][j][k] = 0.f;

    const uint32_t a_lm = ((warp_m * 32 + (lane & 15)) * QSTRIDE + (lane >> 4) * 8) * 2;
    const uint32_t b_lm = (uint32_t)(QA_ELE +
        (warp_n * 32 + (lane & 7) + ((lane >> 4) << 3)) * QSTRIDE +
        (((lane >> 3) & 1) << 3)) * 2;

    auto LOAD = [&](int stage, int kc) {
        int k0 = kc << 6;
        uint32_t sbs = sb + (uint32_t)stage * Q_STAGE_ELE * 2;
#pragma unroll
        for (int i = 0; i < 4; i++) {                // A: 1024 chunks
            int c = tid + (i << 8);
            int r = c >> 3, col = (c & 7) << 3;
            cpa16(sbs + (uint32_t)(r * QSTRIDE + col) * 2,
                  g_x_hi + (size_t)(m0 + r) * KTOT + k0 + col);
        }
#pragma unroll
        for (int i = 0; i < 2; i++) {                // W: 512 chunks
            int c = tid + (i << 8);
            int r = c >> 3, col = (c & 7) << 3;
            cpa16(sbs + (uint32_t)QA_ELE * 2 + (uint32_t)(r * QSTRIDE + col) * 2,
                  g_wa_h + (size_t)(n0 + r) * KTOT + k0 + col);
        }
        CP_COMMIT();
    };

    auto COMPUTE = [&](int st) {
        uint32_t stb = sb + (uint32_t)st * Q_STAGE_ELE * 2;
#pragma unroll
        for (int ks = 0; ks < 4; ks++) {
            uint32_t ah[2][4], bh[2][4];
#pragma unroll
            for (int mt = 0; mt < 2; mt++)
                ldsm4(ah[mt][0], ah[mt][1], ah[mt][2], ah[mt][3],
                      stb + a_lm + (mt * 16 * QSTRIDE + ks * 16) * 2);
#pragma unroll
            for (int np = 0; np < 2; np++)
                ldsm4(bh[np][0], bh[np][1], bh[np][2], bh[np][3],
                      stb + b_lm + (np * 16 * QSTRIDE + ks * 16) * 2);
#pragma unroll
            for (int mt = 0; mt < 2; mt++)
#pragma unroll
                for (int np = 0; np < 2; np++) {
                    MMA_H(acc[mt][np * 2],     ah[mt], bh[np][0], bh[np][1]);
                    MMA_H(acc[mt][np * 2 + 1], ah[mt], bh[np][2], bh[np][3]);
                }
        }
    };

    const int NI = KTOT / 64;            // 32
    LOAD(0, 0);
    LOAD(1, 1);
    LOAD(2, 2);
#pragma unroll 1
    for (int it = 0; it < NI; it++) {
        CP_WAIT2();
        __syncthreads();
        if (it + 3 < NI) LOAD((it + 3) & 3, it + 3);
        else CP_COMMIT();                // keep group count uniform
        COMPUTE(it & 3);
    }

    // ---------------- epilogue ----------------
    const int rb = lane >> 2;
    const int cb = (lane & 3) * 2;
    int sec = n0 >> 11;                  // 0=q 1=k 2=v
    int head = (n0 >> 7) & 15;
#pragma unroll
    for (int mt = 0; mt < 2; mt++)
#pragma unroll
        for (int hf = 0; hf < 2; hf++) {
            int m = m0 + warp_m * 32 + mt * 16 + hf * 8 + rb;
            int b = m >> 11, t = m & 2047;
            size_t rowbase = ((size_t)(b * NH + head) * T_ + t) * HD;
#pragma unroll
            for (int j = 0; j < 4; j++) {
                int n = n0 + warp_n * 32 + j * 8 + cb;
                int hh = n & 127;
                float v0 = acc[mt][j][hf * 2];
                float v1 = acc[mt][j][hf * 2 + 1];
                if (sec == 0) {
                    __half2 h2 = __floats2half2_rn(v0, v1);
                    __half2 l2 = __floats2half2_rn(v0 - __low2float(h2),
                                                   v1 - __high2float(h2));
                    *(__half2*)(g_qh + rowbase + hh) = h2;
                    *(__half2*)(g_ql + rowbase + hh) = l2;
                } else {
                    float cz = cosT[t * FR + (hh >> 1)];
                    float sz = sinT[t * FR + (hh >> 1)];
                    float r0 = v0 * cz - v1 * sz;
                    float r1 = v0 * sz + v1 * cz;
                    __half* dst = (sec == 1) ? g_kh : g_vh;
                    *(__half2*)(dst + rowbase + hh) = __floats2half2_rn(r0, r1);
                }
            }
        }
}

// ---------------------------------------------------------------------------
// Output projection: out[128x64] = (oh+ol) @ Wout_hi^T  (2 MMA terms, BK=32)
// ---------------------------------------------------------------------------
#define GSTRIDE 40
#define GA_ELE (128 * GSTRIDE)
#define GW_ELE (64 * GSTRIDE)
#define G_STAGE_ELE (2 * GA_ELE + GW_ELE)
#define G_SMEM (4 * G_STAGE_ELE * 2)        // 102400 bytes

__global__ __launch_bounds__(256, 2) void out_gemm(float* __restrict__ Cout)
{
    extern __shared__ __half smem_h[];
    const int tid = threadIdx.x;
    const int wid = tid >> 5, lane = tid & 31;
    const int warp_m = wid & 3, warp_n = wid >> 2;
    const int m0 = (int)blockIdx.y << 7, n0 = (int)blockIdx.x << 6;
    const uint32_t sb = smem_u32(smem_h);

    float acc[2][4][4];
#pragma unroll
    for (int i = 0; i < 2; i++)
#pragma unroll
        for (int j = 0; j < 4; j++)
#pragma unroll
            for (int k = 0; k < 4; k++) acc[i][j][k] = 0.f;

    const uint32_t a_lm = ((warp_m * 32 + (lane & 15)) * GSTRIDE + (lane >> 4) * 8) * 2;
    const uint32_t b_lm = (uint32_t)(2 * GA_ELE +
        (warp_n * 32 + (lane & 7) + ((lane >> 4) << 3)) * GSTRIDE +
        (((lane >> 3) & 1) << 3)) * 2;

    auto LOAD = [&](int stage, int kc) {
        int k0 = kc << 5;
        uint32_t sbs = sb + (uint32_t)stage * G_STAGE_ELE * 2;
#pragma unroll
        for (int i = 0; i < 2; i++) {
            int c = tid + (i << 8);
            int r = c >> 2, col = (c & 3) << 3;
            size_t ga = (size_t)(m0 + r) * KTOT + k0 + col;
            uint32_t so = (uint32_t)(r * GSTRIDE + col) * 2;
            cpa16(sbs + so, g_oh + ga);
            cpa16(sbs + (uint32_t)GA_ELE * 2 + so, g_ol + ga);
        }
        {
            int r = tid >> 2, col = (tid & 3) << 3;
            cpa16(sbs + (uint32_t)2 * GA_ELE * 2 + (uint32_t)(r * GSTRIDE + col) * 2,
                  g_wo_h + (size_t)(n0 + r) * KTOT + k0 + col);
        }
        CP_COMMIT();
    };

    auto COMPUTE = [&](int st) {
        uint32_t stb = sb + (uint32_t)st * G_STAGE_ELE * 2;
#pragma unroll
        for (int ks = 0; ks < 2; ks++) {
            uint32_t ah[2][4], al[2][4], bh[2][4];
#pragma unroll
            for (int mt = 0; mt < 2; mt++) {
                uint32_t ad = stb + a_lm + (mt * 16 * GSTRIDE + ks * 16) * 2;
                ldsm4(ah[mt][0], ah[mt][1], ah[mt][2], ah[mt][3], ad);
                ldsm4(al[mt][0], al[mt][1], al[mt][2], al[mt][3],
                      ad + (uint32_t)GA_ELE * 2);
            }
#pragma unroll
            for (int np = 0; np < 2; np++)
                ldsm4(bh[np][0], bh[np][1], bh[np][2], bh[np][3],
                      stb + b_lm + (np * 16 * GSTRIDE + ks * 16) * 2);
#pragma unroll
            for (int mt = 0; mt < 2; mt++)
#pragma unroll
                for (int np = 0; np < 2; np++) {
                    float* d0 = acc[mt][np * 2];
                    float* d1 = acc[mt][np * 2 + 1];
                    MMA_H(d0, ah[mt], bh[np][0], bh[np][1]);
                    MMA_H(d1, ah[mt], bh[np][2], bh[np][3]);
                    MMA_H(d0, al[mt], bh[np][0], bh[np][1]);
                    MMA_H(d1, al[mt], bh[np][2], bh[np][3]);
                }
        }
    };

    const int NI = KTOT / 32;            // 64
    LOAD(0, 0);
    LOAD(1, 1);
    LOAD(2, 2);
#pragma unroll 1
    for (int it = 0; it < NI; it++) {
        CP_WAIT2();
        __syncthreads();
        if (it + 3 < NI) LOAD((it + 3) & 3, it + 3);
        else CP_COMMIT();
        COMPUTE(it & 3);
    }

    const int rb = lane >> 2;
    const int cb = (lane & 3) * 2;
#pragma unroll
    for (int mt = 0; mt < 2; mt++)
#pragma unroll
        for (int hf = 0; hf < 2; hf++) {
            int m = m0 + warp_m * 32 + mt * 16 + hf * 8 + rb;
#pragma unroll
            for (int j = 0; j < 4; j++) {
                int n = n0 + warp_n * 32 + j * 8 + cb;
                *(float2*)&Cout[(size_t)m * D_ + n] =
                    make_float2(acc[mt][j][hf * 2], acc[mt][j][hf * 2 + 1]);
            }
        }
}

// ---------------------------------------------------------------------------
// fp16 tensor-core causal flash attention.
// QK: S = (qh+ql) . kh   (2 MMA, K single fp16); scores scaled by 1/sqrt(H).
// PV: O = (ph+pl) . vh   (2 MMA, P register-split fp16, V single fp16).
// SMEM: Qh Ql Kh Vh, each [64][136] fp16 = 69632 B -> 2+ CTAs/SM.
// ---------------------------------------------------------------------------
#define AT_STRIDE 136
#define AT_TILE   (64 * AT_STRIDE)
#define AT_SMEM_BYTES (4 * AT_TILE * 2)

__global__ __launch_bounds__(128) void attn_mma()
{
    extern __shared__ __half sm_at[];
    const int tid = threadIdx.x, wid = tid >> 5, lane = tid & 31;
    const int qt = 31 - (int)blockIdx.x;
    const int qs = qt << 6;
    const int head = blockIdx.y, b = blockIdx.z;
    const size_t hbase = (size_t)(b * NH + head) * T_ * HD;
    const uint32_t sb = smem_u32(sm_at);

    const uint32_t QH = 0, QL = AT_TILE, KH = 2 * AT_TILE, VH = 3 * AT_TILE;

    // preload Q hi/lo: 1024 16B-chunks per matrix
#pragma unroll
    for (int i = 0; i < 8; i++) {
        int c = tid + i * 128;
        int r = c >> 4, col = (c & 15) << 3;
        size_t g = hbase + (size_t)(qs + r) * HD + col;
        uint32_t so = (uint32_t)(r * AT_STRIDE + col) * 2;
        cpa16(sb + QH * 2 + so, g_qh + g);
        cpa16(sb + QL * 2 + so, g_ql + g);
    }

    float oacc[16][4];
#pragma unroll
    for (int i = 0; i < 16; i++)
#pragma unroll
        for (int j = 0; j < 4; j++) oacc[i][j] = 0.f;
    float mA = -1e30f, mB = -1e30f, lA = 0.f, lB = 0.f;

    const uint32_t qbase = sb + QH * 2 +
        ((wid * 16 + (lane & 15)) * AT_STRIDE + ((lane >> 4) << 3)) * 2;
    const uint32_t kbase = sb + KH * 2 +
        (((lane & 7) + ((lane >> 4) << 3)) * AT_STRIDE + (((lane >> 3) & 1) << 3)) * 2;
    const uint32_t vbase = sb + VH * 2 +
        ((lane & 15) * AT_STRIDE + ((lane >> 4) << 3)) * 2;

#pragma unroll 1
    for (int jt = 0; jt <= qt; jt++) {
        const int j0 = jt << 6;
        if (jt) __syncthreads();
#pragma unroll
        for (int i = 0; i < 8; i++) {
            int c = tid + i * 128;
            int r = c >> 4, col = (c & 15) << 3;
            size_t g = hbase + (size_t)(j0 + r) * HD + col;
            uint32_t so = (uint32_t)(r * AT_STRIDE + col) * 2;
            cpa16(sb + KH * 2 + so, g_kh + g);
            cpa16(sb + VH * 2 + so, g_vh + g);
        }
        CP_COMMIT();
        CP_WAIT0();
        __syncthreads();

        // ---- S = Q K^T (2-term fp16) ----
        float sacc[8][4];
#pragma unroll
        for (int i = 0; i < 8; i++)
#pragma unroll
            for (int j = 0; j < 4; j++) sacc[i][j] = 0.f;

#pragma unroll
        for (int ks = 0; ks < 8; ks++) {
            uint32_t qh[4], ql[4];
            uint32_t qa = qbase + ks * 32;
            ldsm4(qh[0], qh[1], qh[2], qh[3], qa);
            ldsm4(ql[0], ql[1], ql[2], ql[3], qa + (QL - QH) * 2);
#pragma unroll
            for (int np = 0; np < 4; np++) {
                uint32_t kh[4];
                ldsm4(kh[0], kh[1], kh[2], kh[3],
                      kbase + (np * 16 * AT_STRIDE) * 2 + ks * 32);
                float* d0 = sacc[2 * np];
                float* d1 = sacc[2 * np + 1];
                MMA_H(d0, qh, kh[0], kh[1]);
                MMA_H(d0, ql, kh[0], kh[1]);
                MMA_H(d1, qh, kh[2], kh[3]);
                MMA_H(d1, ql, kh[2], kh[3]);
            }
        }

        // ---- scale + causal mask ----
#pragma unroll
        for (int nt = 0; nt < 8; nt++)
#pragma unroll
            for (int j = 0; j < 4; j++) sacc[nt][j] *= QK_SCALE;
        if (jt == qt) {
            int rA = wid * 16 + (lane >> 2);
            int c0 = 2 * (lane & 3);
#pragma unroll
            for (int nt = 0; nt < 8; nt++) {
                int cc = nt * 8 + c0;
                if (cc > rA)         sacc[nt][0] = -1e30f;
                if (cc + 1 > rA)     sacc[nt][1] = -1e30f;
                if (cc > rA + 8)     sacc[nt][2] = -1e30f;
                if (cc + 1 > rA + 8) sacc[nt][3] = -1e30f;
            }
        }

        // ---- online softmax ----
        float tmA = -1e30f, tmB = -1e30f;
#pragma unroll
        for (int nt = 0; nt < 8; nt++) {
            tmA = fmaxf(tmA, fmaxf(sacc[nt][0], sacc[nt][1]));
            tmB = fmaxf(tmB, fmaxf(sacc[nt][2], sacc[nt][3]));
        }
        tmA = fmaxf(tmA, __shfl_xor_sync(0xffffffffu, tmA, 1));
        tmA = fmaxf(tmA, __shfl_xor_sync(0xffffffffu, tmA, 2));
        tmB = fmaxf(tmB, __shfl_xor_sync(0xffffffffu, tmB, 1));
        tmB = fmaxf(tmB, __shfl_xor_sync(0xffffffffu, tmB, 2));
        float mnA = fmaxf(mA, tmA), mnB = fmaxf(mB, tmB);
        float aAl = __expf(mA - mnA), aBl = __expf(mB - mnB);
        mA = mnA; mB = mnB;

        float psA = 0.f, psB = 0.f;
        uint32_t ph[8][2], pl[8][2];
#pragma unroll
        for (int nt = 0; nt < 8; nt++) {
            float p0 = __expf(sacc[nt][0] - mA);
            float p1 = __expf(sacc[nt][1] - mA);
            float p2 = __expf(sacc[nt][2] - mB);
            float p3 = __expf(sacc[nt][3] - mB);
            psA += p0 + p1;
            psB += p2 + p3;
            __half2 hA2 = __floats2half2_rn(p0, p1);
            __half2 hB2 = __floats2half2_rn(p2, p3);
            __half2 lA2 = __floats2half2_rn(p0 - __low2float(hA2),
                                            p1 - __high2float(hA2));
            __half2 lB2 = __floats2half2_rn(p2 - __low2float(hB2),
                                            p3 - __high2float(hB2));
            ph[nt][0] = *(uint32_t*)&hA2;
            ph[nt][1] = *(uint32_t*)&hB2;
            pl[nt][0] = *(uint32_t*)&lA2;
            pl[nt][1] = *(uint32_t*)&lB2;
        }
        lA = lA * aAl + psA;
        lB = lB * aBl + psB;
#pragma unroll
        for (int nt = 0; nt < 16; nt++) {
            oacc[nt][0] *= aAl;
            oacc[nt][1] *= aAl;
            oacc[nt][2] *= aBl;
            oacc[nt][3] *= aBl;
        }

        // ---- O += P V (2-term fp16), V b-frags via ldmatrix.trans ----
#pragma unroll
        for (int ks = 0; ks < 4; ks++) {
            uint32_t aph[4] = {ph[2 * ks][0], ph[2 * ks][1],
                               ph[2 * ks + 1][0], ph[2 * ks + 1][1]};
            uint32_t apl[4] = {pl[2 * ks][0], pl[2 * ks][1],
                               pl[2 * ks + 1][0], pl[2 * ks + 1][1]};
#pragma unroll
            for (int np = 0; np < 8; np++) {
                uint32_t vh[4];
                ldsm4t(vh[0], vh[1], vh[2], vh[3],
                       vbase + (ks * 16 * AT_STRIDE) * 2 + np * 32);
                float* d0 = oacc[2 * np];
                float* d1 = oacc[2 * np + 1];
                MMA_H(d0, aph, vh[0], vh[1]);
                MMA_H(d0, apl, vh[0], vh[1]);
                MMA_H(d1, aph, vh[2], vh[3]);
                MMA_H(d1, apl, vh[2], vh[3]);
            }
        }
    }

    // ---- finalize: normalize, write fp16 hi/lo to g_oh/g_ol [B,T,D] ----
    lA += __shfl_xor_sync(0xffffffffu, lA, 1);
    lA += __shfl_xor_sync(0xffffffffu, lA, 2);
    lB += __shfl_xor_sync(0xffffffffu, lB, 1);
    lB += __shfl_xor_sync(0xffffffffu, lB, 2);
    float invA = 1.f / lA, invB = 1.f / lB;

    int rA = qs + wid * 16 + (lane >> 2);
    int c0 = 2 * (lane & 3);
    size_t baseA = ((size_t)(b * T_ + rA)) * D_ + head * HD;
    size_t baseB = baseA + (size_t)8 * D_;
#pragma unroll
    for (int nt = 0; nt < 16; nt++) {
        int cc = nt * 8 + c0;
        float a0 = oacc[nt][0] * invA, a1 = oacc[nt][1] * invA;
        float b0 = oacc[nt][2] * invB, b1 = oacc[nt][3] * invB;
        __half2 hA = __floats2half2_rn(a0, a1);
        __half2 lA2 = __floats2half2_rn(a0 - __low2float(hA), a1 - __high2float(hA));
        __half2 hB = __floats2half2_rn(b0, b1);
        __half2 lB2 = __floats2half2_rn(b0 - __low2float(hB), b1 - __high2float(hB));
        *(__half2*)(g_oh + baseA + cc) = hA;
        *(__half2*)(g_ol + baseA + cc) = lA2;
        *(__half2*)(g_oh + baseB + cc) = hB;
        *(__half2*)(g_ol + baseB + cc) = lB2;
    }
}

// ---------------------------------------------------------------------------
// Launch. Inputs: x, mask, cos, sin, w_attn, w_out. mask is tril -> causal.
// ---------------------------------------------------------------------------
extern "C" void kernel_launch(void* const* d_in, const int* in_sizes, int n_in,
                              void* d_out, int out_size)
{
    const float* x      = (const float*)d_in[0];
    const float* cosT   = (const float*)d_in[2];
    const float* sinT   = (const float*)d_in[3];
    const float* w_attn = (const float*)d_in[4];
    const float* w_out  = (const float*)d_in[5];
    float* out = (float*)d_out;

    cudaFuncSetAttribute(gemm_qkv, cudaFuncAttributeMaxDynamicSharedMemorySize, Q_SMEM);
    cudaFuncSetAttribute(out_gemm, cudaFuncAttributeMaxDynamicSharedMemorySize, G_SMEM);
    cudaFuncSetAttribute(attn_mma, cudaFuncAttributeMaxDynamicSharedMemorySize,
                         AT_SMEM_BYTES);

    // Preprocessing: x -> fp16, weight transposes (fp16)
    split_act<<<(B_ * T_ * D_ / 4) / 256, 256>>>(x);
    transpose_h<<<dim3(192, 64), dim3(32, 8)>>>(w_attn, D_, 3 * D_, 0);
    transpose_h<<<dim3(64, 64), dim3(32, 8)>>>(w_out, D_, D_, 1);

    // QKV projection (1-term fp16, BK=64) -> q hi/lo, k, v (RoPE'd)
    gemm_qkv<<<dim3(96, 32), 256, Q_SMEM>>>(cosT, sinT);

    // fp16 tensor-core flash attention -> fp16 hi/lo
    attn_mma<<<dim3(32, NH, B_), 128, AT_SMEM_BYTES>>>();

    // Output projection (2-term fp16)
    out_gemm<<<dim3(32, 32), 256, G_SMEM>>>(out);
}

// round 11
// speedup vs baseline: 8.5388x; 1.2908x over previous
#include <cuda_runtime.h>
#include <cuda_fp16.h>
#include <cstdint>

// Problem constants
#define B_   2
#define T_   2048
#define D_   2048
#define NH   16
#define HD   128
#define FR   64
#define KTOT 2048
#define QK_SCALE 0.08838834764831845f   // 1/sqrt(128)

// ---------------------------------------------------------------------------
// Device-global scratch (allocation-free, graph-capture safe)
// ---------------------------------------------------------------------------
__device__ __half g_x_hi[(size_t)B_ * T_ * D_];          // x as fp16
__device__ __half g_oh[(size_t)B_ * T_ * D_];            // attn out (fp16)
__device__ __half g_wa_h[(size_t)3 * D_ * D_];           // w_attn^T fp16: [6144][2048]
__device__ __half g_wo_h[(size_t)D_ * D_];               // w_out^T fp16: [2048][2048]
// Q/K/V single fp16 (K,V RoPE applied; Q unscaled), [B,N,T,H]
__device__ __half g_qh[(size_t)B_ * NH * T_ * HD];
__device__ __half g_kh[(size_t)B_ * NH * T_ * HD];
__device__ __half g_vh[(size_t)B_ * NH * T_ * HD];

__device__ __forceinline__ uint32_t smem_u32(const void* p) {
    uint32_t a;
    asm("{ .reg .u64 t; cvta.to.shared.u64 t, %1; cvt.u32.u64 %0, t; }"
        : "=r"(a) : "l"(p));
    return a;
}
__device__ __forceinline__ void ldsm4(uint32_t& r0, uint32_t& r1, uint32_t& r2,
                                      uint32_t& r3, uint32_t addr) {
    asm volatile("ldmatrix.sync.aligned.m8n8.x4.shared.b16 {%0,%1,%2,%3}, [%4];"
                 : "=r"(r0), "=r"(r1), "=r"(r2), "=r"(r3) : "r"(addr));
}
__device__ __forceinline__ void ldsm4t(uint32_t& r0, uint32_t& r1, uint32_t& r2,
                                       uint32_t& r3, uint32_t addr) {
    asm volatile("ldmatrix.sync.aligned.m8n8.x4.trans.shared.b16 {%0,%1,%2,%3}, [%4];"
                 : "=r"(r0), "=r"(r1), "=r"(r2), "=r"(r3) : "r"(addr));
}
#define MMA_H(d, a, b0, b1)                                                    \
    asm volatile("mma.sync.aligned.m16n8k16.row.col.f32.f16.f16.f32 "          \
                 "{%0,%1,%2,%3},{%4,%5,%6,%7},{%8,%9},{%0,%1,%2,%3};"          \
                 : "+f"((d)[0]), "+f"((d)[1]), "+f"((d)[2]), "+f"((d)[3])      \
                 : "r"((a)[0]), "r"((a)[1]), "r"((a)[2]), "r"((a)[3]),         \
                   "r"(b0), "r"(b1))

__device__ __forceinline__ void cpa16(uint32_t dst, const void* src) {
    asm volatile("cp.async.cg.shared.global [%0], [%1], 16;"
                 :: "r"(dst), "l"(src));
}
#define CP_COMMIT() asm volatile("cp.async.commit_group;" ::: "memory")
#define CP_WAIT0()  asm volatile("cp.async.wait_group 0;" ::: "memory")
#define CP_WAIT2()  asm volatile("cp.async.wait_group 2;" ::: "memory")

// ---------------------------------------------------------------------------
// x -> fp16
// ---------------------------------------------------------------------------
__global__ __launch_bounds__(256) void split_act(const float* __restrict__ src)
{
    int i = blockIdx.x * 256 + threadIdx.x;          // float4 index
    float4 f = ((const float4*)src)[i];
    ((__half2*)g_x_hi)[2 * i]     = __floats2half2_rn(f.x, f.y);
    ((__half2*)g_x_hi)[2 * i + 1] = __floats2half2_rn(f.z, f.w);
}

// ---------------------------------------------------------------------------
// Weight transpose to fp16: src fp32 [R][C] -> dst fp16 [C][R]
// ---------------------------------------------------------------------------
__global__ __launch_bounds__(256) void transpose_h(const float* __restrict__ src,
                                                   int R, int C, int which)
{
    __shared__ float tile[32][33];
    __half* dh = which ? g_wo_h : g_wa_h;
    int x = blockIdx.x * 32 + threadIdx.x;
    int y0 = blockIdx.y * 32;
#pragma unroll
    for (int j = 0; j < 32; j += 8)
        tile[threadIdx.y + j][threadIdx.x] = src[(size_t)(y0 + threadIdx.y + j) * C + x];
    __syncthreads();
    int xo = y0 + threadIdx.x;
    int yo = blockIdx.x * 32;
#pragma unroll
    for (int j = 0; j < 32; j += 8)
        dh[(size_t)(yo + threadIdx.y + j) * R + xo] =
            __float2half_rn(tile[threadIdx.x][threadIdx.y + j]);
}

// ---------------------------------------------------------------------------
// 1-term fp16 GEMM, CTA tile 128x64, 4 warps (2m x 2n), warp tile 64x32,
// BK=64, 4-stage cp.async, 108KB smem -> 2 CTA/SM.
// MODE 0 (QKV): A=g_x_hi, W=g_wa_h; epilogue head split, q plain / k,v RoPE.
// MODE 1 (out): A=g_oh,  W=g_wo_h; plain fp32 store.
// ---------------------------------------------------------------------------
#define QSTRIDE 72
#define QA_ELE (128 * QSTRIDE)              // 9216 halves
#define QW_ELE (64 * QSTRIDE)               // 4608 halves
#define Q_STAGE_ELE (QA_ELE + QW_ELE)       // 13824 halves
#define Q_SMEM (4 * Q_STAGE_ELE * 2)        // 110592 bytes

template <int MODE>
__global__ __launch_bounds__(128, 2) void gemm1(
    const float* __restrict__ cosT, const float* __restrict__ sinT,
    float* __restrict__ Cout)
{
    extern __shared__ __half smem_h[];
    const int tid = threadIdx.x;
    const int wid = tid >> 5, lane = tid & 31;
    const int warp_m = wid & 1, warp_n = wid >> 1;
    const int m0 = (int)blockIdx.y << 7, n0 = (int)blockIdx.x << 6;
    const uint32_t sb = smem_u32(smem_h);

    const __half* Ag = MODE ? g_oh : g_x_hi;
    const __half* Wg = MODE ? g_wo_h : g_wa_h;

    float acc[4][4][4];
#pragma unroll
    for (int i = 0; i < 4; i++)
#pragma unroll
        for (int j = 0; j < 4; j++)
#pragma unroll
            for (int k = 0; k < 4; k++) acc[i][j][k] = 0.f;

    const uint32_t a_lm = ((warp_m * 64 + (lane & 15)) * QSTRIDE + (lane >> 4) * 8) * 2;
    const uint32_t b_lm = (uint32_t)(QA_ELE +
        (warp_n * 32 + (lane & 7) + ((lane >> 4) << 3)) * QSTRIDE +
        (((lane >> 3) & 1) << 3)) * 2;

    auto LOAD = [&](int stage, int kc) {
        int k0 = kc << 6;
        uint32_t sbs = sb + (uint32_t)stage * Q_STAGE_ELE * 2;
#pragma unroll
        for (int i = 0; i < 8; i++) {                // A: 1024 chunks
            int c = tid + (i << 7);
            int r = c >> 3, col = (c & 7) << 3;
            cpa16(sbs + (uint32_t)(r * QSTRIDE + col) * 2,
                  Ag + (size_t)(m0 + r) * KTOT + k0 + col);
        }
#pragma unroll
        for (int i = 0; i < 4; i++) {                // W: 512 chunks
            int c = tid + (i << 7);
            int r = c >> 3, col = (c & 7) << 3;
            cpa16(sbs + (uint32_t)QA_ELE * 2 + (uint32_t)(r * QSTRIDE + col) * 2,
                  Wg + (size_t)(n0 + r) * KTOT + k0 + col);
        }
        CP_COMMIT();
    };

    auto COMPUTE = [&](int st) {
        uint32_t stb = sb + (uint32_t)st * Q_STAGE_ELE * 2;
#pragma unroll
        for (int ks = 0; ks < 4; ks++) {
            uint32_t ah[4][4], bh[2][4];
#pragma unroll
            for (int mt = 0; mt < 4; mt++)
                ldsm4(ah[mt][0], ah[mt][1], ah[mt][2], ah[mt][3],
                      stb + a_lm + (mt * 16 * QSTRIDE + ks * 16) * 2);
#pragma unroll
            for (int np = 0; np < 2; np++)
                ldsm4(bh[np][0], bh[np][1], bh[np][2], bh[np][3],
                      stb + b_lm + (np * 16 * QSTRIDE + ks * 16) * 2);
#pragma unroll
            for (int mt = 0; mt < 4; mt++)
#pragma unroll
                for (int np = 0; np < 2; np++) {
                    MMA_H(acc[mt][np * 2],     ah[mt], bh[np][0], bh[np][1]);
                    MMA_H(acc[mt][np * 2 + 1], ah[mt], bh[np][2], bh[np][3]);
                }
        }
    };

    const int NI = KTOT / 64;            // 32
    LOAD(0, 0);
    LOAD(1, 1);
    LOAD(2, 2);
#pragma unroll 1
    for (int it = 0; it < NI; it++) {
        CP_WAIT2();
        __syncthreads();
        if (it + 3 < NI) LOAD((it + 3) & 3, it + 3);
        else CP_COMMIT();                // keep group count uniform
        COMPUTE(it & 3);
    }

    // ---------------- epilogue ----------------
    const int rb = lane >> 2;
    const int cb = (lane & 3) * 2;
    if (MODE == 0) {
        int sec = n0 >> 11;              // 0=q 1=k 2=v
        int head = (n0 >> 7) & 15;
        __half* dst = (sec == 0) ? g_qh : (sec == 1 ? g_kh : g_vh);
#pragma unroll
        for (int mt = 0; mt < 4; mt++)
#pragma unroll
            for (int hf = 0; hf < 2; hf++) {
                int m = m0 + warp_m * 64 + mt * 16 + hf * 8 + rb;
                int b = m >> 11, t = m & 2047;
                size_t rowbase = ((size_t)(b * NH + head) * T_ + t) * HD;
#pragma unroll
                for (int j = 0; j < 4; j++) {
                    int n = n0 + warp_n * 32 + j * 8 + cb;
                    int hh = n & 127;
                    float v0 = acc[mt][j][hf * 2];
                    float v1 = acc[mt][j][hf * 2 + 1];
                    if (sec) {
                        float cz = cosT[t * FR + (hh >> 1)];
                        float sz = sinT[t * FR + (hh >> 1)];
                        float r0 = v0 * cz - v1 * sz;
                        float r1 = v0 * sz + v1 * cz;
                        v0 = r0; v1 = r1;
                    }
                    *(__half2*)(dst + rowbase + hh) = __floats2half2_rn(v0, v1);
                }
            }
    } else {
#pragma unroll
        for (int mt = 0; mt < 4; mt++)
#pragma unroll
            for (int hf = 0; hf < 2; hf++) {
                int m = m0 + warp_m * 64 + mt * 16 + hf * 8 + rb;
#pragma unroll
                for (int j = 0; j < 4; j++) {
                    int n = n0 + warp_n * 32 + j * 8 + cb;
                    *(float2*)&Cout[(size_t)m * D_ + n] =
                        make_float2(acc[mt][j][hf * 2], acc[mt][j][hf * 2 + 1]);
                }
            }
    }
}

// ---------------------------------------------------------------------------
// fp16 tensor-core causal flash attention.
// QK: S = qh . kh           (1 MMA; scale applied to scores).
// PV: O = (ph+pl) . vh      (2 MMA, P register-split fp16).
// SMEM: Qh Kh Vh, each [64][136] fp16 = 52224 B -> 4 CTAs/SM.
// ---------------------------------------------------------------------------
#define AT_STRIDE 136
#define AT_TILE   (64 * AT_STRIDE)
#define AT_SMEM_BYTES (3 * AT_TILE * 2)

__global__ __launch_bounds__(128) void attn_mma()
{
    extern __shared__ __half sm_at[];
    const int tid = threadIdx.x, wid = tid >> 5, lane = tid & 31;
    const int qt = 31 - (int)blockIdx.x;
    const int qs = qt << 6;
    const int head = blockIdx.y, b = blockIdx.z;
    const size_t hbase = (size_t)(b * NH + head) * T_ * HD;
    const uint32_t sb = smem_u32(sm_at);

    const uint32_t QH = 0, KH = AT_TILE, VH = 2 * AT_TILE;

    // preload Q: 1024 16B-chunks
#pragma unroll
    for (int i = 0; i < 8; i++) {
        int c = tid + i * 128;
        int r = c >> 4, col = (c & 15) << 3;
        cpa16(sb + QH * 2 + (uint32_t)(r * AT_STRIDE + col) * 2,
              g_qh + hbase + (size_t)(qs + r) * HD + col);
    }

    float oacc[16][4];
#pragma unroll
    for (int i = 0; i < 16; i++)
#pragma unroll
        for (int j = 0; j < 4; j++) oacc[i][j] = 0.f;
    float mA = -1e30f, mB = -1e30f, lA = 0.f, lB = 0.f;

    const uint32_t qbase = sb + QH * 2 +
        ((wid * 16 + (lane & 15)) * AT_STRIDE + ((lane >> 4) << 3)) * 2;
    const uint32_t kbase = sb + KH * 2 +
        (((lane & 7) + ((lane >> 4) << 3)) * AT_STRIDE + (((lane >> 3) & 1) << 3)) * 2;
    const uint32_t vbase = sb + VH * 2 +
        ((lane & 15) * AT_STRIDE + ((lane >> 4) << 3)) * 2;

#pragma unroll 1
    for (int jt = 0; jt <= qt; jt++) {
        const int j0 = jt << 6;
        if (jt) __syncthreads();
#pragma unroll
        for (int i = 0; i < 8; i++) {
            int c = tid + i * 128;
            int r = c >> 4, col = (c & 15) << 3;
            size_t g = hbase + (size_t)(j0 + r) * HD + col;
            uint32_t so = (uint32_t)(r * AT_STRIDE + col) * 2;
            cpa16(sb + KH * 2 + so, g_kh + g);
            cpa16(sb + VH * 2 + so, g_vh + g);
        }
        CP_COMMIT();
        CP_WAIT0();
        __syncthreads();

        // ---- S = Q K^T (1-term fp16) ----
        float sacc[8][4];
#pragma unroll
        for (int i = 0; i < 8; i++)
#pragma unroll
            for (int j = 0; j < 4; j++) sacc[i][j] = 0.f;

#pragma unroll
        for (int ks = 0; ks < 8; ks++) {
            uint32_t qh[4];
            ldsm4(qh[0], qh[1], qh[2], qh[3], qbase + ks * 32);
#pragma unroll
            for (int np = 0; np < 4; np++) {
                uint32_t kh[4];
                ldsm4(kh[0], kh[1], kh[2], kh[3],
                      kbase + (np * 16 * AT_STRIDE) * 2 + ks * 32);
                MMA_H(sacc[2 * np],     qh, kh[0], kh[1]);
                MMA_H(sacc[2 * np + 1], qh, kh[2], kh[3]);
            }
        }

        // ---- scale + causal mask ----
#pragma unroll
        for (int nt = 0; nt < 8; nt++)
#pragma unroll
            for (int j = 0; j < 4; j++) sacc[nt][j] *= QK_SCALE;
        if (jt == qt) {
            int rA = wid * 16 + (lane >> 2);
            int c0 = 2 * (lane & 3);
#pragma unroll
            for (int nt = 0; nt < 8; nt++) {
                int cc = nt * 8 + c0;
                if (cc > rA)         sacc[nt][0] = -1e30f;
                if (cc + 1 > rA)     sacc[nt][1] = -1e30f;
                if (cc > rA + 8)     sacc[nt][2] = -1e30f;
                if (cc + 1 > rA + 8) sacc[nt][3] = -1e30f;
            }
        }

        // ---- online softmax ----
        float tmA = -1e30f, tmB = -1e30f;
#pragma unroll
        for (int nt = 0; nt < 8; nt++) {
            tmA = fmaxf(tmA, fmaxf(sacc[nt][0], sacc[nt][1]));
            tmB = fmaxf(tmB, fmaxf(sacc[nt][2], sacc[nt][3]));
        }
        tmA = fmaxf(tmA, __shfl_xor_sync(0xffffffffu, tmA, 1));
        tmA = fmaxf(tmA, __shfl_xor_sync(0xffffffffu, tmA, 2));
        tmB = fmaxf(tmB, __shfl_xor_sync(0xffffffffu, tmB, 1));
        tmB = fmaxf(tmB, __shfl_xor_sync(0xffffffffu, tmB, 2));
        float mnA = fmaxf(mA, tmA), mnB = fmaxf(mB, tmB);
        float aAl = __expf(mA - mnA), aBl = __expf(mB - mnB);
        mA = mnA; mB = mnB;

        float psA = 0.f, psB = 0.f;
        uint32_t ph[8][2], pl[8][2];
#pragma unroll
        for (int nt = 0; nt < 8; nt++) {
            float p0 = __expf(sacc[nt][0] - mA);
            float p1 = __expf(sacc[nt][1] - mA);
            float p2 = __expf(sacc[nt][2] - mB);
            float p3 = __expf(sacc[nt][3] - mB);
            psA += p0 + p1;
            psB += p2 + p3;
            __half2 hA2 = __floats2half2_rn(p0, p1);
            __half2 hB2 = __floats2half2_rn(p2, p3);
            __half2 lA2 = __floats2half2_rn(p0 - __low2float(hA2),
                                            p1 - __high2float(hA2));
            __half2 lB2 = __floats2half2_rn(p2 - __low2float(hB2),
                                            p3 - __high2float(hB2));
            ph[nt][0] = *(uint32_t*)&hA2;
            ph[nt][1] = *(uint32_t*)&hB2;
            pl[nt][0] = *(uint32_t*)&lA2;
            pl[nt][1] = *(uint32_t*)&lB2;
        }
        lA = lA * aAl + psA;
        lB = lB * aBl + psB;
#pragma unroll
        for (int nt = 0; nt < 16; nt++) {
            oacc[nt][0] *= aAl;
            oacc[nt][1] *= aAl;
            oacc[nt][2] *= aBl;
            oacc[nt][3] *= aBl;
        }

        // ---- O += P V (2-term fp16), V b-frags via ldmatrix.trans ----
#pragma unroll
        for (int ks = 0; ks < 4; ks++) {
            uint32_t aph[4] = {ph[2 * ks][0], ph[2 * ks][1],
                               ph[2 * ks + 1][0], ph[2 * ks + 1][1]};
            uint32_t apl[4] = {pl[2 * ks][0], pl[2 * ks][1],
                               pl[2 * ks + 1][0], pl[2 * ks + 1][1]};
#pragma unroll
            for (int np = 0; np < 8; np++) {
                uint32_t vh[4];
                ldsm4t(vh[0], vh[1], vh[2], vh[3],
                       vbase + (ks * 16 * AT_STRIDE) * 2 + np * 32);
                float* d0 = oacc[2 * np];
                float* d1 = oacc[2 * np + 1];
                MMA_H(d0, aph, vh[0], vh[1]);
                MMA_H(d0, apl, vh[0], vh[1]);
                MMA_H(d1, aph, vh[2], vh[3]);
                MMA_H(d1, apl, vh[2], vh[3]);
            }
        }
    }

    // ---- finalize: normalize, write fp16 to g_oh [B,T,D] ----
    lA += __shfl_xor_sync(0xffffffffu, lA, 1);
    lA += __shfl_xor_sync(0xffffffffu, lA, 2);
    lB += __shfl_xor_sync(0xffffffffu, lB, 1);
    lB += __shfl_xor_sync(0xffffffffu, lB, 2);
    float invA = 1.f / lA, invB = 1.f / lB;

    int rA = qs + wid * 16 + (lane >> 2);
    int c0 = 2 * (lane & 3);
    size_t baseA = ((size_t)(b * T_ + rA)) * D_ + head * HD;
    size_t baseB = baseA + (size_t)8 * D_;
#pragma unroll
    for (int nt = 0; nt < 16; nt++) {
        int cc = nt * 8 + c0;
        *(__half2*)(g_oh + baseA + cc) =
            __floats2half2_rn(oacc[nt][0] * invA, oacc[nt][1] * invA);
        *(__half2*)(g_oh + baseB + cc) =
            __floats2half2_rn(oacc[nt][2] * invB, oacc[nt][3] * invB);
    }
}

// ---------------------------------------------------------------------------
// Launch. Inputs: x, mask, cos, sin, w_attn, w_out. mask is tril -> causal.
// ---------------------------------------------------------------------------
extern "C" void kernel_launch(void* const* d_in, const int* in_sizes, int n_in,
                              void* d_out, int out_size)
{
    const float* x      = (const float*)d_in[0];
    const float* cosT   = (const float*)d_in[2];
    const float* sinT   = (const float*)d_in[3];
    const float* w_attn = (const float*)d_in[4];
    const float* w_out  = (const float*)d_in[5];
    float* out = (float*)d_out;

    cudaFuncSetAttribute(gemm1<0>, cudaFuncAttributeMaxDynamicSharedMemorySize, Q_SMEM);
    cudaFuncSetAttribute(gemm1<1>, cudaFuncAttributeMaxDynamicSharedMemorySize, Q_SMEM);
    cudaFuncSetAttribute(attn_mma, cudaFuncAttributeMaxDynamicSharedMemorySize,
                         AT_SMEM_BYTES);

    // Preprocessing: x -> fp16, weight transposes (fp16)
    split_act<<<(B_ * T_ * D_ / 4) / 256, 256>>>(x);
    transpose_h<<<dim3(192, 64), dim3(32, 8)>>>(w_attn, D_, 3 * D_, 0);
    transpose_h<<<dim3(64, 64), dim3(32, 8)>>>(w_out, D_, D_, 1);

    // QKV projection (1-term fp16, BK=64, 64x32 warp tiles)
    gemm1<0><<<dim3(96, 32), 128, Q_SMEM>>>(cosT, sinT, nullptr);

    // fp16 tensor-core flash attention (1-term QK, 2-term PV)
    attn_mma<<<dim3(32, NH, B_), 128, AT_SMEM_BYTES>>>();

    // Output projection (1-term fp16)
    gemm1<1><<<dim3(32, 32), 128, Q_SMEM>>>(cosT, sinT, out);
}

// round 12
// speedup vs baseline: 9.5216x; 1.1151x over previous
#include <cuda_runtime.h>
#include <cuda_fp16.h>
#include <cstdint>

// Problem constants
#define B_   2
#define T_   2048
#define D_   2048
#define NH   16
#define HD   128
#define FR   64
#define KTOT 2048
#define QK_SCALE 0.08838834764831845f   // 1/sqrt(128)

// ---------------------------------------------------------------------------
// Device-global scratch (allocation-free, graph-capture safe)
// ---------------------------------------------------------------------------
__device__ __half g_x_hi[(size_t)B_ * T_ * D_];          // x as fp16
__device__ __half g_oh[(size_t)B_ * T_ * D_];            // attn out (fp16)
__device__ __half g_wa_h[(size_t)3 * D_ * D_];           // w_attn fp16 [2048][6144]
__device__ __half g_wo_h[(size_t)D_ * D_];               // w_out fp16  [2048][2048]
// Q/K/V single fp16 (K,V RoPE applied; Q unscaled), [B,N,T,H]
__device__ __half g_qh[(size_t)B_ * NH * T_ * HD];
__device__ __half g_kh[(size_t)B_ * NH * T_ * HD];
__device__ __half g_vh[(size_t)B_ * NH * T_ * HD];

__device__ __forceinline__ uint32_t smem_u32(const void* p) {
    uint32_t a;
    asm("{ .reg .u64 t; cvta.to.shared.u64 t, %1; cvt.u32.u64 %0, t; }"
        : "=r"(a) : "l"(p));
    return a;
}
__device__ __forceinline__ void ldsm4(uint32_t& r0, uint32_t& r1, uint32_t& r2,
                                      uint32_t& r3, uint32_t addr) {
    asm volatile("ldmatrix.sync.aligned.m8n8.x4.shared.b16 {%0,%1,%2,%3}, [%4];"
                 : "=r"(r0), "=r"(r1), "=r"(r2), "=r"(r3) : "r"(addr));
}
__device__ __forceinline__ void ldsm4t(uint32_t& r0, uint32_t& r1, uint32_t& r2,
                                       uint32_t& r3, uint32_t addr) {
    asm volatile("ldmatrix.sync.aligned.m8n8.x4.trans.shared.b16 {%0,%1,%2,%3}, [%4];"
                 : "=r"(r0), "=r"(r1), "=r"(r2), "=r"(r3) : "r"(addr));
}
#define MMA_H(d, a, b0, b1)                                                    \
    asm volatile("mma.sync.aligned.m16n8k16.row.col.f32.f16.f16.f32 "          \
                 "{%0,%1,%2,%3},{%4,%5,%6,%7},{%8,%9},{%0,%1,%2,%3};"          \
                 : "+f"((d)[0]), "+f"((d)[1]), "+f"((d)[2]), "+f"((d)[3])      \
                 : "r"((a)[0]), "r"((a)[1]), "r"((a)[2]), "r"((a)[3]),         \
                   "r"(b0), "r"(b1))

__device__ __forceinline__ void cpa16(uint32_t dst, const void* src) {
    asm volatile("cp.async.cg.shared.global [%0], [%1], 16;"
                 :: "r"(dst), "l"(src));
}
#define CP_COMMIT() asm volatile("cp.async.commit_group;" ::: "memory")
#define CP_WAIT0()  asm volatile("cp.async.wait_group 0;" ::: "memory")
#define CP_WAIT2()  asm volatile("cp.async.wait_group 2;" ::: "memory")

// ---------------------------------------------------------------------------
// fp32 -> fp16 elementwise copy (x and weights; layout preserved)
// ---------------------------------------------------------------------------
__global__ __launch_bounds__(256) void conv_half(const float* __restrict__ src,
                                                 __half* __restrict__ dst)
{
    int i = blockIdx.x * 256 + threadIdx.x;          // float4 index
    float4 f = ((const float4*)src)[i];
    ((__half2*)dst)[2 * i]     = __floats2half2_rn(f.x, f.y);
    ((__half2*)dst)[2 * i + 1] = __floats2half2_rn(f.z, f.w);
}

// ---------------------------------------------------------------------------
// 1-term fp16 GEMM, CTA tile 128x64, 4 warps (2m x 2n), warp tile 64x32,
// BK=64, 4-stage cp.async. W kept K-major [K][N]; B-fragments via
// ldmatrix.trans (same geometry as the attention V path).
// MODE 0 (QKV): A=g_x_hi, W=g_wa_h (N=6144); epilogue head split + RoPE(k,v).
// MODE 1 (out): A=g_oh,  W=g_wo_h (N=2048); plain fp32 store.
// ---------------------------------------------------------------------------
#define QSTRIDE 72
#define QA_ELE (128 * QSTRIDE)              // 9216 halves (A: 128 m x 64 k)
#define QW_ELE (64 * QSTRIDE)               // 4608 halves (W: 64 k x 64 n)
#define Q_STAGE_ELE (QA_ELE + QW_ELE)       // 13824 halves
#define Q_SMEM (4 * Q_STAGE_ELE * 2)        // 110592 bytes

template <int MODE>
__global__ __launch_bounds__(128, 2) void gemm1(
    const float* __restrict__ cosT, const float* __restrict__ sinT,
    float* __restrict__ Cout)
{
    extern __shared__ __half smem_h[];
    const int tid = threadIdx.x;
    const int wid = tid >> 5, lane = tid & 31;
    const int warp_m = wid & 1, warp_n = wid >> 1;
    const int m0 = (int)blockIdx.y << 7, n0 = (int)blockIdx.x << 6;
    const uint32_t sb = smem_u32(smem_h);

    const __half* Ag = MODE ? g_oh : g_x_hi;
    const __half* Wg = MODE ? g_wo_h : g_wa_h;
    const int WN = MODE ? D_ : 3 * D_;               // W row width (n)

    float acc[4][4][4];
#pragma unroll
    for (int i = 0; i < 4; i++)
#pragma unroll
        for (int j = 0; j < 4; j++)
#pragma unroll
            for (int k = 0; k < 4; k++) acc[i][j][k] = 0.f;

    const uint32_t a_lm = ((warp_m * 64 + (lane & 15)) * QSTRIDE + (lane >> 4) * 8) * 2;
    // W tile [64 k-rows][64 n-cols]: trans-fragment base (attn-V pattern)
    const uint32_t b_lm = (uint32_t)(QA_ELE +
        (lane & 15) * QSTRIDE + ((lane >> 4) << 3) + warp_n * 32) * 2;

    auto LOAD = [&](int stage, int kc) {
        int k0 = kc << 6;
        uint32_t sbs = sb + (uint32_t)stage * Q_STAGE_ELE * 2;
#pragma unroll
        for (int i = 0; i < 8; i++) {                // A: 1024 chunks
            int c = tid + (i << 7);
            int r = c >> 3, col = (c & 7) << 3;
            cpa16(sbs + (uint32_t)(r * QSTRIDE + col) * 2,
                  Ag + (size_t)(m0 + r) * KTOT + k0 + col);
        }
#pragma unroll
        for (int i = 0; i < 4; i++) {                // W: 512 chunks, K-major
            int c = tid + (i << 7);
            int r = c >> 3, col = (c & 7) << 3;      // r = k-row, col = n
            cpa16(sbs + (uint32_t)QA_ELE * 2 + (uint32_t)(r * QSTRIDE + col) * 2,
                  Wg + (size_t)(k0 + r) * WN + n0 + col);
        }
        CP_COMMIT();
    };

    auto COMPUTE = [&](int st) {
        uint32_t stb = sb + (uint32_t)st * Q_STAGE_ELE * 2;
#pragma unroll
        for (int ks = 0; ks < 4; ks++) {
            uint32_t ah[4][4], bh[2][4];
#pragma unroll
            for (int mt = 0; mt < 4; mt++)
                ldsm4(ah[mt][0], ah[mt][1], ah[mt][2], ah[mt][3],
                      stb + a_lm + (mt * 16 * QSTRIDE + ks * 16) * 2);
#pragma unroll
            for (int nn = 0; nn < 2; nn++)
                ldsm4t(bh[nn][0], bh[nn][1], bh[nn][2], bh[nn][3],
                       stb + b_lm + (ks * 16 * QSTRIDE) * 2 + nn * 32);
#pragma unroll
            for (int mt = 0; mt < 4; mt++)
#pragma unroll
                for (int nn = 0; nn < 2; nn++) {
                    MMA_H(acc[mt][nn * 2],     ah[mt], bh[nn][0], bh[nn][1]);
                    MMA_H(acc[mt][nn * 2 + 1], ah[mt], bh[nn][2], bh[nn][3]);
                }
        }
    };

    const int NI = KTOT / 64;            // 32
    LOAD(0, 0);
    LOAD(1, 1);
    LOAD(2, 2);
#pragma unroll 1
    for (int it = 0; it < NI; it++) {
        CP_WAIT2();
        __syncthreads();
        if (it + 3 < NI) LOAD((it + 3) & 3, it + 3);
        else CP_COMMIT();                // keep group count uniform
        COMPUTE(it & 3);
    }

    // ---------------- epilogue ----------------
    const int rb = lane >> 2;
    const int cb = (lane & 3) * 2;
    if (MODE == 0) {
        int sec = n0 >> 11;              // 0=q 1=k 2=v
        int head = (n0 >> 7) & 15;
        __half* dst = (sec == 0) ? g_qh : (sec == 1 ? g_kh : g_vh);
#pragma unroll
        for (int mt = 0; mt < 4; mt++)
#pragma unroll
            for (int hf = 0; hf < 2; hf++) {
                int m = m0 + warp_m * 64 + mt * 16 + hf * 8 + rb;
                int b = m >> 11, t = m & 2047;
                size_t rowbase = ((size_t)(b * NH + head) * T_ + t) * HD;
#pragma unroll
                for (int j = 0; j < 4; j++) {
                    int n = n0 + warp_n * 32 + j * 8 + cb;
                    int hh = n & 127;
                    float v0 = acc[mt][j][hf * 2];
                    float v1 = acc[mt][j][hf * 2 + 1];
                    if (sec) {
                        float cz = cosT[t * FR + (hh >> 1)];
                        float sz = sinT[t * FR + (hh >> 1)];
                        float r0 = v0 * cz - v1 * sz;
                        float r1 = v0 * sz + v1 * cz;
                        v0 = r0; v1 = r1;
                    }
                    *(__half2*)(dst + rowbase + hh) = __floats2half2_rn(v0, v1);
                }
            }
    } else {
#pragma unroll
        for (int mt = 0; mt < 4; mt++)
#pragma unroll
            for (int hf = 0; hf < 2; hf++) {
                int m = m0 + warp_m * 64 + mt * 16 + hf * 8 + rb;
#pragma unroll
                for (int j = 0; j < 4; j++) {
                    int n = n0 + warp_n * 32 + j * 8 + cb;
                    *(float2*)&Cout[(size_t)m * D_ + n] =
                        make_float2(acc[mt][j][hf * 2], acc[mt][j][hf * 2 + 1]);
                }
            }
    }
}

// ---------------------------------------------------------------------------
// fp16 tensor-core causal flash attention.
// QK: S = qh . kh   (1 MMA; scale on scores).
// PV: O = ph . vh   (1 MMA; P fp16).
// SMEM: Qh Kh Vh, each [64][136] fp16 = 52224 B -> up to 4 CTAs/SM.
// ---------------------------------------------------------------------------
#define AT_STRIDE 136
#define AT_TILE   (64 * AT_STRIDE)
#define AT_SMEM_BYTES (3 * AT_TILE * 2)

__global__ __launch_bounds__(128) void attn_mma()
{
    extern __shared__ __half sm_at[];
    const int tid = threadIdx.x, wid = tid >> 5, lane = tid & 31;
    const int qt = 31 - (int)blockIdx.x;
    const int qs = qt << 6;
    const int head = blockIdx.y, b = blockIdx.z;
    const size_t hbase = (size_t)(b * NH + head) * T_ * HD;
    const uint32_t sb = smem_u32(sm_at);

    const uint32_t QH = 0, KH = AT_TILE, VH = 2 * AT_TILE;

#pragma unroll
    for (int i = 0; i < 8; i++) {
        int c = tid + i * 128;
        int r = c >> 4, col = (c & 15) << 3;
        cpa16(sb + QH * 2 + (uint32_t)(r * AT_STRIDE + col) * 2,
              g_qh + hbase + (size_t)(qs + r) * HD + col);
    }

    float oacc[16][4];
#pragma unroll
    for (int i = 0; i < 16; i++)
#pragma unroll
        for (int j = 0; j < 4; j++) oacc[i][j] = 0.f;
    float mA = -1e30f, mB = -1e30f, lA = 0.f, lB = 0.f;

    const uint32_t qbase = sb + QH * 2 +
        ((wid * 16 + (lane & 15)) * AT_STRIDE + ((lane >> 4) << 3)) * 2;
    const uint32_t kbase = sb + KH * 2 +
        (((lane & 7) + ((lane >> 4) << 3)) * AT_STRIDE + (((lane >> 3) & 1) << 3)) * 2;
    const uint32_t vbase = sb + VH * 2 +
        ((lane & 15) * AT_STRIDE + ((lane >> 4) << 3)) * 2;

#pragma unroll 1
    for (int jt = 0; jt <= qt; jt++) {
        const int j0 = jt << 6;
        if (jt) __syncthreads();
#pragma unroll
        for (int i = 0; i < 8; i++) {
            int c = tid + i * 128;
            int r = c >> 4, col = (c & 15) << 3;
            size_t g = hbase + (size_t)(j0 + r) * HD + col;
            uint32_t so = (uint32_t)(r * AT_STRIDE + col) * 2;
            cpa16(sb + KH * 2 + so, g_kh + g);
            cpa16(sb + VH * 2 + so, g_vh + g);
        }
        CP_COMMIT();
        CP_WAIT0();
        __syncthreads();

        // ---- S = Q K^T (1-term fp16) ----
        float sacc[8][4];
#pragma unroll
        for (int i = 0; i < 8; i++)
#pragma unroll
            for (int j = 0; j < 4; j++) sacc[i][j] = 0.f;

#pragma unroll
        for (int ks = 0; ks < 8; ks++) {
            uint32_t qh[4];
            ldsm4(qh[0], qh[1], qh[2], qh[3], qbase + ks * 32);
#pragma unroll
            for (int np = 0; np < 4; np++) {
                uint32_t kh[4];
                ldsm4(kh[0], kh[1], kh[2], kh[3],
                      kbase + (np * 16 * AT_STRIDE) * 2 + ks * 32);
                MMA_H(sacc[2 * np],     qh, kh[0], kh[1]);
                MMA_H(sacc[2 * np + 1], qh, kh[2], kh[3]);
            }
        }

        // ---- scale + causal mask ----
#pragma unroll
        for (int nt = 0; nt < 8; nt++)
#pragma unroll
            for (int j = 0; j < 4; j++) sacc[nt][j] *= QK_SCALE;
        if (jt == qt) {
            int rA = wid * 16 + (lane >> 2);
            int c0 = 2 * (lane & 3);
#pragma unroll
            for (int nt = 0; nt < 8; nt++) {
                int cc = nt * 8 + c0;
                if (cc > rA)         sacc[nt][0] = -1e30f;
                if (cc + 1 > rA)     sacc[nt][1] = -1e30f;
                if (cc > rA + 8)     sacc[nt][2] = -1e30f;
                if (cc + 1 > rA + 8) sacc[nt][3] = -1e30f;
            }
        }

        // ---- online softmax ----
        float tmA = -1e30f, tmB = -1e30f;
#pragma unroll
        for (int nt = 0; nt < 8; nt++) {
            tmA = fmaxf(tmA, fmaxf(sacc[nt][0], sacc[nt][1]));
            tmB = fmaxf(tmB, fmaxf(sacc[nt][2], sacc[nt][3]));
        }
        tmA = fmaxf(tmA, __shfl_xor_sync(0xffffffffu, tmA, 1));
        tmA = fmaxf(tmA, __shfl_xor_sync(0xffffffffu, tmA, 2));
        tmB = fmaxf(tmB, __shfl_xor_sync(0xffffffffu, tmB, 1));
        tmB = fmaxf(tmB, __shfl_xor_sync(0xffffffffu, tmB, 2));
        float mnA = fmaxf(mA, tmA), mnB = fmaxf(mB, tmB);
        float aAl = __expf(mA - mnA), aBl = __expf(mB - mnB);
        mA = mnA; mB = mnB;

        float psA = 0.f, psB = 0.f;
        uint32_t ph[8][2];
#pragma unroll
        for (int nt = 0; nt < 8; nt++) {
            float p0 = __expf(sacc[nt][0] - mA);
            float p1 = __expf(sacc[nt][1] - mA);
            float p2 = __expf(sacc[nt][2] - mB);
            float p3 = __expf(sacc[nt][3] - mB);
            psA += p0 + p1;
            psB += p2 + p3;
            __half2 hA2 = __floats2half2_rn(p0, p1);
            __half2 hB2 = __floats2half2_rn(p2, p3);
            ph[nt][0] = *(uint32_t*)&hA2;
            ph[nt][1] = *(uint32_t*)&hB2;
        }
        lA = lA * aAl + psA;
        lB = lB * aBl + psB;
#pragma unroll
        for (int nt = 0; nt < 16; nt++) {
            oacc[nt][0] *= aAl;
            oacc[nt][1] *= aAl;
            oacc[nt][2] *= aBl;
            oacc[nt][3] *= aBl;
        }

        // ---- O += P V (1-term fp16), V b-frags via ldmatrix.trans ----
#pragma unroll
        for (int ks = 0; ks < 4; ks++) {
            uint32_t aph[4] = {ph[2 * ks][0], ph[2 * ks][1],
                               ph[2 * ks + 1][0], ph[2 * ks + 1][1]};
#pragma unroll
            for (int np = 0; np < 8; np++) {
                uint32_t vh[4];
                ldsm4t(vh[0], vh[1], vh[2], vh[3],
                       vbase + (ks * 16 * AT_STRIDE) * 2 + np * 32);
                MMA_H(oacc[2 * np],     aph, vh[0], vh[1]);
                MMA_H(oacc[2 * np + 1], aph, vh[2], vh[3]);
            }
        }
    }

    // ---- finalize: normalize, write fp16 to g_oh [B,T,D] ----
    lA += __shfl_xor_sync(0xffffffffu, lA, 1);
    lA += __shfl_xor_sync(0xffffffffu, lA, 2);
    lB += __shfl_xor_sync(0xffffffffu, lB, 1);
    lB += __shfl_xor_sync(0xffffffffu, lB, 2);
    float invA = 1.f / lA, invB = 1.f / lB;

    int rA = qs + wid * 16 + (lane >> 2);
    int c0 = 2 * (lane & 3);
    size_t baseA = ((size_t)(b * T_ + rA)) * D_ + head * HD;
    size_t baseB = baseA + (size_t)8 * D_;
#pragma unroll
    for (int nt = 0; nt < 16; nt++) {
        int cc = nt * 8 + c0;
        *(__half2*)(g_oh + baseA + cc) =
            __floats2half2_rn(oacc[nt][0] * invA, oacc[nt][1] * invA);
        *(__half2*)(g_oh + baseB + cc) =
            __floats2half2_rn(oacc[nt][2] * invB, oacc[nt][3] * invB);
    }
}

// ---------------------------------------------------------------------------
// Launch. Inputs: x, mask, cos, sin, w_attn, w_out. mask is tril -> causal.
// ---------------------------------------------------------------------------
extern "C" void kernel_launch(void* const* d_in, const int* in_sizes, int n_in,
                              void* d_out, int out_size)
{
    const float* x      = (const float*)d_in[0];
    const float* cosT   = (const float*)d_in[2];
    const float* sinT   = (const float*)d_in[3];
    const float* w_attn = (const float*)d_in[4];
    const float* w_out  = (const float*)d_in[5];
    float* out = (float*)d_out;

    cudaFuncSetAttribute(gemm1<0>, cudaFuncAttributeMaxDynamicSharedMemorySize, Q_SMEM);
    cudaFuncSetAttribute(gemm1<1>, cudaFuncAttributeMaxDynamicSharedMemorySize, Q_SMEM);
    cudaFuncSetAttribute(attn_mma, cudaFuncAttributeMaxDynamicSharedMemorySize,
                         AT_SMEM_BYTES);

    // Preprocessing: fp32 -> fp16, layout preserved (no transpose)
    __half* d_xh; cudaGetSymbolAddress((void**)&d_xh, g_x_hi);
    __half* d_wa; cudaGetSymbolAddress((void**)&d_wa, g_wa_h);
    __half* d_wo; cudaGetSymbolAddress((void**)&d_wo, g_wo_h);
    conv_half<<<(B_ * T_ * D_ / 4) / 256, 256>>>(x, d_xh);
    conv_half<<<(3 * D_ * D_ / 4) / 256, 256>>>(w_attn, d_wa);
    conv_half<<<(D_ * D_ / 4) / 256, 256>>>(w_out, d_wo);

    // QKV projection (1-term fp16, BK=64, W K-major via ldsm.trans)
    gemm1<0><<<dim3(96, 32), 128, Q_SMEM>>>(cosT, sinT, nullptr);

    // fp16 tensor-core flash attention (1-term QK, 1-term PV)
    attn_mma<<<dim3(32, NH, B_), 128, AT_SMEM_BYTES>>>();

    // Output projection (1-term fp16)
    gemm1<1><<<dim3(32, 32), 128, Q_SMEM>>>(cosT, sinT, out);
}

// round 14
// speedup vs baseline: 9.6090x; 1.0092x over previous
#include <cuda_runtime.h>
#include <cuda_fp16.h>
#include <cstdint>

// Problem constants
#define B_   2
#define T_   2048
#define D_   2048
#define NH   16
#define HD   128
#define FR   64
#define KTOT 2048
#define QK_SCALE 0.08838834764831845f   // 1/sqrt(128)

// ---------------------------------------------------------------------------
// Device-global scratch (allocation-free, graph-capture safe)
// ---------------------------------------------------------------------------
__device__ __half g_x_hi[(size_t)B_ * T_ * D_];          // x as fp16
__device__ __half g_oh[(size_t)B_ * T_ * D_];            // attn out (fp16)
__device__ __half g_wa_h[(size_t)3 * D_ * D_];           // w_attn fp16 [2048][6144]
__device__ __half g_wo_h[(size_t)D_ * D_];               // w_out fp16  [2048][2048]
// Q/K/V single fp16 (K,V RoPE applied; Q unscaled), [B,N,T,H]
__device__ __half g_qh[(size_t)B_ * NH * T_ * HD];
__device__ __half g_kh[(size_t)B_ * NH * T_ * HD];
__device__ __half g_vh[(size_t)B_ * NH * T_ * HD];

__device__ __forceinline__ uint32_t smem_u32(const void* p) {
    uint32_t a;
    asm("{ .reg .u64 t; cvta.to.shared.u64 t, %1; cvt.u32.u64 %0, t; }"
        : "=r"(a) : "l"(p));
    return a;
}
__device__ __forceinline__ void ldsm4(uint32_t& r0, uint32_t& r1, uint32_t& r2,
                                      uint32_t& r3, uint32_t addr) {
    asm volatile("ldmatrix.sync.aligned.m8n8.x4.shared.b16 {%0,%1,%2,%3}, [%4];"
                 : "=r"(r0), "=r"(r1), "=r"(r2), "=r"(r3) : "r"(addr));
}
__device__ __forceinline__ void ldsm4t(uint32_t& r0, uint32_t& r1, uint32_t& r2,
                                       uint32_t& r3, uint32_t addr) {
    asm volatile("ldmatrix.sync.aligned.m8n8.x4.trans.shared.b16 {%0,%1,%2,%3}, [%4];"
                 : "=r"(r0), "=r"(r1), "=r"(r2), "=r"(r3) : "r"(addr));
}
#define MMA_H(d, a, b0, b1)                                                    \
    asm volatile("mma.sync.aligned.m16n8k16.row.col.f32.f16.f16.f32 "          \
                 "{%0,%1,%2,%3},{%4,%5,%6,%7},{%8,%9},{%0,%1,%2,%3};"          \
                 : "+f"((d)[0]), "+f"((d)[1]), "+f"((d)[2]), "+f"((d)[3])      \
                 : "r"((a)[0]), "r"((a)[1]), "r"((a)[2]), "r"((a)[3]),         \
                   "r"(b0), "r"(b1))

__device__ __forceinline__ void cpa16(uint32_t dst, const void* src) {
    asm volatile("cp.async.cg.shared.global [%0], [%1], 16;"
                 :: "r"(dst), "l"(src));
}
#define CP_COMMIT() asm volatile("cp.async.commit_group;" ::: "memory")
#define CP_WAIT0()  asm volatile("cp.async.wait_group 0;" ::: "memory")
#define CP_WAIT1()  asm volatile("cp.async.wait_group 1;" ::: "memory")

// ---------------------------------------------------------------------------
// Fused fp32->fp16 conversion for x, w_attn, w_out (one launch)
// ---------------------------------------------------------------------------
#define NX4 ((size_t)B_ * T_ * D_ / 4)        // 2097152
#define NA4 ((size_t)3 * D_ * D_ / 4)         // 3145728
#define NO4 ((size_t)D_ * D_ / 4)             // 1048576

__global__ __launch_bounds__(256) void conv_all(const float* __restrict__ x,
                                                const float* __restrict__ wa,
                                                const float* __restrict__ wo)
{
    size_t i = (size_t)blockIdx.x * 256 + threadIdx.x;
    const float* src;
    __half* dst;
    size_t j;
    if (i < NX4)            { src = x;  dst = g_x_hi; j = i; }
    else if (i < NX4 + NA4) { src = wa; dst = g_wa_h; j = i - NX4; }
    else                    { src = wo; dst = g_wo_h; j = i - NX4 - NA4; }
    float4 f = ((const float4*)src)[j];
    ((__half2*)dst)[2 * j]     = __floats2half2_rn(f.x, f.y);
    ((__half2*)dst)[2 * j + 1] = __floats2half2_rn(f.z, f.w);
}

// ---------------------------------------------------------------------------
// 1-term fp16 GEMM, CTA tile 128x64, 4 warps (2m x 2n), warp tile 64x32,
// BK=64, 3-stage cp.async ring, register-level fragment double buffering.
// W kept K-major [K][N]; B-fragments via ldmatrix.trans.
// MODE 0 (QKV): A=g_x_hi, W=g_wa_h (N=6144); epilogue head split + RoPE(k,v).
// MODE 1 (out): A=g_oh,  W=g_wo_h (N=2048); plain fp32 store.
// ---------------------------------------------------------------------------
#define QSTRIDE 72
#define QA_ELE (128 * QSTRIDE)              // 9216 halves (A: 128 m x 64 k)
#define QW_ELE (64 * QSTRIDE)               // 4608 halves (W: 64 k x 64 n)
#define Q_STAGE_ELE (QA_ELE + QW_ELE)       // 13824 halves
#define Q_SMEM (3 * Q_STAGE_ELE * 2)        // 82944 bytes

template <int MODE>
__global__ __launch_bounds__(128, 2) void gemm1(
    const float* __restrict__ cosT, const float* __restrict__ sinT,
    float* __restrict__ Cout)
{
    extern __shared__ __half smem_h[];
    const int tid = threadIdx.x;
    const int wid = tid >> 5, lane = tid & 31;
    const int warp_m = wid & 1, warp_n = wid >> 1;
    const int m0 = (int)blockIdx.y << 7, n0 = (int)blockIdx.x << 6;
    const uint32_t sb = smem_u32(smem_h);

    const __half* Ag = MODE ? g_oh : g_x_hi;
    const __half* Wg = MODE ? g_wo_h : g_wa_h;
    const int WN = MODE ? D_ : 3 * D_;               // W row width (n)

    float acc[4][4][4];
#pragma unroll
    for (int i = 0; i < 4; i++)
#pragma unroll
        for (int j = 0; j < 4; j++)
#pragma unroll
            for (int k = 0; k < 4; k++) acc[i][j][k] = 0.f;

    const uint32_t a_lm = ((warp_m * 64 + (lane & 15)) * QSTRIDE + (lane >> 4) * 8) * 2;
    const uint32_t b_lm = (uint32_t)(QA_ELE +
        (lane & 15) * QSTRIDE + ((lane >> 4) << 3) + warp_n * 32) * 2;

    auto LOAD = [&](int stage, int kc) {
        int k0 = kc << 6;
        uint32_t sbs = sb + (uint32_t)stage * Q_STAGE_ELE * 2;
#pragma unroll
        for (int i = 0; i < 8; i++) {                // A: 1024 chunks
            int c = tid + (i << 7);
            int r = c >> 3, col = (c & 7) << 3;
            cpa16(sbs + (uint32_t)(r * QSTRIDE + col) * 2,
                  Ag + (size_t)(m0 + r) * KTOT + k0 + col);
        }
#pragma unroll
        for (int i = 0; i < 4; i++) {                // W: 512 chunks, K-major
            int c = tid + (i << 7);
            int r = c >> 3, col = (c & 7) << 3;      // r = k-row, col = n
            cpa16(sbs + (uint32_t)QA_ELE * 2 + (uint32_t)(r * QSTRIDE + col) * 2,
                  Wg + (size_t)(k0 + r) * WN + n0 + col);
        }
        CP_COMMIT();
    };

    auto COMPUTE = [&](int st) {
        uint32_t stb = sb + (uint32_t)st * Q_STAGE_ELE * 2;
        uint32_t ah[2][4][4], bh[2][2][4];
        // prologue: fragments for ks = 0
#pragma unroll
        for (int mt = 0; mt < 4; mt++)
            ldsm4(ah[0][mt][0], ah[0][mt][1], ah[0][mt][2], ah[0][mt][3],
                  stb + a_lm + (mt * 16 * QSTRIDE) * 2);
#pragma unroll
        for (int nn = 0; nn < 2; nn++)
            ldsm4t(bh[0][nn][0], bh[0][nn][1], bh[0][nn][2], bh[0][nn][3],
                   stb + b_lm + nn * 32);
#pragma unroll
        for (int ks = 0; ks < 4; ks++) {
            const int cur = ks & 1, nxt = cur ^ 1;
            if (ks < 3) {                            // prefetch ks+1 fragments
#pragma unroll
                for (int mt = 0; mt < 4; mt++)
                    ldsm4(ah[nxt][mt][0], ah[nxt][mt][1],
                          ah[nxt][mt][2], ah[nxt][mt][3],
                          stb + a_lm + (mt * 16 * QSTRIDE + (ks + 1) * 16) * 2);
#pragma unroll
                for (int nn = 0; nn < 2; nn++)
                    ldsm4t(bh[nxt][nn][0], bh[nxt][nn][1],
                           bh[nxt][nn][2], bh[nxt][nn][3],
                           stb + b_lm + ((ks + 1) * 16 * QSTRIDE) * 2 + nn * 32);
            }
#pragma unroll
            for (int mt = 0; mt < 4; mt++)
#pragma unroll
                for (int nn = 0; nn < 2; nn++) {
                    MMA_H(acc[mt][nn * 2],     ah[cur][mt],
                          bh[cur][nn][0], bh[cur][nn][1]);
                    MMA_H(acc[mt][nn * 2 + 1], ah[cur][mt],
                          bh[cur][nn][2], bh[cur][nn][3]);
                }
        }
    };

    const int NI = KTOT / 64;            // 32
    LOAD(0, 0);
    LOAD(1, 1);
#pragma unroll 1
    for (int it = 0; it < NI; it++) {
        CP_WAIT1();
        __syncthreads();
        if (it + 2 < NI) LOAD((it + 2) % 3, it + 2);
        else CP_COMMIT();                // keep group count uniform
        COMPUTE(it % 3);
    }

    // ---------------- epilogue ----------------
    const int rb = lane >> 2;
    const int cb = (lane & 3) * 2;
    if (MODE == 0) {
        int sec = n0 >> 11;              // 0=q 1=k 2=v
        int head = (n0 >> 7) & 15;
        __half* dst = (sec == 0) ? g_qh : (sec == 1 ? g_kh : g_vh);
#pragma unroll
        for (int mt = 0; mt < 4; mt++)
#pragma unroll
            for (int hf = 0; hf < 2; hf++) {
                int m = m0 + warp_m * 64 + mt * 16 + hf * 8 + rb;
                int b = m >> 11, t = m & 2047;
                size_t rowbase = ((size_t)(b * NH + head) * T_ + t) * HD;
#pragma unroll
                for (int j = 0; j < 4; j++) {
                    int n = n0 + warp_n * 32 + j * 8 + cb;
                    int hh = n & 127;
                    float v0 = acc[mt][j][hf * 2];
                    float v1 = acc[mt][j][hf * 2 + 1];
                    if (sec) {
                        float cz = cosT[t * FR + (hh >> 1)];
                        float sz = sinT[t * FR + (hh >> 1)];
                        float r0 = v0 * cz - v1 * sz;
                        float r1 = v0 * sz + v1 * cz;
                        v0 = r0; v1 = r1;
                    }
                    *(__half2*)(dst + rowbase + hh) = __floats2half2_rn(v0, v1);
                }
            }
    } else {
#pragma unroll
        for (int mt = 0; mt < 4; mt++)
#pragma unroll
            for (int hf = 0; hf < 2; hf++) {
                int m = m0 + warp_m * 64 + mt * 16 + hf * 8 + rb;
#pragma unroll
                for (int j = 0; j < 4; j++) {
                    int n = n0 + warp_n * 32 + j * 8 + cb;
                    *(float2*)&Cout[(size_t)m * D_ + n] =
                        make_float2(acc[mt][j][hf * 2], acc[mt][j][hf * 2 + 1]);
                }
            }
    }
}

// ---------------------------------------------------------------------------
// fp16 tensor-core causal flash attention (unchanged from R12).
// QK: S = qh . kh   (1 MMA; scale on scores).
// PV: O = ph . vh   (1 MMA; P fp16).
// SMEM: Qh Kh Vh, each [64][136] fp16 = 52224 B -> up to 4 CTAs/SM.
// ---------------------------------------------------------------------------
#define AT_STRIDE 136
#define AT_TILE   (64 * AT_STRIDE)
#define AT_SMEM_BYTES (3 * AT_TILE * 2)

__global__ __launch_bounds__(128) void attn_mma()
{
    extern __shared__ __half sm_at[];
    const int tid = threadIdx.x, wid = tid >> 5, lane = tid & 31;
    const int qt = 31 - (int)blockIdx.x;
    const int qs = qt << 6;
    const int head = blockIdx.y, b = blockIdx.z;
    const size_t hbase = (size_t)(b * NH + head) * T_ * HD;
    const uint32_t sb = smem_u32(sm_at);

    const uint32_t QH = 0, KH = AT_TILE, VH = 2 * AT_TILE;

#pragma unroll
    for (int i = 0; i < 8; i++) {
        int c = tid + i * 128;
        int r = c >> 4, col = (c & 15) << 3;
        cpa16(sb + QH * 2 + (uint32_t)(r * AT_STRIDE + col) * 2,
              g_qh + hbase + (size_t)(qs + r) * HD + col);
    }

    float oacc[16][4];
#pragma unroll
    for (int i = 0; i < 16; i++)
#pragma unroll
        for (int j = 0; j < 4; j++) oacc[i][j] = 0.f;
    float mA = -1e30f, mB = -1e30f, lA = 0.f, lB = 0.f;

    const uint32_t qbase = sb + QH * 2 +
        ((wid * 16 + (lane & 15)) * AT_STRIDE + ((lane >> 4) << 3)) * 2;
    const uint32_t kbase = sb + KH * 2 +
        (((lane & 7) + ((lane >> 4) << 3)) * AT_STRIDE + (((lane >> 3) & 1) << 3)) * 2;
    const uint32_t vbase = sb + VH * 2 +
        ((lane & 15) * AT_STRIDE + ((lane >> 4) << 3)) * 2;

#pragma unroll 1
    for (int jt = 0; jt <= qt; jt++) {
        const int j0 = jt << 6;
        if (jt) __syncthreads();
#pragma unroll
        for (int i = 0; i < 8; i++) {
            int c = tid + i * 128;
            int r = c >> 4, col = (c & 15) << 3;
            size_t g = hbase + (size_t)(j0 + r) * HD + col;
            uint32_t so = (uint32_t)(r * AT_STRIDE + col) * 2;
            cpa16(sb + KH * 2 + so, g_kh + g);
            cpa16(sb + VH * 2 + so, g_vh + g);
        }
        CP_COMMIT();
        CP_WAIT0();
        __syncthreads();

        float sacc[8][4];
#pragma unroll
        for (int i = 0; i < 8; i++)
#pragma unroll
            for (int j = 0; j < 4; j++) sacc[i][j] = 0.f;

#pragma unroll
        for (int ks = 0; ks < 8; ks++) {
            uint32_t qh[4];
            ldsm4(qh[0], qh[1], qh[2], qh[3], qbase + ks * 32);
#pragma unroll
            for (int np = 0; np < 4; np++) {
                uint32_t kh[4];
                ldsm4(kh[0], kh[1], kh[2], kh[3],
                      kbase + (np * 16 * AT_STRIDE) * 2 + ks * 32);
                MMA_H(sacc[2 * np],     qh, kh[0], kh[1]);
                MMA_H(sacc[2 * np + 1], qh, kh[2], kh[3]);
            }
        }

#pragma unroll
        for (int nt = 0; nt < 8; nt++)
#pragma unroll
            for (int j = 0; j < 4; j++) sacc[nt][j] *= QK_SCALE;
        if (jt == qt) {
            int rA = wid * 16 + (lane >> 2);
            int c0 = 2 * (lane & 3);
#pragma unroll
            for (int nt = 0; nt < 8; nt++) {
                int cc = nt * 8 + c0;
                if (cc > rA)         sacc[nt][0] = -1e30f;
                if (cc + 1 > rA)     sacc[nt][1] = -1e30f;
                if (cc > rA + 8)     sacc[nt][2] = -1e30f;
                if (cc + 1 > rA + 8) sacc[nt][3] = -1e30f;
            }
        }

        float tmA = -1e30f, tmB = -1e30f;
#pragma unroll
        for (int nt = 0; nt < 8; nt++) {
            tmA = fmaxf(tmA, fmaxf(sacc[nt][0], sacc[nt][1]));
            tmB = fmaxf(tmB, fmaxf(sacc[nt][2], sacc[nt][3]));
        }
        tmA = fmaxf(tmA, __shfl_xor_sync(0xffffffffu, tmA, 1));
        tmA = fmaxf(tmA, __shfl_xor_sync(0xffffffffu, tmA, 2));
        tmB = fmaxf(tmB, __shfl_xor_sync(0xffffffffu, tmB, 1));
        tmB = fmaxf(tmB, __shfl_xor_sync(0xffffffffu, tmB, 2));
        float mnA = fmaxf(mA, tmA), mnB = fmaxf(mB, tmB);
        float aAl = __expf(mA - mnA), aBl = __expf(mB - mnB);
        mA = mnA; mB = mnB;

        float psA = 0.f, psB = 0.f;
        uint32_t ph[8][2];
#pragma unroll
        for (int nt = 0; nt < 8; nt++) {
            float p0 = __expf(sacc[nt][0] - mA);
            float p1 = __expf(sacc[nt][1] - mA);
            float p2 = __expf(sacc[nt][2] - mB);
            float p3 = __expf(sacc[nt][3] - mB);
            psA += p0 + p1;
            psB += p2 + p3;
            __half2 hA2 = __floats2half2_rn(p0, p1);
            __half2 hB2 = __floats2half2_rn(p2, p3);
            ph[nt][0] = *(uint32_t*)&hA2;
            ph[nt][1] = *(uint32_t*)&hB2;
        }
        lA = lA * aAl + psA;
        lB = lB * aBl + psB;
#pragma unroll
        for (int nt = 0; nt < 16; nt++) {
            oacc[nt][0] *= aAl;
            oacc[nt][1] *= aAl;
            oacc[nt][2] *= aBl;
            oacc[nt][3] *= aBl;
        }

#pragma unroll
        for (int ks = 0; ks < 4; ks++) {
            uint32_t aph[4] = {ph[2 * ks][0], ph[2 * ks][1],
                               ph[2 * ks + 1][0], ph[2 * ks + 1][1]};
#pragma unroll
            for (int np = 0; np < 8; np++) {
                uint32_t vh[4];
                ldsm4t(vh[0], vh[1], vh[2], vh[3],
                       vbase + (ks * 16 * AT_STRIDE) * 2 + np * 32);
                MMA_H(oacc[2 * np],     aph, vh[0], vh[1]);
                MMA_H(oacc[2 * np + 1], aph, vh[2], vh[3]);
            }
        }
    }

    lA += __shfl_xor_sync(0xffffffffu, lA, 1);
    lA += __shfl_xor_sync(0xffffffffu, lA, 2);
    lB += __shfl_xor_sync(0xffffffffu, lB, 1);
    lB += __shfl_xor_sync(0xffffffffu, lB, 2);
    float invA = 1.f / lA, invB = 1.f / lB;

    int rA = qs + wid * 16 + (lane >> 2);
    int c0 = 2 * (lane & 3);
    size_t baseA = ((size_t)(b * T_ + rA)) * D_ + head * HD;
    size_t baseB = baseA + (size_t)8 * D_;
#pragma unroll
    for (int nt = 0; nt < 16; nt++) {
        int cc = nt * 8 + c0;
        *(__half2*)(g_oh + baseA + cc) =
            __floats2half2_rn(oacc[nt][0] * invA, oacc[nt][1] * invA);
        *(__half2*)(g_oh + baseB + cc) =
            __floats2half2_rn(oacc[nt][2] * invB, oacc[nt][3] * invB);
    }
}

// ---------------------------------------------------------------------------
// Launch. Inputs: x, mask, cos, sin, w_attn, w_out. mask is tril -> causal.
// ---------------------------------------------------------------------------
extern "C" void kernel_launch(void* const* d_in, const int* in_sizes, int n_in,
                              void* d_out, int out_size)
{
    const float* x      = (const float*)d_in[0];
    const float* cosT   = (const float*)d_in[2];
    const float* sinT   = (const float*)d_in[3];
    const float* w_attn = (const float*)d_in[4];
    const float* w_out  = (const float*)d_in[5];
    float* out = (float*)d_out;

    cudaFuncSetAttribute(gemm1<0>, cudaFuncAttributeMaxDynamicSharedMemorySize, Q_SMEM);
    cudaFuncSetAttribute(gemm1<1>, cudaFuncAttributeMaxDynamicSharedMemorySize, Q_SMEM);
    cudaFuncSetAttribute(attn_mma, cudaFuncAttributeMaxDynamicSharedMemorySize,
                         AT_SMEM_BYTES);

    // Preprocessing: fp32 -> fp16 for x + both weights in ONE launch
    conv_all<<<(unsigned)((NX4 + NA4 + NO4) / 256), 256>>>(x, w_attn, w_out);

    // QKV projection (1-term fp16, BK=64, frag double-buffered)
    gemm1<0><<<dim3(96, 32), 128, Q_SMEM>>>(cosT, sinT, nullptr);

    // fp16 tensor-core flash attention (1-term QK, 1-term PV)
    attn_mma<<<dim3(32, NH, B_), 128, AT_SMEM_BYTES>>>();

    // Output projection (1-term fp16)
    gemm1<1><<<dim3(32, 32), 128, Q_SMEM>>>(cosT, sinT, out);
}

// round 15
// speedup vs baseline: 9.7459x; 1.0142x over previous
#include <cuda_runtime.h>
#include <cuda_fp16.h>
#include <cstdint>

// Problem constants
#define B_   2
#define T_   2048
#define D_   2048
#define NH   16
#define HD   128
#define FR   64
#define KTOT 2048
#define QK_SCALE 0.08838834764831845f   // 1/sqrt(128)

// ---------------------------------------------------------------------------
// Device-global scratch (allocation-free, graph-capture safe)
// ---------------------------------------------------------------------------
__device__ __half g_x_hi[(size_t)B_ * T_ * D_];          // x as fp16
__device__ __half g_oh[(size_t)B_ * T_ * D_];            // attn out (fp16)
__device__ __half g_wa_h[(size_t)3 * D_ * D_];           // w_attn fp16 [2048][6144]
__device__ __half g_wo_h[(size_t)D_ * D_];               // w_out fp16  [2048][2048]
// Q/K/V single fp16 (K,V RoPE applied; Q unscaled), [B,N,T,H]
__device__ __half g_qh[(size_t)B_ * NH * T_ * HD];
__device__ __half g_kh[(size_t)B_ * NH * T_ * HD];
__device__ __half g_vh[(size_t)B_ * NH * T_ * HD];

__device__ __forceinline__ uint32_t smem_u32(const void* p) {
    uint32_t a;
    asm("{ .reg .u64 t; cvta.to.shared.u64 t, %1; cvt.u32.u64 %0, t; }"
        : "=r"(a) : "l"(p));
    return a;
}
__device__ __forceinline__ void ldsm4(uint32_t& r0, uint32_t& r1, uint32_t& r2,
                                      uint32_t& r3, uint32_t addr) {
    asm volatile("ldmatrix.sync.aligned.m8n8.x4.shared.b16 {%0,%1,%2,%3}, [%4];"
                 : "=r"(r0), "=r"(r1), "=r"(r2), "=r"(r3) : "r"(addr));
}
__device__ __forceinline__ void ldsm4t(uint32_t& r0, uint32_t& r1, uint32_t& r2,
                                       uint32_t& r3, uint32_t addr) {
    asm volatile("ldmatrix.sync.aligned.m8n8.x4.trans.shared.b16 {%0,%1,%2,%3}, [%4];"
                 : "=r"(r0), "=r"(r1), "=r"(r2), "=r"(r3) : "r"(addr));
}
#define MMA_H(d, a, b0, b1)                                                    \
    asm volatile("mma.sync.aligned.m16n8k16.row.col.f32.f16.f16.f32 "          \
                 "{%0,%1,%2,%3},{%4,%5,%6,%7},{%8,%9},{%0,%1,%2,%3};"          \
                 : "+f"((d)[0]), "+f"((d)[1]), "+f"((d)[2]), "+f"((d)[3])      \
                 : "r"((a)[0]), "r"((a)[1]), "r"((a)[2]), "r"((a)[3]),         \
                   "r"(b0), "r"(b1))

__device__ __forceinline__ void cpa16(uint32_t dst, const void* src) {
    asm volatile("cp.async.cg.shared.global [%0], [%1], 16;"
                 :: "r"(dst), "l"(src));
}
#define CP_COMMIT() asm volatile("cp.async.commit_group;" ::: "memory")
#define CP_WAIT0()  asm volatile("cp.async.wait_group 0;" ::: "memory")
#define CP_WAIT1()  asm volatile("cp.async.wait_group 1;" ::: "memory")

// ---------------------------------------------------------------------------
// Fused fp32->fp16 conversion for x, w_attn, w_out (one launch)
// ---------------------------------------------------------------------------
#define NX4 ((size_t)B_ * T_ * D_ / 4)        // 2097152
#define NA4 ((size_t)3 * D_ * D_ / 4)         // 3145728
#define NO4 ((size_t)D_ * D_ / 4)             // 1048576

__global__ __launch_bounds__(256) void conv_all(const float* __restrict__ x,
                                                const float* __restrict__ wa,
                                                const float* __restrict__ wo)
{
    size_t i = (size_t)blockIdx.x * 256 + threadIdx.x;
    const float* src;
    __half* dst;
    size_t j;
    if (i < NX4)            { src = x;  dst = g_x_hi; j = i; }
    else if (i < NX4 + NA4) { src = wa; dst = g_wa_h; j = i - NX4; }
    else                    { src = wo; dst = g_wo_h; j = i - NX4 - NA4; }
    float4 f = ((const float4*)src)[j];
    ((__half2*)dst)[2 * j]     = __floats2half2_rn(f.x, f.y);
    ((__half2*)dst)[2 * j + 1] = __floats2half2_rn(f.z, f.w);
}

// ---------------------------------------------------------------------------
// 1-term fp16 GEMM, CTA tile 128x64, 4 warps (2m x 2n), warp tile 64x32,
// BK=64, 3-stage cp.async ring, register-level fragment double buffering.
// W kept K-major [K][N]; B-fragments via ldmatrix.trans.
// MODE 0 (QKV): A=g_x_hi, W=g_wa_h (N=6144); epilogue head split + RoPE(k,v).
// MODE 1 (out): A=g_oh,  W=g_wo_h (N=2048); plain fp32 store.
// ---------------------------------------------------------------------------
#define QSTRIDE 72
#define QA_ELE (128 * QSTRIDE)              // 9216 halves (A: 128 m x 64 k)
#define QW_ELE (64 * QSTRIDE)               // 4608 halves (W: 64 k x 64 n)
#define Q_STAGE_ELE (QA_ELE + QW_ELE)       // 13824 halves
#define Q_SMEM (3 * Q_STAGE_ELE * 2)        // 82944 bytes

template <int MODE>
__global__ __launch_bounds__(128, 2) void gemm1(
    const float* __restrict__ cosT, const float* __restrict__ sinT,
    float* __restrict__ Cout)
{
    extern __shared__ __half smem_h[];
    const int tid = threadIdx.x;
    const int wid = tid >> 5, lane = tid & 31;
    const int warp_m = wid & 1, warp_n = wid >> 1;
    const int m0 = (int)blockIdx.y << 7, n0 = (int)blockIdx.x << 6;
    const uint32_t sb = smem_u32(smem_h);

    const __half* Ag = MODE ? g_oh : g_x_hi;
    const __half* Wg = MODE ? g_wo_h : g_wa_h;
    const int WN = MODE ? D_ : 3 * D_;               // W row width (n)

    float acc[4][4][4];
#pragma unroll
    for (int i = 0; i < 4; i++)
#pragma unroll
        for (int j = 0; j < 4; j++)
#pragma unroll
            for (int k = 0; k < 4; k++) acc[i][j][k] = 0.f;

    const uint32_t a_lm = ((warp_m * 64 + (lane & 15)) * QSTRIDE + (lane >> 4) * 8) * 2;
    const uint32_t b_lm = (uint32_t)(QA_ELE +
        (lane & 15) * QSTRIDE + ((lane >> 4) << 3) + warp_n * 32) * 2;

    auto LOAD = [&](int stage, int kc) {
        int k0 = kc << 6;
        uint32_t sbs = sb + (uint32_t)stage * Q_STAGE_ELE * 2;
#pragma unroll
        for (int i = 0; i < 8; i++) {                // A: 1024 chunks
            int c = tid + (i << 7);
            int r = c >> 3, col = (c & 7) << 3;
            cpa16(sbs + (uint32_t)(r * QSTRIDE + col) * 2,
                  Ag + (size_t)(m0 + r) * KTOT + k0 + col);
        }
#pragma unroll
        for (int i = 0; i < 4; i++) {                // W: 512 chunks, K-major
            int c = tid + (i << 7);
            int r = c >> 3, col = (c & 7) << 3;      // r = k-row, col = n
            cpa16(sbs + (uint32_t)QA_ELE * 2 + (uint32_t)(r * QSTRIDE + col) * 2,
                  Wg + (size_t)(k0 + r) * WN + n0 + col);
        }
        CP_COMMIT();
    };

    auto COMPUTE = [&](int st) {
        uint32_t stb = sb + (uint32_t)st * Q_STAGE_ELE * 2;
        uint32_t ah[2][4][4], bh[2][2][4];
        // prologue: fragments for ks = 0
#pragma unroll
        for (int mt = 0; mt < 4; mt++)
            ldsm4(ah[0][mt][0], ah[0][mt][1], ah[0][mt][2], ah[0][mt][3],
                  stb + a_lm + (mt * 16 * QSTRIDE) * 2);
#pragma unroll
        for (int nn = 0; nn < 2; nn++)
            ldsm4t(bh[0][nn][0], bh[0][nn][1], bh[0][nn][2], bh[0][nn][3],
                   stb + b_lm + nn * 32);
#pragma unroll
        for (int ks = 0; ks < 4; ks++) {
            const int cur = ks & 1, nxt = cur ^ 1;
            if (ks < 3) {                            // prefetch ks+1 fragments
#pragma unroll
                for (int mt = 0; mt < 4; mt++)
                    ldsm4(ah[nxt][mt][0], ah[nxt][mt][1],
                          ah[nxt][mt][2], ah[nxt][mt][3],
                          stb + a_lm + (mt * 16 * QSTRIDE + (ks + 1) * 16) * 2);
#pragma unroll
                for (int nn = 0; nn < 2; nn++)
                    ldsm4t(bh[nxt][nn][0], bh[nxt][nn][1],
                           bh[nxt][nn][2], bh[nxt][nn][3],
                           stb + b_lm + ((ks + 1) * 16 * QSTRIDE) * 2 + nn * 32);
            }
#pragma unroll
            for (int mt = 0; mt < 4; mt++)
#pragma unroll
                for (int nn = 0; nn < 2; nn++) {
                    MMA_H(acc[mt][nn * 2],     ah[cur][mt],
                          bh[cur][nn][0], bh[cur][nn][1]);
                    MMA_H(acc[mt][nn * 2 + 1], ah[cur][mt],
                          bh[cur][nn][2], bh[cur][nn][3]);
                }
        }
    };

    const int NI = KTOT / 64;            // 32
    LOAD(0, 0);
    LOAD(1, 1);
#pragma unroll 1
    for (int it = 0; it < NI; it++) {
        CP_WAIT1();
        __syncthreads();
        if (it + 2 < NI) LOAD((it + 2) % 3, it + 2);
        else CP_COMMIT();                // keep group count uniform
        COMPUTE(it % 3);
    }

    // ---------------- epilogue ----------------
    const int rb = lane >> 2;
    const int cb = (lane & 3) * 2;
    if (MODE == 0) {
        int sec = n0 >> 11;              // 0=q 1=k 2=v
        int head = (n0 >> 7) & 15;
        __half* dst = (sec == 0) ? g_qh : (sec == 1 ? g_kh : g_vh);
#pragma unroll
        for (int mt = 0; mt < 4; mt++)
#pragma unroll
            for (int hf = 0; hf < 2; hf++) {
                int m = m0 + warp_m * 64 + mt * 16 + hf * 8 + rb;
                int b = m >> 11, t = m & 2047;
                size_t rowbase = ((size_t)(b * NH + head) * T_ + t) * HD;
#pragma unroll
                for (int j = 0; j < 4; j++) {
                    int n = n0 + warp_n * 32 + j * 8 + cb;
                    int hh = n & 127;
                    float v0 = acc[mt][j][hf * 2];
                    float v1 = acc[mt][j][hf * 2 + 1];
                    if (sec) {
                        float cz = cosT[t * FR + (hh >> 1)];
                        float sz = sinT[t * FR + (hh >> 1)];
                        float r0 = v0 * cz - v1 * sz;
                        float r1 = v0 * sz + v1 * cz;
                        v0 = r0; v1 = r1;
                    }
                    *(__half2*)(dst + rowbase + hh) = __floats2half2_rn(v0, v1);
                }
            }
    } else {
#pragma unroll
        for (int mt = 0; mt < 4; mt++)
#pragma unroll
            for (int hf = 0; hf < 2; hf++) {
                int m = m0 + warp_m * 64 + mt * 16 + hf * 8 + rb;
#pragma unroll
                for (int j = 0; j < 4; j++) {
                    int n = n0 + warp_n * 32 + j * 8 + cb;
                    *(float2*)&Cout[(size_t)m * D_ + n] =
                        make_float2(acc[mt][j][hf * 2], acc[mt][j][hf * 2 + 1]);
                }
            }
    }
}

// ---------------------------------------------------------------------------
// fp16 tensor-core causal flash attention, K/V double-buffered.
// QK: S = qh . kh   (1 MMA; scale on scores).
// PV: O = ph . vh   (1 MMA; P fp16).
// SMEM: Q + 2x(K,V), each [64][136] fp16 = 87040 B -> 2 CTAs/SM.
// ---------------------------------------------------------------------------
#define AT_STRIDE 136
#define AT_TILE   (64 * AT_STRIDE)
#define AT_SMEM_BYTES (5 * AT_TILE * 2)

__global__ __launch_bounds__(128, 2) void attn_mma()
{
    extern __shared__ __half sm_at[];
    const int tid = threadIdx.x, wid = tid >> 5, lane = tid & 31;
    const int qt = 31 - (int)blockIdx.x;
    const int qs = qt << 6;
    const int head = blockIdx.y, b = blockIdx.z;
    const size_t hbase = (size_t)(b * NH + head) * T_ * HD;
    const uint32_t sb = smem_u32(sm_at);

    // buffers: Q at 0; buf p: K at (1+2p)*AT_TILE, V at (2+2p)*AT_TILE
    auto kv_load = [&](int jt, int p) {
        const int j0 = jt << 6;
        uint32_t kb = (uint32_t)(1 + 2 * p) * AT_TILE * 2;
        uint32_t vb = (uint32_t)(2 + 2 * p) * AT_TILE * 2;
#pragma unroll
        for (int i = 0; i < 8; i++) {
            int c = tid + i * 128;
            int r = c >> 4, col = (c & 15) << 3;
            size_t g = hbase + (size_t)(j0 + r) * HD + col;
            uint32_t so = (uint32_t)(r * AT_STRIDE + col) * 2;
            cpa16(sb + kb + so, g_kh + g);
            cpa16(sb + vb + so, g_vh + g);
        }
    };

    // prologue: Q + KV tile 0 in one group
#pragma unroll
    for (int i = 0; i < 8; i++) {
        int c = tid + i * 128;
        int r = c >> 4, col = (c & 15) << 3;
        cpa16(sb + (uint32_t)(r * AT_STRIDE + col) * 2,
              g_qh + hbase + (size_t)(qs + r) * HD + col);
    }
    kv_load(0, 0);
    CP_COMMIT();

    float oacc[16][4];
#pragma unroll
    for (int i = 0; i < 16; i++)
#pragma unroll
        for (int j = 0; j < 4; j++) oacc[i][j] = 0.f;
    float mA = -1e30f, mB = -1e30f, lA = 0.f, lB = 0.f;

    const uint32_t qbase = sb +
        ((wid * 16 + (lane & 15)) * AT_STRIDE + ((lane >> 4) << 3)) * 2;
    const uint32_t k_lm =
        (((lane & 7) + ((lane >> 4) << 3)) * AT_STRIDE + (((lane >> 3) & 1) << 3)) * 2;
    const uint32_t v_lm =
        ((lane & 15) * AT_STRIDE + ((lane >> 4) << 3)) * 2;

#pragma unroll 1
    for (int jt = 0; jt <= qt; jt++) {
        const int p = jt & 1;
        // issue next tile's loads into the other buffer, then wait for this one
        if (jt < qt) kv_load(jt + 1, p ^ 1);
        CP_COMMIT();                     // uniform group count
        CP_WAIT1();                      // tile jt (and Q) resident
        __syncthreads();

        const uint32_t kbase = sb + (uint32_t)(1 + 2 * p) * AT_TILE * 2 + k_lm;
        const uint32_t vbase = sb + (uint32_t)(2 + 2 * p) * AT_TILE * 2 + v_lm;

        // ---- S = Q K^T (1-term fp16) ----
        float sacc[8][4];
#pragma unroll
        for (int i = 0; i < 8; i++)
#pragma unroll
            for (int j = 0; j < 4; j++) sacc[i][j] = 0.f;

#pragma unroll
        for (int ks = 0; ks < 8; ks++) {
            uint32_t qh[4];
            ldsm4(qh[0], qh[1], qh[2], qh[3], qbase + ks * 32);
#pragma unroll
            for (int np = 0; np < 4; np++) {
                uint32_t kh[4];
                ldsm4(kh[0], kh[1], kh[2], kh[3],
                      kbase + (np * 16 * AT_STRIDE) * 2 + ks * 32);
                MMA_H(sacc[2 * np],     qh, kh[0], kh[1]);
                MMA_H(sacc[2 * np + 1], qh, kh[2], kh[3]);
            }
        }

        // ---- scale + causal mask ----
#pragma unroll
        for (int nt = 0; nt < 8; nt++)
#pragma unroll
            for (int j = 0; j < 4; j++) sacc[nt][j] *= QK_SCALE;
        if (jt == qt) {
            int rA = wid * 16 + (lane >> 2);
            int c0 = 2 * (lane & 3);
#pragma unroll
            for (int nt = 0; nt < 8; nt++) {
                int cc = nt * 8 + c0;
                if (cc > rA)         sacc[nt][0] = -1e30f;
                if (cc + 1 > rA)     sacc[nt][1] = -1e30f;
                if (cc > rA + 8)     sacc[nt][2] = -1e30f;
                if (cc + 1 > rA + 8) sacc[nt][3] = -1e30f;
            }
        }

        // ---- online softmax ----
        float tmA = -1e30f, tmB = -1e30f;
#pragma unroll
        for (int nt = 0; nt < 8; nt++) {
            tmA = fmaxf(tmA, fmaxf(sacc[nt][0], sacc[nt][1]));
            tmB = fmaxf(tmB, fmaxf(sacc[nt][2], sacc[nt][3]));
        }
        tmA = fmaxf(tmA, __shfl_xor_sync(0xffffffffu, tmA, 1));
        tmA = fmaxf(tmA, __shfl_xor_sync(0xffffffffu, tmA, 2));
        tmB = fmaxf(tmB, __shfl_xor_sync(0xffffffffu, tmB, 1));
        tmB = fmaxf(tmB, __shfl_xor_sync(0xffffffffu, tmB, 2));
        float mnA = fmaxf(mA, tmA), mnB = fmaxf(mB, tmB);
        float aAl = __expf(mA - mnA), aBl = __expf(mB - mnB);
        mA = mnA; mB = mnB;

        float psA = 0.f, psB = 0.f;
        uint32_t ph[8][2];
#pragma unroll
        for (int nt = 0; nt < 8; nt++) {
            float p0 = __expf(sacc[nt][0] - mA);
            float p1 = __expf(sacc[nt][1] - mA);
            float p2 = __expf(sacc[nt][2] - mB);
            float p3 = __expf(sacc[nt][3] - mB);
            psA += p0 + p1;
            psB += p2 + p3;
            __half2 hA2 = __floats2half2_rn(p0, p1);
            __half2 hB2 = __floats2half2_rn(p2, p3);
            ph[nt][0] = *(uint32_t*)&hA2;
            ph[nt][1] = *(uint32_t*)&hB2;
        }
        lA = lA * aAl + psA;
        lB = lB * aBl + psB;
#pragma unroll
        for (int nt = 0; nt < 16; nt++) {
            oacc[nt][0] *= aAl;
            oacc[nt][1] *= aAl;
            oacc[nt][2] *= aBl;
            oacc[nt][3] *= aBl;
        }

        // ---- O += P V (1-term fp16), V b-frags via ldmatrix.trans ----
#pragma unroll
        for (int ks = 0; ks < 4; ks++) {
            uint32_t aph[4] = {ph[2 * ks][0], ph[2 * ks][1],
                               ph[2 * ks + 1][0], ph[2 * ks + 1][1]};
#pragma unroll
            for (int np = 0; np < 8; np++) {
                uint32_t vh[4];
                ldsm4t(vh[0], vh[1], vh[2], vh[3],
                       vbase + (ks * 16 * AT_STRIDE) * 2 + np * 32);
                MMA_H(oacc[2 * np],     aph, vh[0], vh[1]);
                MMA_H(oacc[2 * np + 1], aph, vh[2], vh[3]);
            }
        }
        __syncthreads();                 // buf[jt&1] free for tile jt+2's load
    }

    // ---- finalize: normalize, write fp16 to g_oh [B,T,D] ----
    lA += __shfl_xor_sync(0xffffffffu, lA, 1);
    lA += __shfl_xor_sync(0xffffffffu, lA, 2);
    lB += __shfl_xor_sync(0xffffffffu, lB, 1);
    lB += __shfl_xor_sync(0xffffffffu, lB, 2);
    float invA = 1.f / lA, invB = 1.f / lB;

    int rA = qs + wid * 16 + (lane >> 2);
    int c0 = 2 * (lane & 3);
    size_t baseA = ((size_t)(b * T_ + rA)) * D_ + head * HD;
    size_t baseB = baseA + (size_t)8 * D_;
#pragma unroll
    for (int nt = 0; nt < 16; nt++) {
        int cc = nt * 8 + c0;
        *(__half2*)(g_oh + baseA + cc) =
            __floats2half2_rn(oacc[nt][0] * invA, oacc[nt][1] * invA);
        *(__half2*)(g_oh + baseB + cc) =
            __floats2half2_rn(oacc[nt][2] * invB, oacc[nt][3] * invB);
    }
}

// ---------------------------------------------------------------------------
// Launch. Inputs: x, mask, cos, sin, w_attn, w_out. mask is tril -> causal.
// ---------------------------------------------------------------------------
extern "C" void kernel_launch(void* const* d_in, const int* in_sizes, int n_in,
                              void* d_out, int out_size)
{
    const float* x      = (const float*)d_in[0];
    const float* cosT   = (const float*)d_in[2];
    const float* sinT   = (const float*)d_in[3];
    const float* w_attn = (const float*)d_in[4];
    const float* w_out  = (const float*)d_in[5];
    float* out = (float*)d_out;

    cudaFuncSetAttribute(gemm1<0>, cudaFuncAttributeMaxDynamicSharedMemorySize, Q_SMEM);
    cudaFuncSetAttribute(gemm1<1>, cudaFuncAttributeMaxDynamicSharedMemorySize, Q_SMEM);
    cudaFuncSetAttribute(attn_mma, cudaFuncAttributeMaxDynamicSharedMemorySize,
                         AT_SMEM_BYTES);

    // Preprocessing: fp32 -> fp16 for x + both weights in ONE launch
    conv_all<<<(unsigned)((NX4 + NA4 + NO4) / 256), 256>>>(x, w_attn, w_out);

    // QKV projection (1-term fp16, BK=64, frag double-buffered)
    gemm1<0><<<dim3(96, 32), 128, Q_SMEM>>>(cosT, sinT, nullptr);

    // fp16 tensor-core flash attention (K/V double-buffered)
    attn_mma<<<dim3(32, NH, B_), 128, AT_SMEM_BYTES>>>();

    // Output projection (1-term fp16)
    gemm1<1><<<dim3(32, 32), 128, Q_SMEM>>>(cosT, sinT, out);
}